// round 1
// baseline (speedup 1.0000x reference)
#include <cuda_runtime.h>
#include <math.h>
#include <stdint.h>

#define NN 13627
#define EE 504378
#define E2T (EE + NN)

// ---------------- scratch (static device globals; no allocation) ----------------
__device__ float g_xl1[NN * 300];
__device__ float g_xr1[NN * 300];
__device__ float g_h1 [NN * 300];
__device__ float g_xl2[NN * 100];
__device__ float g_xr2[NN * 100];
__device__ float g_h2 [NN * 100];
__device__ float g_lin1[NN * 100];
__device__ float g_lin2[NN * 100];
__device__ float g_xo[NN * 100];
__device__ float g_z [NN * 100];
__device__ float g_xl3[NN];
__device__ float g_xr3[NN];
__device__ float g_e  [E2T];
__device__ int   g_deg[NN];
__device__ int   g_off[NN + 1];
__device__ int   g_cur[NN];
__device__ int   g_src[E2T];
__device__ float g_loss[2];

// ---------------- utility kernels ----------------
__global__ void zero_kernel(int* deg, int* cur, float* loss) {
    int i = blockIdx.x * blockDim.x + threadIdx.x;
    if (i < NN) { deg[i] = 0; cur[i] = 0; }
    if (i < 2) loss[i] = 0.f;
}

// histogram of destinations (edges + implicit self loops)
__global__ void hist_kernel(const int* __restrict__ ei, int* __restrict__ deg) {
    int k = blockIdx.x * blockDim.x + threadIdx.x;
    if (k >= E2T) return;
    int d = (k < EE) ? ei[EE + k] : (k - EE);
    atomicAdd(&deg[d], 1);
}

// single-block exclusive scan over NN bins
__global__ void scan_kernel(const int* __restrict__ deg, int* __restrict__ off) {
    __shared__ int sdata[1024];
    const int n = NN;
    int tid = threadIdx.x;
    const int per = (n + 1023) / 1024;  // 14
    int start = tid * per;
    int vals[16];
    int local = 0;
    for (int i = 0; i < per; i++) {
        int idx = start + i;
        int v = (idx < n) ? deg[idx] : 0;
        vals[i] = local;
        local += v;
    }
    sdata[tid] = local;
    __syncthreads();
    for (int ofs = 1; ofs < 1024; ofs <<= 1) {
        int v = (tid >= ofs) ? sdata[tid - ofs] : 0;
        __syncthreads();
        sdata[tid] += v;
        __syncthreads();
    }
    int base = (tid == 0) ? 0 : sdata[tid - 1];
    for (int i = 0; i < per; i++) {
        int idx = start + i;
        if (idx < n) off[idx] = base + vals[i];
    }
    if (tid == 0) off[n] = sdata[1023];
}

__global__ void scatter_kernel(const int* __restrict__ ei, int* __restrict__ cur,
                               const int* __restrict__ off, int* __restrict__ ssrc) {
    int k = blockIdx.x * blockDim.x + threadIdx.x;
    if (k >= E2T) return;
    int s, d;
    if (k < EE) { s = ei[k]; d = ei[EE + k]; }
    else        { s = d = k - EE; }
    int pos = off[d] + atomicAdd(&cur[d], 1);
    ssrc[pos] = s;
}

// ---------------- fp32 tiled GEMM: C[M,F] = A[M,K] @ B[K,F] (+bias)(relu) ----------------
#define GBM 64
#define GBN 64
#define GBK 16
__global__ __launch_bounds__(256) void gemm_kernel(
    const float* __restrict__ A, const float* __restrict__ B,
    const float* __restrict__ bias, float* __restrict__ C,
    int M, int K, int Fdim, int act)
{
    __shared__ float As[GBK][GBM];
    __shared__ float Bs[GBK][GBN];
    int block_row = blockIdx.y * GBM;
    int block_col = blockIdx.x * GBN;
    int tid = threadIdx.x;
    int tx = tid & 15, ty = tid >> 4;
    float acc[4][4] = {};
    for (int k0 = 0; k0 < K; k0 += GBK) {
        for (int i = tid; i < GBM * GBK; i += 256) {
            int r = i >> 4, c = i & 15;
            int gr = block_row + r, gc = k0 + c;
            As[c][r] = (gr < M && gc < K) ? A[(size_t)gr * K + gc] : 0.f;
        }
        for (int i = tid; i < GBK * GBN; i += 256) {
            int r = i >> 6, c = i & 63;
            int gr = k0 + r, gc = block_col + c;
            Bs[r][c] = (gr < K && gc < Fdim) ? B[(size_t)gr * Fdim + gc] : 0.f;
        }
        __syncthreads();
#pragma unroll
        for (int kk = 0; kk < GBK; kk++) {
            float4 av = *reinterpret_cast<const float4*>(&As[kk][ty * 4]);
            float4 bv = *reinterpret_cast<const float4*>(&Bs[kk][tx * 4]);
            float a[4] = {av.x, av.y, av.z, av.w};
            float b[4] = {bv.x, bv.y, bv.z, bv.w};
#pragma unroll
            for (int i = 0; i < 4; i++)
#pragma unroll
                for (int j = 0; j < 4; j++)
                    acc[i][j] += a[i] * b[j];
        }
        __syncthreads();
    }
#pragma unroll
    for (int i = 0; i < 4; i++) {
        int gr = block_row + ty * 4 + i;
        if (gr >= M) continue;
#pragma unroll
        for (int j = 0; j < 4; j++) {
            int gc = block_col + tx * 4 + j;
            if (gc >= Fdim) continue;
            float v = acc[i][j];
            if (bias) v += bias[gc];
            if (act) v = fmaxf(v, 0.f);
            C[(size_t)gr * Fdim + gc] = v;
        }
    }
}

// ---------------- GATv2 segment softmax + aggregation: one warp per dst node ----------------
template <int F>
__global__ __launch_bounds__(256) void gat_agg_kernel(
    const float* __restrict__ xl, const float* __restrict__ xr,
    const float* __restrict__ att, const float* __restrict__ bias,
    const int* __restrict__ ssrc, const int* __restrict__ off,
    float* __restrict__ ebuf, float* __restrict__ out, int relu)
{
    constexpr int NJ = (F + 31) / 32;
    int warp = (blockIdx.x * blockDim.x + threadIdx.x) >> 5;
    int lane = threadIdx.x & 31;
    if (warp >= NN) return;
    int d = warp;

    float xrreg[NJ], attreg[NJ];
#pragma unroll
    for (int j = 0; j < NJ; j++) {
        int f = lane + 32 * j;
        xrreg[j]  = (f < F) ? xr[(size_t)d * F + f] : 0.f;
        attreg[j] = (f < F) ? att[f] : 0.f;
    }
    int k0 = off[d], k1 = off[d + 1];

    // pass 1: scores + running max
    float m = -1e30f;
    for (int k = k0; k < k1; k++) {
        int s = ssrc[k];
        float p = 0.f;
#pragma unroll
        for (int j = 0; j < NJ; j++) {
            int f = lane + 32 * j;
            float v = (f < F) ? (xl[(size_t)s * F + f] + xrreg[j]) : 0.f;
            v = (v > 0.f) ? v : 0.2f * v;     // leaky_relu(., 0.2)
            p += v * attreg[j];
        }
#pragma unroll
        for (int o = 16; o > 0; o >>= 1) p += __shfl_xor_sync(0xffffffffu, p, o);
        if (lane == 0) ebuf[k] = p;
        m = fmaxf(m, p);
    }
    __syncwarp();

    // pass 2: sum of exp
    float ssum = 0.f;
    for (int k = k0 + lane; k < k1; k += 32) ssum += __expf(ebuf[k] - m);
#pragma unroll
    for (int o = 16; o > 0; o >>= 1) ssum += __shfl_xor_sync(0xffffffffu, ssum, o);
    float inv = 1.f / (ssum + 1e-16f);

    // pass 3: weighted aggregate
    float acc[NJ];
#pragma unroll
    for (int j = 0; j < NJ; j++) acc[j] = 0.f;
    for (int k = k0; k < k1; k++) {
        int s = ssrc[k];
        float w = __expf(ebuf[k] - m) * inv;
#pragma unroll
        for (int j = 0; j < NJ; j++) {
            int f = lane + 32 * j;
            if (f < F) acc[j] += w * xl[(size_t)s * F + f];
        }
    }
#pragma unroll
    for (int j = 0; j < NJ; j++) {
        int f = lane + 32 * j;
        if (f < F) {
            float v = acc[j] + bias[f];
            if (relu) v = fmaxf(v, 0.f);
            out[(size_t)d * F + f] = v;
        }
    }
}

// ---------------- residual adds: xo = h2 + lin1, z = h2 + lin2 ----------------
__global__ void add_kernel(const float* __restrict__ h2,
                           const float* __restrict__ lin1, const float* __restrict__ lin2,
                           float* __restrict__ xo, float* __restrict__ z) {
    int i = blockIdx.x * blockDim.x + threadIdx.x;
    if (i >= NN * 100) return;
    float h = h2[i];
    xo[i] = h + lin1[i];
    z[i]  = h + lin2[i];
}

// ---------------- link-prediction loss: one warp per edge (grid-stride) ----------------
__global__ void loss_kernel(const float* __restrict__ z, const int* __restrict__ ea,
                            const int* __restrict__ eb, int positive, float* __restrict__ accum) {
    int warp = (blockIdx.x * blockDim.x + threadIdx.x) >> 5;
    int lane = threadIdx.x & 31;
    int nwarps = (gridDim.x * blockDim.x) >> 5;
    float local = 0.f;
    for (int e = warp; e < EE; e += nwarps) {
        int a = ea[e], b = eb[e];
        float p = 0.f;
#pragma unroll
        for (int f = lane; f < 100; f += 32)
            p += z[(size_t)a * 100 + f] * z[(size_t)b * 100 + f];
#pragma unroll
        for (int o = 16; o > 0; o >>= 1) p += __shfl_xor_sync(0xffffffffu, p, o);
        if (lane == 0) {
            float sig = 1.f / (1.f + expf(-p));
            local += positive ? logf(sig + 1e-15f) : logf(1.f - sig + 1e-15f);
        }
    }
    if (lane == 0) atomicAdd(accum, local);
}

__global__ void finalize_kernel(float* __restrict__ d_out, const float* __restrict__ loss,
                                const float* __restrict__ c1, const float* __restrict__ c2) {
    if (threadIdx.x == 0) {
        d_out[NN]     = -(loss[0] + loss[1]) / (float)EE;
        d_out[NN + 1] = c1[0];
        d_out[NN + 2] = c2[0];
    }
}

// ---------------- launch ----------------
extern "C" void kernel_launch(void* const* d_in, const int* in_sizes, int n_in,
                              void* d_out, int out_size) {
    const float* x     = (const float*)d_in[0];
    const int*   ei    = (const int*)  d_in[1];
    const int*   nei   = (const int*)  d_in[2];
    const float* Wl1   = (const float*)d_in[3];
    const float* Wr1   = (const float*)d_in[4];
    const float* att1  = (const float*)d_in[5];
    const float* b1    = (const float*)d_in[6];
    const float* Wl2   = (const float*)d_in[7];
    const float* Wr2   = (const float*)d_in[8];
    const float* att2  = (const float*)d_in[9];
    const float* b2    = (const float*)d_in[10];
    const float* Wl3   = (const float*)d_in[11];
    const float* Wr3   = (const float*)d_in[12];
    const float* att3  = (const float*)d_in[13];
    const float* b3    = (const float*)d_in[14];
    const float* Wlin1 = (const float*)d_in[15];
    const float* blin1 = (const float*)d_in[16];
    const float* Wlin2 = (const float*)d_in[17];
    const float* blin2 = (const float*)d_in[18];
    const float* c1    = (const float*)d_in[19];
    const float* c2    = (const float*)d_in[20];
    float* out = (float*)d_out;

    float *xl1, *xr1, *h1, *xl2, *xr2, *h2, *lin1, *lin2, *xo, *z, *xl3, *xr3, *ebuf, *loss;
    int *deg, *off, *cur, *ssrc;
    cudaGetSymbolAddress((void**)&xl1,  g_xl1);
    cudaGetSymbolAddress((void**)&xr1,  g_xr1);
    cudaGetSymbolAddress((void**)&h1,   g_h1);
    cudaGetSymbolAddress((void**)&xl2,  g_xl2);
    cudaGetSymbolAddress((void**)&xr2,  g_xr2);
    cudaGetSymbolAddress((void**)&h2,   g_h2);
    cudaGetSymbolAddress((void**)&lin1, g_lin1);
    cudaGetSymbolAddress((void**)&lin2, g_lin2);
    cudaGetSymbolAddress((void**)&xo,   g_xo);
    cudaGetSymbolAddress((void**)&z,    g_z);
    cudaGetSymbolAddress((void**)&xl3,  g_xl3);
    cudaGetSymbolAddress((void**)&xr3,  g_xr3);
    cudaGetSymbolAddress((void**)&ebuf, g_e);
    cudaGetSymbolAddress((void**)&loss, g_loss);
    cudaGetSymbolAddress((void**)&deg,  g_deg);
    cudaGetSymbolAddress((void**)&off,  g_off);
    cudaGetSymbolAddress((void**)&cur,  g_cur);
    cudaGetSymbolAddress((void**)&ssrc, g_src);

    // ---- build CSR-by-dst (edges + self loops) ----
    zero_kernel<<<(NN + 255) / 256, 256>>>(deg, cur, loss);
    hist_kernel<<<(E2T + 255) / 256, 256>>>(ei, deg);
    scan_kernel<<<1, 1024>>>(deg, off);
    scatter_kernel<<<(E2T + 255) / 256, 256>>>(ei, cur, off, ssrc);

    dim3 tb(256);
    auto ggrid = [](int M, int F) { return dim3((F + GBN - 1) / GBN, (M + GBM - 1) / GBM); };

    // ---- layer 1 projections + skip linears ----
    gemm_kernel<<<ggrid(NN, 300), tb>>>(x, Wl1, nullptr, xl1, NN, 500, 300, 0);
    gemm_kernel<<<ggrid(NN, 300), tb>>>(x, Wr1, nullptr, xr1, NN, 500, 300, 0);
    gemm_kernel<<<ggrid(NN, 100), tb>>>(x, Wlin1, blin1, lin1, NN, 500, 100, 1);
    gemm_kernel<<<ggrid(NN, 100), tb>>>(x, Wlin2, blin2, lin2, NN, 500, 100, 1);

    int agg_blocks = (NN + 7) / 8;  // 8 warps per block
    gat_agg_kernel<300><<<agg_blocks, 256>>>(xl1, xr1, att1, b1, ssrc, off, ebuf, h1, 1);

    // ---- layer 2 ----
    gemm_kernel<<<ggrid(NN, 100), tb>>>(h1, Wl2, nullptr, xl2, NN, 300, 100, 0);
    gemm_kernel<<<ggrid(NN, 100), tb>>>(h1, Wr2, nullptr, xr2, NN, 300, 100, 0);
    gat_agg_kernel<100><<<agg_blocks, 256>>>(xl2, xr2, att2, b2, ssrc, off, ebuf, h2, 1);

    // ---- residuals ----
    add_kernel<<<(NN * 100 + 255) / 256, 256>>>(h2, lin1, lin2, xo, z);

    // ---- reconstruction loss ----
    loss_kernel<<<2048, 256>>>(z, ei, ei + EE, 1, loss + 0);
    loss_kernel<<<2048, 256>>>(z, nei, nei + EE, 0, loss + 1);

    // ---- layer 3 (F=1) ----
    gemm_kernel<<<ggrid(NN, 1), tb>>>(xo, Wl3, nullptr, xl3, NN, 100, 1, 0);
    gemm_kernel<<<ggrid(NN, 1), tb>>>(xo, Wr3, nullptr, xr3, NN, 100, 1, 0);
    gat_agg_kernel<1><<<agg_blocks, 256>>>(xl3, xr3, att3, b3, ssrc, off, ebuf, out, 0);

    finalize_kernel<<<1, 32>>>(out, loss, c1, c2);
}

// round 3
// speedup vs baseline: 1.5608x; 1.5608x over previous
#include <cuda_runtime.h>
#include <math.h>
#include <stdint.h>

#define NN 13627
#define EE 504378
#define E2T (EE + NN)

// ---------------- scratch (static device globals; no allocation) ----------------
__device__ float g_xl1[NN * 300];
__device__ float g_xr1[NN * 300];
__device__ float g_h1 [NN * 300];
__device__ float g_xl2[NN * 100];
__device__ float g_xr2[NN * 100];
__device__ float g_h2 [NN * 100];
__device__ float g_lin1[NN * 100];
__device__ float g_lin2[NN * 100];
__device__ float g_xo[NN * 100];
__device__ float g_z [NN * 100];
__device__ float g_xl3[NN];
__device__ float g_xr3[NN];
__device__ int   g_deg[NN];
__device__ int   g_off[NN + 1];
__device__ int   g_cur[NN];
__device__ int   g_src[E2T];
__device__ float g_loss[2];

// ---------------- utility kernels ----------------
__global__ void zero_kernel(int* deg, int* cur, float* loss) {
    int i = blockIdx.x * blockDim.x + threadIdx.x;
    if (i < NN) { deg[i] = 0; cur[i] = 0; }
    if (i < 2) loss[i] = 0.f;
}

__global__ void hist_kernel(const int* __restrict__ ei, int* __restrict__ deg) {
    int k = blockIdx.x * blockDim.x + threadIdx.x;
    if (k >= E2T) return;
    int d = (k < EE) ? ei[EE + k] : (k - EE);
    atomicAdd(&deg[d], 1);
}

__global__ void scan_kernel(const int* __restrict__ deg, int* __restrict__ off) {
    __shared__ int sdata[1024];
    const int n = NN;
    int tid = threadIdx.x;
    const int per = (n + 1023) / 1024;  // 14
    int start = tid * per;
    int vals[16];
    int local = 0;
    for (int i = 0; i < per; i++) {
        int idx = start + i;
        int v = (idx < n) ? deg[idx] : 0;
        vals[i] = local;
        local += v;
    }
    sdata[tid] = local;
    __syncthreads();
    for (int ofs = 1; ofs < 1024; ofs <<= 1) {
        int v = (tid >= ofs) ? sdata[tid - ofs] : 0;
        __syncthreads();
        sdata[tid] += v;
        __syncthreads();
    }
    int base = (tid == 0) ? 0 : sdata[tid - 1];
    for (int i = 0; i < per; i++) {
        int idx = start + i;
        if (idx < n) off[idx] = base + vals[i];
    }
    if (tid == 0) off[n] = sdata[1023];
}

__global__ void scatter_kernel(const int* __restrict__ ei, int* __restrict__ cur,
                               const int* __restrict__ off, int* __restrict__ ssrc) {
    int k = blockIdx.x * blockDim.x + threadIdx.x;
    if (k >= E2T) return;
    int s, d;
    if (k < EE) { s = ei[k]; d = ei[EE + k]; }
    else        { s = d = k - EE; }
    int pos = off[d] + atomicAdd(&cur[d], 1);
    ssrc[pos] = s;
}

// ---------------- fp32 SGEMM: 128x64x16 tile, 8x4 per thread ----------------
#define BM 128
#define BN 64
#define BK 16
#define ASTRIDE (BM + 4)

__global__ __launch_bounds__(256) void gemm_kernel(
    const float* __restrict__ A, const float* __restrict__ B,
    const float* __restrict__ bias, float* __restrict__ C,
    int M, int K, int N, int act)
{
    __shared__ float As[BK][ASTRIDE];   // [k][m], padded
    __shared__ float Bs[BK][BN];        // [k][n]

    int tid  = threadIdx.x;
    int warp = tid >> 5, lane = tid & 31;
    int warp_m = warp & 3;            // 4 warps along M
    int warp_n = warp >> 2;           // 2 warps along N
    int lm = lane & 3;
    int ln = lane >> 2;
    int tm0 = warp_m * 32 + lm * 8;   // 8 consecutive rows
    int tn0 = warp_n * 32 + ln * 4;   // 4 consecutive cols
    int row0 = blockIdx.y * BM;
    int col0 = blockIdx.x * BN;

    // A staging: 512 float4 (128x16), 2 per thread
    int ar = tid >> 2;                // 0..63
    int ac = (tid & 3) * 4;           // 0,4,8,12
    // B staging: 256 float4 (16x64), 1 per thread
    int br = tid >> 4;                // 0..15
    int bc = (tid & 15) * 4;          // 0..60

    float acc[8][4] = {};

    for (int k0 = 0; k0 < K; k0 += BK) {
        // ---- load A tile (transpose to [k][m]); K,N are multiples of 4 ----
#pragma unroll
        for (int h = 0; h < 2; h++) {
            int r  = ar + h * 64;
            int gr = row0 + r;
            int gk = k0 + ac;
            float4 v = make_float4(0.f, 0.f, 0.f, 0.f);
            if (gr < M && gk < K)
                v = *reinterpret_cast<const float4*>(&A[(size_t)gr * K + gk]);
            As[ac + 0][r] = v.x;
            As[ac + 1][r] = v.y;
            As[ac + 2][r] = v.z;
            As[ac + 3][r] = v.w;
        }
        // ---- load B tile ----
        {
            int gk = k0 + br;
            int gc = col0 + bc;
            float4 v = make_float4(0.f, 0.f, 0.f, 0.f);
            if (gk < K && gc < N)
                v = *reinterpret_cast<const float4*>(&B[(size_t)gk * N + gc]);
            *reinterpret_cast<float4*>(&Bs[br][bc]) = v;
        }
        __syncthreads();

#pragma unroll
        for (int kk = 0; kk < BK; kk++) {
            float4 a0 = *reinterpret_cast<const float4*>(&As[kk][tm0]);
            float4 a1 = *reinterpret_cast<const float4*>(&As[kk][tm0 + 4]);
            float4 bv = *reinterpret_cast<const float4*>(&Bs[kk][tn0]);
            float a[8] = {a0.x, a0.y, a0.z, a0.w, a1.x, a1.y, a1.z, a1.w};
            float b[4] = {bv.x, bv.y, bv.z, bv.w};
#pragma unroll
            for (int i = 0; i < 8; i++)
#pragma unroll
                for (int j = 0; j < 4; j++)
                    acc[i][j] += a[i] * b[j];
        }
        __syncthreads();
    }

#pragma unroll
    for (int i = 0; i < 8; i++) {
        int gr = row0 + tm0 + i;
        if (gr >= M) continue;
#pragma unroll
        for (int j = 0; j < 4; j++) {
            int gc = col0 + tn0 + j;
            if (gc >= N) continue;
            float v = acc[i][j];
            if (bias) v += bias[gc];
            if (act) v = fmaxf(v, 0.f);
            C[(size_t)gr * N + gc] = v;
        }
    }
}

// ---------------- GATv2: single-pass online softmax + aggregation, warp/node ----------------
template <int F>
__global__ __launch_bounds__(256) void gat_agg_kernel(
    const float* __restrict__ xl, const float* __restrict__ xr,
    const float* __restrict__ att, const float* __restrict__ bias,
    const int* __restrict__ ssrc, const int* __restrict__ off,
    float* __restrict__ out, int relu)
{
    constexpr int NJ = (F + 31) / 32;
    int warp = (blockIdx.x * blockDim.x + threadIdx.x) >> 5;
    int lane = threadIdx.x & 31;
    if (warp >= NN) return;
    int d = warp;

    float xrreg[NJ], attreg[NJ];
#pragma unroll
    for (int j = 0; j < NJ; j++) {
        int f = lane + 32 * j;
        xrreg[j]  = (f < F) ? xr[(size_t)d * F + f] : 0.f;
        attreg[j] = (f < F) ? att[f] : 0.f;
    }
    int k0 = off[d], k1 = off[d + 1];

    float m = -1e30f, ssum = 0.f;
    float acc[NJ];
#pragma unroll
    for (int j = 0; j < NJ; j++) acc[j] = 0.f;

    for (int k = k0; k < k1; k++) {
        int s = ssrc[k];
        float xls[NJ];
#pragma unroll
        for (int j = 0; j < NJ; j++) {
            int f = lane + 32 * j;
            xls[j] = (f < F) ? xl[(size_t)s * F + f] : 0.f;
        }
        float p = 0.f;
#pragma unroll
        for (int j = 0; j < NJ; j++) {
            float v = xls[j] + xrreg[j];
            v = (v > 0.f) ? v : 0.2f * v;     // leaky_relu(., 0.2)
            p += v * attreg[j];
        }
#pragma unroll
        for (int o = 16; o > 0; o >>= 1) p += __shfl_xor_sync(0xffffffffu, p, o);

        if (p > m) {
            float sc = __expf(m - p);         // first iter: exp(-inf) -> 0
            ssum = ssum * sc + 1.f;
#pragma unroll
            for (int j = 0; j < NJ; j++) acc[j] = acc[j] * sc + xls[j];
            m = p;
        } else {
            float w = __expf(p - m);
            ssum += w;
#pragma unroll
            for (int j = 0; j < NJ; j++) acc[j] += w * xls[j];
        }
    }

    float inv = 1.f / (ssum + 1e-16f);
#pragma unroll
    for (int j = 0; j < NJ; j++) {
        int f = lane + 32 * j;
        if (f < F) {
            float v = acc[j] * inv + bias[f];
            if (relu) v = fmaxf(v, 0.f);
            out[(size_t)d * F + f] = v;
        }
    }
}

// ---------------- residual adds ----------------
__global__ void add_kernel(const float* __restrict__ h2,
                           const float* __restrict__ lin1, const float* __restrict__ lin2,
                           float* __restrict__ xo, float* __restrict__ z) {
    int i = blockIdx.x * blockDim.x + threadIdx.x;
    if (i >= NN * 100) return;
    float h = h2[i];
    xo[i] = h + lin1[i];
    z[i]  = h + lin2[i];
}

// ---------------- layer-3 projections: warp per node, two K=100 dots ----------------
__global__ __launch_bounds__(256) void lin3_kernel(
    const float* __restrict__ xo, const float* __restrict__ Wl3, const float* __restrict__ Wr3,
    float* __restrict__ xl3, float* __restrict__ xr3)
{
    int warp = (blockIdx.x * blockDim.x + threadIdx.x) >> 5;
    int lane = threadIdx.x & 31;
    if (warp >= NN) return;
    float pl = 0.f, pr = 0.f;
#pragma unroll
    for (int f = lane; f < 100; f += 32) {
        float v = xo[(size_t)warp * 100 + f];
        pl += v * Wl3[f];
        pr += v * Wr3[f];
    }
#pragma unroll
    for (int o = 16; o > 0; o >>= 1) {
        pl += __shfl_xor_sync(0xffffffffu, pl, o);
        pr += __shfl_xor_sync(0xffffffffu, pr, o);
    }
    if (lane == 0) { xl3[warp] = pl; xr3[warp] = pr; }
}

// ---------------- layer-3 GAT (F=1): warp per node, lanes parallel over edges ----------------
__global__ __launch_bounds__(256) void gat3_kernel(
    const float* __restrict__ xl3, const float* __restrict__ xr3,
    const float* __restrict__ att3, const float* __restrict__ b3,
    const int* __restrict__ ssrc, const int* __restrict__ off,
    float* __restrict__ out)
{
    int warp = (blockIdx.x * blockDim.x + threadIdx.x) >> 5;
    int lane = threadIdx.x & 31;
    if (warp >= NN) return;
    int d = warp;
    float a0 = att3[0];
    float xrd = xr3[d];
    int k0 = off[d], k1 = off[d + 1];

    // pass 1: max score
    float m = -1e30f;
    for (int k = k0 + lane; k < k1; k += 32) {
        float v = xl3[ssrc[k]] + xrd;
        v = (v > 0.f) ? v : 0.2f * v;
        m = fmaxf(m, v * a0);
    }
#pragma unroll
    for (int o = 16; o > 0; o >>= 1) m = fmaxf(m, __shfl_xor_sync(0xffffffffu, m, o));

    // pass 2: sum + weighted aggregate
    float ssum = 0.f, acc = 0.f;
    for (int k = k0 + lane; k < k1; k += 32) {
        float xs = xl3[ssrc[k]];
        float v = xs + xrd;
        v = (v > 0.f) ? v : 0.2f * v;
        float w = __expf(v * a0 - m);
        ssum += w;
        acc  += w * xs;
    }
#pragma unroll
    for (int o = 16; o > 0; o >>= 1) {
        ssum += __shfl_xor_sync(0xffffffffu, ssum, o);
        acc  += __shfl_xor_sync(0xffffffffu, acc, o);
    }
    if (lane == 0) out[d] = acc / (ssum + 1e-16f) + b3[0];
}

// ---------------- link-prediction loss: warp per edge (grid-stride) ----------------
__global__ void loss_kernel(const float* __restrict__ z, const int* __restrict__ ea,
                            const int* __restrict__ eb, int positive, float* __restrict__ accum) {
    int warp = (blockIdx.x * blockDim.x + threadIdx.x) >> 5;
    int lane = threadIdx.x & 31;
    int nwarps = (gridDim.x * blockDim.x) >> 5;
    float local = 0.f;
    for (int e = warp; e < EE; e += nwarps) {
        int a = ea[e], b = eb[e];
        float p = 0.f;
#pragma unroll
        for (int f = lane; f < 100; f += 32)
            p += z[(size_t)a * 100 + f] * z[(size_t)b * 100 + f];
#pragma unroll
        for (int o = 16; o > 0; o >>= 1) p += __shfl_xor_sync(0xffffffffu, p, o);
        if (lane == 0) {
            float sig = 1.f / (1.f + expf(-p));
            local += positive ? logf(sig + 1e-15f) : logf(1.f - sig + 1e-15f);
        }
    }
    if (lane == 0) atomicAdd(accum, local);
}

__global__ void finalize_kernel(float* __restrict__ d_out, const float* __restrict__ loss,
                                const float* __restrict__ c1, const float* __restrict__ c2) {
    if (threadIdx.x == 0) {
        d_out[NN]     = -(loss[0] + loss[1]) / (float)EE;
        d_out[NN + 1] = c1[0];
        d_out[NN + 2] = c2[0];
    }
}

// ---------------- launch ----------------
extern "C" void kernel_launch(void* const* d_in, const int* in_sizes, int n_in,
                              void* d_out, int out_size) {
    const float* x     = (const float*)d_in[0];
    const int*   ei    = (const int*)  d_in[1];
    const int*   nei   = (const int*)  d_in[2];
    const float* Wl1   = (const float*)d_in[3];
    const float* Wr1   = (const float*)d_in[4];
    const float* att1  = (const float*)d_in[5];
    const float* b1    = (const float*)d_in[6];
    const float* Wl2   = (const float*)d_in[7];
    const float* Wr2   = (const float*)d_in[8];
    const float* att2  = (const float*)d_in[9];
    const float* b2    = (const float*)d_in[10];
    const float* Wl3   = (const float*)d_in[11];
    const float* Wr3   = (const float*)d_in[12];
    const float* att3  = (const float*)d_in[13];
    const float* b3    = (const float*)d_in[14];
    const float* Wlin1 = (const float*)d_in[15];
    const float* blin1 = (const float*)d_in[16];
    const float* Wlin2 = (const float*)d_in[17];
    const float* blin2 = (const float*)d_in[18];
    const float* c1    = (const float*)d_in[19];
    const float* c2    = (const float*)d_in[20];
    float* out = (float*)d_out;

    float *xl1, *xr1, *h1, *xl2, *xr2, *h2, *lin1, *lin2, *xo, *z, *xl3, *xr3, *loss;
    int *deg, *off, *cur, *ssrc;
    cudaGetSymbolAddress((void**)&xl1,  g_xl1);
    cudaGetSymbolAddress((void**)&xr1,  g_xr1);
    cudaGetSymbolAddress((void**)&h1,   g_h1);
    cudaGetSymbolAddress((void**)&xl2,  g_xl2);
    cudaGetSymbolAddress((void**)&xr2,  g_xr2);
    cudaGetSymbolAddress((void**)&h2,   g_h2);
    cudaGetSymbolAddress((void**)&lin1, g_lin1);
    cudaGetSymbolAddress((void**)&lin2, g_lin2);
    cudaGetSymbolAddress((void**)&xo,   g_xo);
    cudaGetSymbolAddress((void**)&z,    g_z);
    cudaGetSymbolAddress((void**)&xl3,  g_xl3);
    cudaGetSymbolAddress((void**)&xr3,  g_xr3);
    cudaGetSymbolAddress((void**)&loss, g_loss);
    cudaGetSymbolAddress((void**)&deg,  g_deg);
    cudaGetSymbolAddress((void**)&off,  g_off);
    cudaGetSymbolAddress((void**)&cur,  g_cur);
    cudaGetSymbolAddress((void**)&ssrc, g_src);

    // ---- build CSR-by-dst (edges + self loops) ----
    zero_kernel<<<(NN + 255) / 256, 256>>>(deg, cur, loss);
    hist_kernel<<<(E2T + 255) / 256, 256>>>(ei, deg);
    scan_kernel<<<1, 1024>>>(deg, off);
    scatter_kernel<<<(E2T + 255) / 256, 256>>>(ei, cur, off, ssrc);

    dim3 tb(256);
    auto ggrid = [](int M, int N) { return dim3((N + BN - 1) / BN, (M + BM - 1) / BM); };

    // ---- layer 1 projections + skip linears ----
    gemm_kernel<<<ggrid(NN, 300), tb>>>(x, Wl1, nullptr, xl1, NN, 500, 300, 0);
    gemm_kernel<<<ggrid(NN, 300), tb>>>(x, Wr1, nullptr, xr1, NN, 500, 300, 0);
    gemm_kernel<<<ggrid(NN, 100), tb>>>(x, Wlin1, blin1, lin1, NN, 500, 100, 1);
    gemm_kernel<<<ggrid(NN, 100), tb>>>(x, Wlin2, blin2, lin2, NN, 500, 100, 1);

    int agg_blocks = (NN + 7) / 8;  // 8 warps per block
    gat_agg_kernel<300><<<agg_blocks, 256>>>(xl1, xr1, att1, b1, ssrc, off, h1, 1);

    // ---- layer 2 ----
    gemm_kernel<<<ggrid(NN, 100), tb>>>(h1, Wl2, nullptr, xl2, NN, 300, 100, 0);
    gemm_kernel<<<ggrid(NN, 100), tb>>>(h1, Wr2, nullptr, xr2, NN, 300, 100, 0);
    gat_agg_kernel<100><<<agg_blocks, 256>>>(xl2, xr2, att2, b2, ssrc, off, h2, 1);

    // ---- residuals ----
    add_kernel<<<(NN * 100 + 255) / 256, 256>>>(h2, lin1, lin2, xo, z);

    // ---- reconstruction loss ----
    loss_kernel<<<2048, 256>>>(z, ei, ei + EE, 1, loss + 0);
    loss_kernel<<<2048, 256>>>(z, nei, nei + EE, 0, loss + 1);

    // ---- layer 3 ----
    lin3_kernel<<<agg_blocks, 256>>>(xo, Wl3, Wr3, xl3, xr3);
    gat3_kernel<<<agg_blocks, 256>>>(xl3, xr3, att3, b3, ssrc, off, out);

    finalize_kernel<<<1, 32>>>(out, loss, c1, c2);
}

// round 4
// speedup vs baseline: 2.2433x; 1.4373x over previous
#include <cuda_runtime.h>
#include <math.h>
#include <stdint.h>

#define NN 13627
#define EE 504378
#define E2T (EE + NN)

// ---------------- scratch (static device globals; no allocation) ----------------
__device__ float g_xl1[NN * 300];
__device__ float g_xr1[NN * 300];
__device__ float g_h1 [NN * 300];
__device__ float g_xl2[NN * 100];
__device__ float g_xr2[NN * 100];
__device__ float g_h2 [NN * 100];
__device__ float g_lin1[NN * 100];
__device__ float g_lin2[NN * 100];
__device__ float g_xo[NN * 100];
__device__ float g_z [NN * 100];
__device__ float g_xl3[NN];
__device__ float g_xr3[NN];
__device__ int   g_deg[NN];
__device__ int   g_off[NN + 1];
__device__ int   g_cur[NN];
__device__ int   g_src[E2T];
__device__ float g_loss[2];

// ---------------- utility kernels ----------------
__global__ void zero_kernel(int* deg, int* cur, float* loss) {
    int i = blockIdx.x * blockDim.x + threadIdx.x;
    if (i < NN) { deg[i] = 0; cur[i] = 0; }
    if (i < 2) loss[i] = 0.f;
}

__global__ void hist_kernel(const int* __restrict__ ei, int* __restrict__ deg) {
    int k = blockIdx.x * blockDim.x + threadIdx.x;
    if (k >= E2T) return;
    int d = (k < EE) ? ei[EE + k] : (k - EE);
    atomicAdd(&deg[d], 1);
}

__global__ void scan_kernel(const int* __restrict__ deg, int* __restrict__ off) {
    __shared__ int sdata[1024];
    const int n = NN;
    int tid = threadIdx.x;
    const int per = (n + 1023) / 1024;  // 14
    int start = tid * per;
    int vals[16];
    int local = 0;
    for (int i = 0; i < per; i++) {
        int idx = start + i;
        int v = (idx < n) ? deg[idx] : 0;
        vals[i] = local;
        local += v;
    }
    sdata[tid] = local;
    __syncthreads();
    for (int ofs = 1; ofs < 1024; ofs <<= 1) {
        int v = (tid >= ofs) ? sdata[tid - ofs] : 0;
        __syncthreads();
        sdata[tid] += v;
        __syncthreads();
    }
    int base = (tid == 0) ? 0 : sdata[tid - 1];
    for (int i = 0; i < per; i++) {
        int idx = start + i;
        if (idx < n) off[idx] = base + vals[i];
    }
    if (tid == 0) off[n] = sdata[1023];
}

__global__ void scatter_kernel(const int* __restrict__ ei, int* __restrict__ cur,
                               const int* __restrict__ off, int* __restrict__ ssrc) {
    int k = blockIdx.x * blockDim.x + threadIdx.x;
    if (k >= E2T) return;
    int s, d;
    if (k < EE) { s = ei[k]; d = ei[EE + k]; }
    else        { s = d = k - EE; }
    int pos = off[d] + atomicAdd(&cur[d], 1);
    ssrc[pos] = s;
}

// ---------------- TF32 tensor-core GEMM: C[M,N] = A[M,K] @ B[K,N] ----------------
// Block 128x64, 8 warps (4 along M x 2 along N), warp tile 32x32 = 2x4 m16n8k8.
#define BM 128
#define BN 64
#define BK 16
#define AS_STRIDE 20   // conflict-free for A-frag pattern (r*20+c distinct mod 32)
#define BS_STRIDE 72   // conflict-free for B-frag pattern (k*72+n -> k*8+n mod 32)

__device__ __forceinline__ uint32_t f2tf32(float f) {
    uint32_t o;
    asm("cvt.rna.tf32.f32 %0, %1;" : "=r"(o) : "f"(f));
    return o;
}

__global__ __launch_bounds__(256) void gemm_tf32_kernel(
    const float* __restrict__ A, const float* __restrict__ B,
    const float* __restrict__ bias, float* __restrict__ C,
    int M, int K, int N, int act)
{
    __shared__ uint32_t As[BM][AS_STRIDE];   // [m][k] tf32 bits
    __shared__ uint32_t Bs[BK][BS_STRIDE];   // [k][n] tf32 bits

    int tid  = threadIdx.x;
    int warp = tid >> 5, lane = tid & 31;
    int warp_m = warp & 3;            // 4 warps along M (32 rows each)
    int warp_n = warp >> 2;           // 2 warps along N (32 cols each)
    int row0 = blockIdx.y * BM;
    int col0 = blockIdx.x * BN;
    int qr = lane >> 2;               // lane/4 : 0..7
    int qc = lane & 3;                // lane%4 : 0..3

    // staging indices
    int ar = tid >> 2;                // 0..63  (rows ar, ar+64)
    int ac = (tid & 3) * 4;           // 0,4,8,12
    int br = tid >> 4;                // 0..15
    int bc = (tid & 15) * 4;          // 0..60

    float c[2][4][4];                 // [mi][nj][frag]
#pragma unroll
    for (int mi = 0; mi < 2; mi++)
#pragma unroll
        for (int nj = 0; nj < 4; nj++)
#pragma unroll
            for (int q = 0; q < 4; q++) c[mi][nj][q] = 0.f;

    for (int k0 = 0; k0 < K; k0 += BK) {
        // ---- stage A (convert to tf32) ----
#pragma unroll
        for (int h = 0; h < 2; h++) {
            int r  = ar + h * 64;
            int gr = row0 + r;
            int gk = k0 + ac;
            float4 v = make_float4(0.f, 0.f, 0.f, 0.f);
            if (gr < M && gk < K)
                v = *reinterpret_cast<const float4*>(&A[(size_t)gr * K + gk]);
            As[r][ac + 0] = f2tf32(v.x);
            As[r][ac + 1] = f2tf32(v.y);
            As[r][ac + 2] = f2tf32(v.z);
            As[r][ac + 3] = f2tf32(v.w);
        }
        // ---- stage B ----
        {
            int gk = k0 + br;
            int gc = col0 + bc;
            float4 v = make_float4(0.f, 0.f, 0.f, 0.f);
            if (gk < K && gc < N)
                v = *reinterpret_cast<const float4*>(&B[(size_t)gk * N + gc]);
            Bs[br][bc + 0] = f2tf32(v.x);
            Bs[br][bc + 1] = f2tf32(v.y);
            Bs[br][bc + 2] = f2tf32(v.z);
            Bs[br][bc + 3] = f2tf32(v.w);
        }
        __syncthreads();

#pragma unroll
        for (int ks = 0; ks < 2; ks++) {
            int kb = ks * 8;
            uint32_t afrag[2][4], bfrag[4][2];
#pragma unroll
            for (int mi = 0; mi < 2; mi++) {
                int mrow = warp_m * 32 + mi * 16 + qr;
                afrag[mi][0] = As[mrow    ][kb + qc];
                afrag[mi][1] = As[mrow + 8][kb + qc];
                afrag[mi][2] = As[mrow    ][kb + qc + 4];
                afrag[mi][3] = As[mrow + 8][kb + qc + 4];
            }
#pragma unroll
            for (int nj = 0; nj < 4; nj++) {
                int ncol = warp_n * 32 + nj * 8 + qr;
                bfrag[nj][0] = Bs[kb + qc    ][ncol];
                bfrag[nj][1] = Bs[kb + qc + 4][ncol];
            }
#pragma unroll
            for (int mi = 0; mi < 2; mi++)
#pragma unroll
                for (int nj = 0; nj < 4; nj++) {
                    asm volatile(
                        "mma.sync.aligned.m16n8k8.row.col.f32.tf32.tf32.f32 "
                        "{%0,%1,%2,%3}, {%4,%5,%6,%7}, {%8,%9}, {%0,%1,%2,%3};"
                        : "+f"(c[mi][nj][0]), "+f"(c[mi][nj][1]),
                          "+f"(c[mi][nj][2]), "+f"(c[mi][nj][3])
                        : "r"(afrag[mi][0]), "r"(afrag[mi][1]),
                          "r"(afrag[mi][2]), "r"(afrag[mi][3]),
                          "r"(bfrag[nj][0]), "r"(bfrag[nj][1]));
                }
        }
        __syncthreads();
    }

    // ---- epilogue ----
#pragma unroll
    for (int mi = 0; mi < 2; mi++) {
#pragma unroll
        for (int rh = 0; rh < 2; rh++) {          // row half: +0 / +8
            int gr = row0 + warp_m * 32 + mi * 16 + rh * 8 + qr;
            if (gr >= M) continue;
#pragma unroll
            for (int nj = 0; nj < 4; nj++) {
#pragma unroll
                for (int jc = 0; jc < 2; jc++) {
                    int gc = col0 + warp_n * 32 + nj * 8 + qc * 2 + jc;
                    if (gc >= N) continue;
                    float v = c[mi][nj][rh * 2 + jc];
                    if (bias) v += bias[gc];
                    if (act) v = fmaxf(v, 0.f);
                    C[(size_t)gr * N + gc] = v;
                }
            }
        }
    }
}

// ---------------- GATv2: single-pass online softmax + aggregation, warp/node ----------------
template <int F>
__global__ __launch_bounds__(256) void gat_agg_kernel(
    const float* __restrict__ xl, const float* __restrict__ xr,
    const float* __restrict__ att, const float* __restrict__ bias,
    const int* __restrict__ ssrc, const int* __restrict__ off,
    float* __restrict__ out, int relu)
{
    constexpr int NJ = (F + 31) / 32;
    int warp = (blockIdx.x * blockDim.x + threadIdx.x) >> 5;
    int lane = threadIdx.x & 31;
    if (warp >= NN) return;
    int d = warp;

    float xrreg[NJ], attreg[NJ];
#pragma unroll
    for (int j = 0; j < NJ; j++) {
        int f = lane + 32 * j;
        xrreg[j]  = (f < F) ? xr[(size_t)d * F + f] : 0.f;
        attreg[j] = (f < F) ? att[f] : 0.f;
    }
    int k0 = off[d], k1 = off[d + 1];

    float m = -1e30f, ssum = 0.f;
    float acc[NJ];
#pragma unroll
    for (int j = 0; j < NJ; j++) acc[j] = 0.f;

    for (int k = k0; k < k1; k++) {
        int s = ssrc[k];
        float xls[NJ];
#pragma unroll
        for (int j = 0; j < NJ; j++) {
            int f = lane + 32 * j;
            xls[j] = (f < F) ? xl[(size_t)s * F + f] : 0.f;
        }
        float p = 0.f;
#pragma unroll
        for (int j = 0; j < NJ; j++) {
            float v = xls[j] + xrreg[j];
            v = (v > 0.f) ? v : 0.2f * v;     // leaky_relu(., 0.2)
            p += v * attreg[j];
        }
#pragma unroll
        for (int o = 16; o > 0; o >>= 1) p += __shfl_xor_sync(0xffffffffu, p, o);

        if (p > m) {
            float sc = __expf(m - p);         // first iter: exp(-inf) -> 0
            ssum = ssum * sc + 1.f;
#pragma unroll
            for (int j = 0; j < NJ; j++) acc[j] = acc[j] * sc + xls[j];
            m = p;
        } else {
            float w = __expf(p - m);
            ssum += w;
#pragma unroll
            for (int j = 0; j < NJ; j++) acc[j] += w * xls[j];
        }
    }

    float inv = 1.f / (ssum + 1e-16f);
#pragma unroll
    for (int j = 0; j < NJ; j++) {
        int f = lane + 32 * j;
        if (f < F) {
            float v = acc[j] * inv + bias[f];
            if (relu) v = fmaxf(v, 0.f);
            out[(size_t)d * F + f] = v;
        }
    }
}

// ---------------- residual adds ----------------
__global__ void add_kernel(const float* __restrict__ h2,
                           const float* __restrict__ lin1, const float* __restrict__ lin2,
                           float* __restrict__ xo, float* __restrict__ z) {
    int i = blockIdx.x * blockDim.x + threadIdx.x;
    if (i >= NN * 100) return;
    float h = h2[i];
    xo[i] = h + lin1[i];
    z[i]  = h + lin2[i];
}

// ---------------- layer-3 projections: warp per node, two K=100 dots ----------------
__global__ __launch_bounds__(256) void lin3_kernel(
    const float* __restrict__ xo, const float* __restrict__ Wl3, const float* __restrict__ Wr3,
    float* __restrict__ xl3, float* __restrict__ xr3)
{
    int warp = (blockIdx.x * blockDim.x + threadIdx.x) >> 5;
    int lane = threadIdx.x & 31;
    if (warp >= NN) return;
    float pl = 0.f, pr = 0.f;
#pragma unroll
    for (int f = lane; f < 100; f += 32) {
        float v = xo[(size_t)warp * 100 + f];
        pl += v * Wl3[f];
        pr += v * Wr3[f];
    }
#pragma unroll
    for (int o = 16; o > 0; o >>= 1) {
        pl += __shfl_xor_sync(0xffffffffu, pl, o);
        pr += __shfl_xor_sync(0xffffffffu, pr, o);
    }
    if (lane == 0) { xl3[warp] = pl; xr3[warp] = pr; }
}

// ---------------- layer-3 GAT (F=1): warp per node, lanes parallel over edges ----------------
__global__ __launch_bounds__(256) void gat3_kernel(
    const float* __restrict__ xl3, const float* __restrict__ xr3,
    const float* __restrict__ att3, const float* __restrict__ b3,
    const int* __restrict__ ssrc, const int* __restrict__ off,
    float* __restrict__ out)
{
    int warp = (blockIdx.x * blockDim.x + threadIdx.x) >> 5;
    int lane = threadIdx.x & 31;
    if (warp >= NN) return;
    int d = warp;
    float a0 = att3[0];
    float xrd = xr3[d];
    int k0 = off[d], k1 = off[d + 1];

    float m = -1e30f;
    for (int k = k0 + lane; k < k1; k += 32) {
        float v = xl3[ssrc[k]] + xrd;
        v = (v > 0.f) ? v : 0.2f * v;
        m = fmaxf(m, v * a0);
    }
#pragma unroll
    for (int o = 16; o > 0; o >>= 1) m = fmaxf(m, __shfl_xor_sync(0xffffffffu, m, o));

    float ssum = 0.f, acc = 0.f;
    for (int k = k0 + lane; k < k1; k += 32) {
        float xs = xl3[ssrc[k]];
        float v = xs + xrd;
        v = (v > 0.f) ? v : 0.2f * v;
        float w = __expf(v * a0 - m);
        ssum += w;
        acc  += w * xs;
    }
#pragma unroll
    for (int o = 16; o > 0; o >>= 1) {
        ssum += __shfl_xor_sync(0xffffffffu, ssum, o);
        acc  += __shfl_xor_sync(0xffffffffu, acc, o);
    }
    if (lane == 0) out[d] = acc / (ssum + 1e-16f) + b3[0];
}

// ---------------- link-prediction loss: pos+neg in one launch ----------------
__global__ void loss_kernel(const float* __restrict__ z, const int* __restrict__ ei,
                            const int* __restrict__ nei, float* __restrict__ accum) {
    int half = gridDim.x >> 1;
    int positive = (blockIdx.x < half) ? 1 : 0;
    int bid = positive ? blockIdx.x : (blockIdx.x - half);
    const int* ea = positive ? ei : nei;
    const int* eb = positive ? (ei + EE) : (nei + EE);

    int warp = (bid * blockDim.x + threadIdx.x) >> 5;
    int lane = threadIdx.x & 31;
    int nwarps = (half * blockDim.x) >> 5;
    float local = 0.f;
    for (int e = warp; e < EE; e += nwarps) {
        int a = ea[e], b = eb[e];
        float p = 0.f;
#pragma unroll
        for (int f = lane; f < 100; f += 32)
            p += z[(size_t)a * 100 + f] * z[(size_t)b * 100 + f];
#pragma unroll
        for (int o = 16; o > 0; o >>= 1) p += __shfl_xor_sync(0xffffffffu, p, o);
        if (lane == 0) {
            float sig = 1.f / (1.f + expf(-p));
            local += positive ? logf(sig + 1e-15f) : logf(1.f - sig + 1e-15f);
        }
    }
    if (lane == 0) atomicAdd(&accum[positive ? 0 : 1], local);
}

__global__ void finalize_kernel(float* __restrict__ d_out, const float* __restrict__ loss,
                                const float* __restrict__ c1, const float* __restrict__ c2) {
    if (threadIdx.x == 0) {
        d_out[NN]     = -(loss[0] + loss[1]) / (float)EE;
        d_out[NN + 1] = c1[0];
        d_out[NN + 2] = c2[0];
    }
}

// ---------------- launch ----------------
extern "C" void kernel_launch(void* const* d_in, const int* in_sizes, int n_in,
                              void* d_out, int out_size) {
    const float* x     = (const float*)d_in[0];
    const int*   ei    = (const int*)  d_in[1];
    const int*   nei   = (const int*)  d_in[2];
    const float* Wl1   = (const float*)d_in[3];
    const float* Wr1   = (const float*)d_in[4];
    const float* att1  = (const float*)d_in[5];
    const float* b1    = (const float*)d_in[6];
    const float* Wl2   = (const float*)d_in[7];
    const float* Wr2   = (const float*)d_in[8];
    const float* att2  = (const float*)d_in[9];
    const float* b2    = (const float*)d_in[10];
    const float* Wl3   = (const float*)d_in[11];
    const float* Wr3   = (const float*)d_in[12];
    const float* att3  = (const float*)d_in[13];
    const float* b3    = (const float*)d_in[14];
    const float* Wlin1 = (const float*)d_in[15];
    const float* blin1 = (const float*)d_in[16];
    const float* Wlin2 = (const float*)d_in[17];
    const float* blin2 = (const float*)d_in[18];
    const float* c1    = (const float*)d_in[19];
    const float* c2    = (const float*)d_in[20];
    float* out = (float*)d_out;

    float *xl1, *xr1, *h1, *xl2, *xr2, *h2, *lin1, *lin2, *xo, *z, *xl3, *xr3, *loss;
    int *deg, *off, *cur, *ssrc;
    cudaGetSymbolAddress((void**)&xl1,  g_xl1);
    cudaGetSymbolAddress((void**)&xr1,  g_xr1);
    cudaGetSymbolAddress((void**)&h1,   g_h1);
    cudaGetSymbolAddress((void**)&xl2,  g_xl2);
    cudaGetSymbolAddress((void**)&xr2,  g_xr2);
    cudaGetSymbolAddress((void**)&h2,   g_h2);
    cudaGetSymbolAddress((void**)&lin1, g_lin1);
    cudaGetSymbolAddress((void**)&lin2, g_lin2);
    cudaGetSymbolAddress((void**)&xo,   g_xo);
    cudaGetSymbolAddress((void**)&z,    g_z);
    cudaGetSymbolAddress((void**)&xl3,  g_xl3);
    cudaGetSymbolAddress((void**)&xr3,  g_xr3);
    cudaGetSymbolAddress((void**)&loss, g_loss);
    cudaGetSymbolAddress((void**)&deg,  g_deg);
    cudaGetSymbolAddress((void**)&off,  g_off);
    cudaGetSymbolAddress((void**)&cur,  g_cur);
    cudaGetSymbolAddress((void**)&ssrc, g_src);

    // ---- build CSR-by-dst (edges + self loops) ----
    zero_kernel<<<(NN + 255) / 256, 256>>>(deg, cur, loss);
    hist_kernel<<<(E2T + 255) / 256, 256>>>(ei, deg);
    scan_kernel<<<1, 1024>>>(deg, off);
    scatter_kernel<<<(E2T + 255) / 256, 256>>>(ei, cur, off, ssrc);

    dim3 tb(256);
    auto ggrid = [](int M, int N) { return dim3((N + BN - 1) / BN, (M + BM - 1) / BM); };

    // ---- layer 1 projections + skip linears (TF32 tensor cores) ----
    gemm_tf32_kernel<<<ggrid(NN, 300), tb>>>(x, Wl1, nullptr, xl1, NN, 500, 300, 0);
    gemm_tf32_kernel<<<ggrid(NN, 300), tb>>>(x, Wr1, nullptr, xr1, NN, 500, 300, 0);
    gemm_tf32_kernel<<<ggrid(NN, 100), tb>>>(x, Wlin1, blin1, lin1, NN, 500, 100, 1);
    gemm_tf32_kernel<<<ggrid(NN, 100), tb>>>(x, Wlin2, blin2, lin2, NN, 500, 100, 1);

    int agg_blocks = (NN + 7) / 8;  // 8 warps per block
    gat_agg_kernel<300><<<agg_blocks, 256>>>(xl1, xr1, att1, b1, ssrc, off, h1, 1);

    // ---- layer 2 ----
    gemm_tf32_kernel<<<ggrid(NN, 100), tb>>>(h1, Wl2, nullptr, xl2, NN, 300, 100, 0);
    gemm_tf32_kernel<<<ggrid(NN, 100), tb>>>(h1, Wr2, nullptr, xr2, NN, 300, 100, 0);
    gat_agg_kernel<100><<<agg_blocks, 256>>>(xl2, xr2, att2, b2, ssrc, off, h2, 1);

    // ---- residuals ----
    add_kernel<<<(NN * 100 + 255) / 256, 256>>>(h2, lin1, lin2, xo, z);

    // ---- reconstruction loss (pos + neg in one launch) ----
    loss_kernel<<<4096, 256>>>(z, ei, nei, loss);

    // ---- layer 3 ----
    lin3_kernel<<<agg_blocks, 256>>>(xo, Wl3, Wr3, xl3, xr3);
    gat3_kernel<<<agg_blocks, 256>>>(xl3, xr3, att3, b3, ssrc, off, out);

    finalize_kernel<<<1, 32>>>(out, loss, c1, c2);
}

// round 5
// speedup vs baseline: 2.4841x; 1.1074x over previous
#include <cuda_runtime.h>
#include <math.h>
#include <stdint.h>

#define NN 13627
#define EE 504378
#define E2T (EE + NN)

// ---------------- scratch (static device globals; no allocation) ----------------
__device__ float g_xl1[NN * 300];
__device__ float g_xr1[NN * 300];
__device__ float g_h1 [NN * 300];
__device__ float g_xl2[NN * 100];
__device__ float g_xr2[NN * 100];
__device__ float g_h2 [NN * 100];
__device__ float g_lin1[NN * 100];
__device__ float g_lin2[NN * 100];
__device__ float g_xo[NN * 100];
__device__ float g_z [NN * 100];
__device__ float g_xl3[NN];
__device__ float g_xr3[NN];
__device__ int   g_deg[NN];
__device__ int   g_off[NN + 1];
__device__ int   g_cur[NN];
__device__ int   g_src[E2T];
__device__ float g_loss[2];

// ---------------- utility kernels ----------------
__global__ void zero_kernel(int* deg, int* cur, float* loss) {
    int i = blockIdx.x * blockDim.x + threadIdx.x;
    if (i < NN) { deg[i] = 0; cur[i] = 0; }
    if (i < 2) loss[i] = 0.f;
}

__global__ void hist_kernel(const int* __restrict__ ei, int* __restrict__ deg) {
    int k = blockIdx.x * blockDim.x + threadIdx.x;
    if (k >= E2T) return;
    int d = (k < EE) ? ei[EE + k] : (k - EE);
    atomicAdd(&deg[d], 1);
}

__global__ void scan_kernel(const int* __restrict__ deg, int* __restrict__ off) {
    __shared__ int sdata[1024];
    const int n = NN;
    int tid = threadIdx.x;
    const int per = (n + 1023) / 1024;  // 14
    int start = tid * per;
    int vals[16];
    int local = 0;
    for (int i = 0; i < per; i++) {
        int idx = start + i;
        int v = (idx < n) ? deg[idx] : 0;
        vals[i] = local;
        local += v;
    }
    sdata[tid] = local;
    __syncthreads();
    for (int ofs = 1; ofs < 1024; ofs <<= 1) {
        int v = (tid >= ofs) ? sdata[tid - ofs] : 0;
        __syncthreads();
        sdata[tid] += v;
        __syncthreads();
    }
    int base = (tid == 0) ? 0 : sdata[tid - 1];
    for (int i = 0; i < per; i++) {
        int idx = start + i;
        if (idx < n) off[idx] = base + vals[i];
    }
    if (tid == 0) off[n] = sdata[1023];
}

__global__ void scatter_kernel(const int* __restrict__ ei, int* __restrict__ cur,
                               const int* __restrict__ off, int* __restrict__ ssrc) {
    int k = blockIdx.x * blockDim.x + threadIdx.x;
    if (k >= E2T) return;
    int s, d;
    if (k < EE) { s = ei[k]; d = ei[EE + k]; }
    else        { s = d = k - EE; }
    int pos = off[d] + atomicAdd(&cur[d], 1);
    ssrc[pos] = s;
}

// ---------------- TF32 tensor-core GEMM, multi-segment B ----------------
// Block 128x64, 8 warps (4 along M x 2 along N), warp tile 32x32 = 2x4 m16n8k8.
// blockIdx.x selects a 64-col block within one of up to 4 (B, bias, C, N, act) segments.
#define BM 128
#define BN 64
#define BK 16
#define AS_STRIDE 20
#define BS_STRIDE 72

struct GSeg {
    const float* B;
    const float* bias;
    float* C;
    int N;
    int act;
    int blk0;   // first block-col of this segment
};

__device__ __forceinline__ uint32_t f2tf32(float f) {
    uint32_t o;
    asm("cvt.rna.tf32.f32 %0, %1;" : "=r"(o) : "f"(f));
    return o;
}

__global__ __launch_bounds__(256) void gemm_tf32_multi(
    const float* __restrict__ A, int M, int K,
    GSeg s0, GSeg s1, GSeg s2, GSeg s3, int nseg)
{
    __shared__ uint32_t As[BM][AS_STRIDE];   // [m][k] tf32 bits
    __shared__ uint32_t Bs[BK][BS_STRIDE];   // [k][n] tf32 bits

    GSeg sg = s0;
    if (nseg > 1 && (int)blockIdx.x >= s1.blk0) sg = s1;
    if (nseg > 2 && (int)blockIdx.x >= s2.blk0) sg = s2;
    if (nseg > 3 && (int)blockIdx.x >= s3.blk0) sg = s3;
    const float* B = sg.B;
    int N = sg.N;

    int tid  = threadIdx.x;
    int warp = tid >> 5, lane = tid & 31;
    int warp_m = warp & 3;
    int warp_n = warp >> 2;
    int row0 = blockIdx.y * BM;
    int col0 = ((int)blockIdx.x - sg.blk0) * BN;
    int qr = lane >> 2;
    int qc = lane & 3;

    int ar = tid >> 2;
    int ac = (tid & 3) * 4;
    int br = tid >> 4;
    int bc = (tid & 15) * 4;

    float c[2][4][4];
#pragma unroll
    for (int mi = 0; mi < 2; mi++)
#pragma unroll
        for (int nj = 0; nj < 4; nj++)
#pragma unroll
            for (int q = 0; q < 4; q++) c[mi][nj][q] = 0.f;

    for (int k0 = 0; k0 < K; k0 += BK) {
#pragma unroll
        for (int h = 0; h < 2; h++) {
            int r  = ar + h * 64;
            int gr = row0 + r;
            int gk = k0 + ac;
            float4 v = make_float4(0.f, 0.f, 0.f, 0.f);
            if (gr < M && gk < K)
                v = *reinterpret_cast<const float4*>(&A[(size_t)gr * K + gk]);
            As[r][ac + 0] = f2tf32(v.x);
            As[r][ac + 1] = f2tf32(v.y);
            As[r][ac + 2] = f2tf32(v.z);
            As[r][ac + 3] = f2tf32(v.w);
        }
        {
            int gk = k0 + br;
            int gc = col0 + bc;
            float4 v = make_float4(0.f, 0.f, 0.f, 0.f);
            if (gk < K && gc + 3 < N)
                v = *reinterpret_cast<const float4*>(&B[(size_t)gk * N + gc]);
            else if (gk < K) {
                if (gc + 0 < N) v.x = B[(size_t)gk * N + gc + 0];
                if (gc + 1 < N) v.y = B[(size_t)gk * N + gc + 1];
                if (gc + 2 < N) v.z = B[(size_t)gk * N + gc + 2];
            }
            Bs[br][bc + 0] = f2tf32(v.x);
            Bs[br][bc + 1] = f2tf32(v.y);
            Bs[br][bc + 2] = f2tf32(v.z);
            Bs[br][bc + 3] = f2tf32(v.w);
        }
        __syncthreads();

#pragma unroll
        for (int ks = 0; ks < 2; ks++) {
            int kb = ks * 8;
            uint32_t afrag[2][4], bfrag[4][2];
#pragma unroll
            for (int mi = 0; mi < 2; mi++) {
                int mrow = warp_m * 32 + mi * 16 + qr;
                afrag[mi][0] = As[mrow    ][kb + qc];
                afrag[mi][1] = As[mrow + 8][kb + qc];
                afrag[mi][2] = As[mrow    ][kb + qc + 4];
                afrag[mi][3] = As[mrow + 8][kb + qc + 4];
            }
#pragma unroll
            for (int nj = 0; nj < 4; nj++) {
                int ncol = warp_n * 32 + nj * 8 + qr;
                bfrag[nj][0] = Bs[kb + qc    ][ncol];
                bfrag[nj][1] = Bs[kb + qc + 4][ncol];
            }
#pragma unroll
            for (int mi = 0; mi < 2; mi++)
#pragma unroll
                for (int nj = 0; nj < 4; nj++) {
                    asm volatile(
                        "mma.sync.aligned.m16n8k8.row.col.f32.tf32.tf32.f32 "
                        "{%0,%1,%2,%3}, {%4,%5,%6,%7}, {%8,%9}, {%0,%1,%2,%3};"
                        : "+f"(c[mi][nj][0]), "+f"(c[mi][nj][1]),
                          "+f"(c[mi][nj][2]), "+f"(c[mi][nj][3])
                        : "r"(afrag[mi][0]), "r"(afrag[mi][1]),
                          "r"(afrag[mi][2]), "r"(afrag[mi][3]),
                          "r"(bfrag[nj][0]), "r"(bfrag[nj][1]));
                }
        }
        __syncthreads();
    }

#pragma unroll
    for (int mi = 0; mi < 2; mi++) {
#pragma unroll
        for (int rh = 0; rh < 2; rh++) {
            int gr = row0 + warp_m * 32 + mi * 16 + rh * 8 + qr;
            if (gr >= M) continue;
#pragma unroll
            for (int nj = 0; nj < 4; nj++) {
#pragma unroll
                for (int jc = 0; jc < 2; jc++) {
                    int gc = col0 + warp_n * 32 + nj * 8 + qc * 2 + jc;
                    if (gc >= N) continue;
                    float v = c[mi][nj][rh * 2 + jc];
                    if (sg.bias) v += sg.bias[gc];
                    if (sg.act) v = fmaxf(v, 0.f);
                    sg.C[(size_t)gr * N + gc] = v;
                }
            }
        }
    }
}

// ---------------- GATv2: single-pass online softmax, float4 lanes, warp/node ----------------
template <int F>
__global__ __launch_bounds__(256) void gat_agg_kernel(
    const float* __restrict__ xl, const float* __restrict__ xr,
    const float* __restrict__ att, const float* __restrict__ bias,
    const int* __restrict__ ssrc, const int* __restrict__ off,
    float* __restrict__ out, int relu)
{
    static_assert(F % 4 == 0, "F must be multiple of 4");
    constexpr int C4 = F / 4;               // float4 chunks per row
    constexpr int NJ = (C4 + 31) / 32;      // chunks per lane
    int warp = (blockIdx.x * blockDim.x + threadIdx.x) >> 5;
    int lane = threadIdx.x & 31;
    if (warp >= NN) return;
    int d = warp;

    float4 xrv[NJ], attv[NJ], acc[NJ];
    bool act[NJ];
#pragma unroll
    for (int j = 0; j < NJ; j++) {
        int cidx = lane + 32 * j;
        act[j] = (cidx < C4);
        float4 zf = make_float4(0.f, 0.f, 0.f, 0.f);
        xrv[j]  = act[j] ? *reinterpret_cast<const float4*>(&xr[(size_t)d * F + 4 * cidx]) : zf;
        attv[j] = act[j] ? *reinterpret_cast<const float4*>(&att[4 * cidx]) : zf;
        acc[j]  = zf;
    }
    int k0 = off[d], k1 = off[d + 1];

    float m = -1e30f, ssum = 0.f;

    for (int k = k0; k < k1; k++) {
        int s = ssrc[k];
        const float4* xlr = reinterpret_cast<const float4*>(xl + (size_t)s * F);
        float4 xls[NJ];
#pragma unroll
        for (int j = 0; j < NJ; j++) {
            int cidx = lane + 32 * j;
            xls[j] = act[j] ? xlr[cidx] : make_float4(0.f, 0.f, 0.f, 0.f);
        }
        float p = 0.f;
#pragma unroll
        for (int j = 0; j < NJ; j++) {
            float v;
            v = xls[j].x + xrv[j].x; v = (v > 0.f) ? v : 0.2f * v; p += v * attv[j].x;
            v = xls[j].y + xrv[j].y; v = (v > 0.f) ? v : 0.2f * v; p += v * attv[j].y;
            v = xls[j].z + xrv[j].z; v = (v > 0.f) ? v : 0.2f * v; p += v * attv[j].z;
            v = xls[j].w + xrv[j].w; v = (v > 0.f) ? v : 0.2f * v; p += v * attv[j].w;
        }
#pragma unroll
        for (int o = 16; o > 0; o >>= 1) p += __shfl_xor_sync(0xffffffffu, p, o);

        if (p > m) {
            float sc = __expf(m - p);         // first iter: exp(-inf) -> 0
            ssum = ssum * sc + 1.f;
#pragma unroll
            for (int j = 0; j < NJ; j++) {
                acc[j].x = acc[j].x * sc + xls[j].x;
                acc[j].y = acc[j].y * sc + xls[j].y;
                acc[j].z = acc[j].z * sc + xls[j].z;
                acc[j].w = acc[j].w * sc + xls[j].w;
            }
            m = p;
        } else {
            float w = __expf(p - m);
            ssum += w;
#pragma unroll
            for (int j = 0; j < NJ; j++) {
                acc[j].x += w * xls[j].x;
                acc[j].y += w * xls[j].y;
                acc[j].z += w * xls[j].z;
                acc[j].w += w * xls[j].w;
            }
        }
    }

    float inv = 1.f / (ssum + 1e-16f);
#pragma unroll
    for (int j = 0; j < NJ; j++) {
        int cidx = lane + 32 * j;
        if (!act[j]) continue;
        float4 bv = *reinterpret_cast<const float4*>(&bias[4 * cidx]);
        float4 o;
        o.x = acc[j].x * inv + bv.x;
        o.y = acc[j].y * inv + bv.y;
        o.z = acc[j].z * inv + bv.z;
        o.w = acc[j].w * inv + bv.w;
        if (relu) {
            o.x = fmaxf(o.x, 0.f); o.y = fmaxf(o.y, 0.f);
            o.z = fmaxf(o.z, 0.f); o.w = fmaxf(o.w, 0.f);
        }
        *reinterpret_cast<float4*>(&out[(size_t)d * F + 4 * cidx]) = o;
    }
}

// ---------------- residual adds ----------------
__global__ void add_kernel(const float* __restrict__ h2,
                           const float* __restrict__ lin1, const float* __restrict__ lin2,
                           float* __restrict__ xo, float* __restrict__ z) {
    int i = blockIdx.x * blockDim.x + threadIdx.x;
    if (i >= NN * 100) return;
    float h = h2[i];
    xo[i] = h + lin1[i];
    z[i]  = h + lin2[i];
}

// ---------------- layer-3 projections: warp per node, two K=100 dots ----------------
__global__ __launch_bounds__(256) void lin3_kernel(
    const float* __restrict__ xo, const float* __restrict__ Wl3, const float* __restrict__ Wr3,
    float* __restrict__ xl3, float* __restrict__ xr3)
{
    int warp = (blockIdx.x * blockDim.x + threadIdx.x) >> 5;
    int lane = threadIdx.x & 31;
    if (warp >= NN) return;
    float pl = 0.f, pr = 0.f;
    if (lane < 25) {
        float4 v = *reinterpret_cast<const float4*>(&xo[(size_t)warp * 100 + lane * 4]);
        float4 wl = *reinterpret_cast<const float4*>(&Wl3[lane * 4]);
        float4 wr = *reinterpret_cast<const float4*>(&Wr3[lane * 4]);
        pl = v.x * wl.x + v.y * wl.y + v.z * wl.z + v.w * wl.w;
        pr = v.x * wr.x + v.y * wr.y + v.z * wr.z + v.w * wr.w;
    }
#pragma unroll
    for (int o = 16; o > 0; o >>= 1) {
        pl += __shfl_xor_sync(0xffffffffu, pl, o);
        pr += __shfl_xor_sync(0xffffffffu, pr, o);
    }
    if (lane == 0) { xl3[warp] = pl; xr3[warp] = pr; }
}

// ---------------- layer-3 GAT (F=1): warp per node, lanes parallel over edges ----------------
__global__ __launch_bounds__(256) void gat3_kernel(
    const float* __restrict__ xl3, const float* __restrict__ xr3,
    const float* __restrict__ att3, const float* __restrict__ b3,
    const int* __restrict__ ssrc, const int* __restrict__ off,
    float* __restrict__ out)
{
    int warp = (blockIdx.x * blockDim.x + threadIdx.x) >> 5;
    int lane = threadIdx.x & 31;
    if (warp >= NN) return;
    int d = warp;
    float a0 = att3[0];
    float xrd = xr3[d];
    int k0 = off[d], k1 = off[d + 1];

    float m = -1e30f;
    for (int k = k0 + lane; k < k1; k += 32) {
        float v = xl3[ssrc[k]] + xrd;
        v = (v > 0.f) ? v : 0.2f * v;
        m = fmaxf(m, v * a0);
    }
#pragma unroll
    for (int o = 16; o > 0; o >>= 1) m = fmaxf(m, __shfl_xor_sync(0xffffffffu, m, o));

    float ssum = 0.f, acc = 0.f;
    for (int k = k0 + lane; k < k1; k += 32) {
        float xs = xl3[ssrc[k]];
        float v = xs + xrd;
        v = (v > 0.f) ? v : 0.2f * v;
        float w = __expf(v * a0 - m);
        ssum += w;
        acc  += w * xs;
    }
#pragma unroll
    for (int o = 16; o > 0; o >>= 1) {
        ssum += __shfl_xor_sync(0xffffffffu, ssum, o);
        acc  += __shfl_xor_sync(0xffffffffu, acc, o);
    }
    if (lane == 0) out[d] = acc / (ssum + 1e-16f) + b3[0];
}

// ---------------- link-prediction loss: pos+neg, float4 lanes ----------------
__global__ void loss_kernel(const float* __restrict__ z, const int* __restrict__ ei,
                            const int* __restrict__ nei, float* __restrict__ accum) {
    int half = gridDim.x >> 1;
    int positive = (blockIdx.x < half) ? 1 : 0;
    int bid = positive ? blockIdx.x : (blockIdx.x - half);
    const int* ea = positive ? ei : nei;
    const int* eb = positive ? (ei + EE) : (nei + EE);

    int warp = (bid * blockDim.x + threadIdx.x) >> 5;
    int lane = threadIdx.x & 31;
    int nwarps = (half * blockDim.x) >> 5;
    float local = 0.f;
    for (int e = warp; e < EE; e += nwarps) {
        int a = ea[e], b = eb[e];
        float p = 0.f;
        if (lane < 25) {
            float4 va = *reinterpret_cast<const float4*>(&z[(size_t)a * 100 + lane * 4]);
            float4 vb = *reinterpret_cast<const float4*>(&z[(size_t)b * 100 + lane * 4]);
            p = va.x * vb.x + va.y * vb.y + va.z * vb.z + va.w * vb.w;
        }
#pragma unroll
        for (int o = 16; o > 0; o >>= 1) p += __shfl_xor_sync(0xffffffffu, p, o);
        if (lane == 0) {
            float sig = 1.f / (1.f + expf(-p));
            local += positive ? logf(sig + 1e-15f) : logf(1.f - sig + 1e-15f);
        }
    }
    if (lane == 0) atomicAdd(&accum[positive ? 0 : 1], local);
}

__global__ void finalize_kernel(float* __restrict__ d_out, const float* __restrict__ loss,
                                const float* __restrict__ c1, const float* __restrict__ c2) {
    if (threadIdx.x == 0) {
        d_out[NN]     = -(loss[0] + loss[1]) / (float)EE;
        d_out[NN + 1] = c1[0];
        d_out[NN + 2] = c2[0];
    }
}

// ---------------- launch ----------------
extern "C" void kernel_launch(void* const* d_in, const int* in_sizes, int n_in,
                              void* d_out, int out_size) {
    const float* x     = (const float*)d_in[0];
    const int*   ei    = (const int*)  d_in[1];
    const int*   nei   = (const int*)  d_in[2];
    const float* Wl1   = (const float*)d_in[3];
    const float* Wr1   = (const float*)d_in[4];
    const float* att1  = (const float*)d_in[5];
    const float* b1    = (const float*)d_in[6];
    const float* Wl2   = (const float*)d_in[7];
    const float* Wr2   = (const float*)d_in[8];
    const float* att2  = (const float*)d_in[9];
    const float* b2    = (const float*)d_in[10];
    const float* Wl3   = (const float*)d_in[11];
    const float* Wr3   = (const float*)d_in[12];
    const float* att3  = (const float*)d_in[13];
    const float* b3    = (const float*)d_in[14];
    const float* Wlin1 = (const float*)d_in[15];
    const float* blin1 = (const float*)d_in[16];
    const float* Wlin2 = (const float*)d_in[17];
    const float* blin2 = (const float*)d_in[18];
    const float* c1    = (const float*)d_in[19];
    const float* c2    = (const float*)d_in[20];
    float* out = (float*)d_out;

    float *xl1, *xr1, *h1, *xl2, *xr2, *h2, *lin1, *lin2, *xo, *z, *xl3, *xr3, *loss;
    int *deg, *off, *cur, *ssrc;
    cudaGetSymbolAddress((void**)&xl1,  g_xl1);
    cudaGetSymbolAddress((void**)&xr1,  g_xr1);
    cudaGetSymbolAddress((void**)&h1,   g_h1);
    cudaGetSymbolAddress((void**)&xl2,  g_xl2);
    cudaGetSymbolAddress((void**)&xr2,  g_xr2);
    cudaGetSymbolAddress((void**)&h2,   g_h2);
    cudaGetSymbolAddress((void**)&lin1, g_lin1);
    cudaGetSymbolAddress((void**)&lin2, g_lin2);
    cudaGetSymbolAddress((void**)&xo,   g_xo);
    cudaGetSymbolAddress((void**)&z,    g_z);
    cudaGetSymbolAddress((void**)&xl3,  g_xl3);
    cudaGetSymbolAddress((void**)&xr3,  g_xr3);
    cudaGetSymbolAddress((void**)&loss, g_loss);
    cudaGetSymbolAddress((void**)&deg,  g_deg);
    cudaGetSymbolAddress((void**)&off,  g_off);
    cudaGetSymbolAddress((void**)&cur,  g_cur);
    cudaGetSymbolAddress((void**)&ssrc, g_src);

    // ---- build CSR-by-dst (edges + self loops) ----
    zero_kernel<<<(NN + 255) / 256, 256>>>(deg, cur, loss);
    hist_kernel<<<(E2T + 255) / 256, 256>>>(ei, deg);
    scan_kernel<<<1, 1024>>>(deg, off);
    scatter_kernel<<<(E2T + 255) / 256, 256>>>(ei, cur, off, ssrc);

    dim3 tb(256);
    int rows = (NN + BM - 1) / BM;   // 107

    // ---- layer 1: [Wl1 | Wr1 | Wlin1 | Wlin2] in one launch ----
    {
        GSeg s0 = { Wl1,   nullptr, xl1,  300, 0, 0  };
        GSeg s1 = { Wr1,   nullptr, xr1,  300, 0, 5  };
        GSeg s2 = { Wlin1, blin1,   lin1, 100, 1, 10 };
        GSeg s3 = { Wlin2, blin2,   lin2, 100, 1, 12 };
        gemm_tf32_multi<<<dim3(14, rows), tb>>>(x, NN, 500, s0, s1, s2, s3, 4);
    }

    int agg_blocks = (NN + 7) / 8;  // 8 warps per block
    gat_agg_kernel<300><<<agg_blocks, 256>>>(xl1, xr1, att1, b1, ssrc, off, h1, 1);

    // ---- layer 2: [Wl2 | Wr2] in one launch ----
    {
        GSeg s0 = { Wl2, nullptr, xl2, 100, 0, 0 };
        GSeg s1 = { Wr2, nullptr, xr2, 100, 0, 2 };
        gemm_tf32_multi<<<dim3(4, rows), tb>>>(h1, NN, 300, s0, s1, s0, s1, 2);
    }
    gat_agg_kernel<100><<<agg_blocks, 256>>>(xl2, xr2, att2, b2, ssrc, off, h2, 1);

    // ---- residuals ----
    add_kernel<<<(NN * 100 + 255) / 256, 256>>>(h2, lin1, lin2, xo, z);

    // ---- reconstruction loss (pos + neg in one launch) ----
    loss_kernel<<<4096, 256>>>(z, ei, nei, loss);

    // ---- layer 3 ----
    lin3_kernel<<<agg_blocks, 256>>>(xo, Wl3, Wr3, xl3, xr3);
    gat3_kernel<<<agg_blocks, 256>>>(xl3, xr3, att3, b3, ssrc, off, out);

    finalize_kernel<<<1, 32>>>(out, loss, c1, c2);
}

// round 7
// speedup vs baseline: 2.9467x; 1.1862x over previous
#include <cuda_runtime.h>
#include <math.h>
#include <stdint.h>

#define NN 13627
#define EE 504378
#define E2T (EE + NN)

// ---------------- scratch (static device globals; no allocation) ----------------
__device__ uint32_t g_xtf [NN * 500];   // x as tf32 bits
__device__ uint32_t g_h1tf[NN * 300];   // h1 as tf32 bits
__device__ uint32_t g_wtf [460000];     // all weights as tf32 bits
__device__ float g_xl1[NN * 300];
__device__ float g_xr1[NN * 300];
__device__ float g_xl2[NN * 100];
__device__ float g_xr2[NN * 100];
__device__ float g_h2 [NN * 100];
__device__ float g_lin1[NN * 100];
__device__ float g_lin2[NN * 100];
__device__ float g_xo[NN * 100];
__device__ float g_z [NN * 100];
__device__ float g_xl3[NN];
__device__ float g_xr3[NN];
__device__ int   g_deg[NN];
__device__ int   g_off[NN + 1];
__device__ int   g_cur[NN];
__device__ int   g_src[E2T];
__device__ float g_loss[2];

// weight offsets inside g_wtf
#define OFF_WL1   0
#define OFF_WR1   150000
#define OFF_WLIN1 300000
#define OFF_WLIN2 350000
#define OFF_WL2   400000
#define OFF_WR2   430000

__device__ __forceinline__ uint32_t f2tf32(float f) {
    uint32_t o;
    asm("cvt.rna.tf32.f32 %0, %1;" : "=r"(o) : "f"(f));
    return o;
}

// ---------------- tf32 conversion: 7 segments in one launch ----------------
struct CSeg { const float* src; uint32_t* dst; int n4; };  // n4 = n/4

__global__ void conv_multi(CSeg c0, CSeg c1, CSeg c2, CSeg c3, CSeg c4, CSeg c5, CSeg c6) {
    int i = blockIdx.x * blockDim.x + threadIdx.x;
    CSeg segs[7] = {c0, c1, c2, c3, c4, c5, c6};
#pragma unroll
    for (int j = 0; j < 7; j++) {
        if (i < segs[j].n4) {
            float4 v = reinterpret_cast<const float4*>(segs[j].src)[i];
            uint4 o;
            o.x = f2tf32(v.x); o.y = f2tf32(v.y);
            o.z = f2tf32(v.z); o.w = f2tf32(v.w);
            reinterpret_cast<uint4*>(segs[j].dst)[i] = o;
        }
    }
}

// ---------------- utility kernels ----------------
__global__ void zero_kernel(int* deg, int* cur, float* loss) {
    int i = blockIdx.x * blockDim.x + threadIdx.x;
    if (i < NN) { deg[i] = 0; cur[i] = 0; }
    if (i < 2) loss[i] = 0.f;
}

__global__ void hist_kernel(const int* __restrict__ ei, int* __restrict__ deg) {
    int k = blockIdx.x * blockDim.x + threadIdx.x;
    if (k >= E2T) return;
    int d = (k < EE) ? ei[EE + k] : (k - EE);
    atomicAdd(&deg[d], 1);
}

__global__ void scan_kernel(const int* __restrict__ deg, int* __restrict__ off) {
    __shared__ int sdata[1024];
    const int n = NN;
    int tid = threadIdx.x;
    const int per = (n + 1023) / 1024;  // 14
    int start = tid * per;
    int vals[16];
    int local = 0;
    for (int i = 0; i < per; i++) {
        int idx = start + i;
        int v = (idx < n) ? deg[idx] : 0;
        vals[i] = local;
        local += v;
    }
    sdata[tid] = local;
    __syncthreads();
    for (int ofs = 1; ofs < 1024; ofs <<= 1) {
        int v = (tid >= ofs) ? sdata[tid - ofs] : 0;
        __syncthreads();
        sdata[tid] += v;
        __syncthreads();
    }
    int base = (tid == 0) ? 0 : sdata[tid - 1];
    for (int i = 0; i < per; i++) {
        int idx = start + i;
        if (idx < n) off[idx] = base + vals[i];
    }
    if (tid == 0) off[n] = sdata[1023];
}

__global__ void scatter_kernel(const int* __restrict__ ei, int* __restrict__ cur,
                               const int* __restrict__ off, int* __restrict__ ssrc) {
    int k = blockIdx.x * blockDim.x + threadIdx.x;
    if (k >= E2T) return;
    int s, d;
    if (k < EE) { s = ei[k]; d = ei[EE + k]; }
    else        { s = d = k - EE; }
    int pos = off[d] + atomicAdd(&cur[d], 1);
    ssrc[pos] = s;
}

// ---------------- TF32 GEMM, cp.async double-buffered, multi-segment B ----------------
#define BM 128
#define BN 64
#define BK 16
#define AS_STRIDE 20
#define BS_STRIDE 72

struct GSeg {
    const uint32_t* B;   // tf32 bits [K,N]
    const float* bias;
    float* C;
    int N;
    int act;
    int blk0;
};

__device__ __forceinline__ void cpa16(uint32_t dst, const void* src, int sz) {
    asm volatile("cp.async.ca.shared.global [%0], [%1], 16, %2;\n"
                 :: "r"(dst), "l"(src), "r"(sz));
}

__global__ __launch_bounds__(256) void gemm_tf32_multi(
    const uint32_t* __restrict__ A, int M, int K,
    GSeg s0, GSeg s1, GSeg s2, GSeg s3, int nseg)
{
    __shared__ uint32_t As[2][BM][AS_STRIDE];
    __shared__ uint32_t Bs[2][BK][BS_STRIDE];

    GSeg sg = s0;
    if (nseg > 1 && (int)blockIdx.x >= s1.blk0) sg = s1;
    if (nseg > 2 && (int)blockIdx.x >= s2.blk0) sg = s2;
    if (nseg > 3 && (int)blockIdx.x >= s3.blk0) sg = s3;
    const uint32_t* B = sg.B;
    int N = sg.N;

    int tid  = threadIdx.x;
    int warp = tid >> 5, lane = tid & 31;
    int warp_m = warp & 3;
    int warp_n = warp >> 2;
    int row0 = blockIdx.y * BM;
    int col0 = ((int)blockIdx.x - sg.blk0) * BN;
    int qr = lane >> 2;
    int qc = lane & 3;

    int ar = tid >> 2;                // 0..63
    int ac = (tid & 3) * 4;           // 0,4,8,12
    int br = tid >> 4;                // 0..15
    int bc = (tid & 15) * 4;          // 0..60

    uint32_t as_base = (uint32_t)__cvta_generic_to_shared(&As[0][0][0]);
    uint32_t bs_base = (uint32_t)__cvta_generic_to_shared(&Bs[0][0][0]);
    const uint32_t asbuf = BM * AS_STRIDE * 4;   // bytes per A buffer
    const uint32_t bsbuf = BK * BS_STRIDE * 4;

    int ntiles = (K + BK - 1) / BK;

    float c[2][4][4];
#pragma unroll
    for (int mi = 0; mi < 2; mi++)
#pragma unroll
        for (int nj = 0; nj < 4; nj++)
#pragma unroll
            for (int q = 0; q < 4; q++) c[mi][nj][q] = 0.f;

    auto load_tile = [&](int t, int buf) {
        int k0 = t * BK;
#pragma unroll
        for (int h = 0; h < 2; h++) {
            int r  = ar + h * 64;
            int gr = row0 + r;
            int gk = k0 + ac;
            bool ok = (gr < M) && (gk + 3 < K);
            const uint32_t* src = ok ? (A + (size_t)gr * K + gk) : A;
            cpa16(as_base + buf * asbuf + (r * AS_STRIDE + ac) * 4, src, ok ? 16 : 0);
        }
        {
            int gk = k0 + br;
            int gc = col0 + bc;
            bool ok = (gk < K) && (gc + 3 < N);
            const uint32_t* src = ok ? (B + (size_t)gk * N + gc) : B;
            cpa16(bs_base + buf * bsbuf + (br * BS_STRIDE + bc) * 4, src, ok ? 16 : 0);
        }
        asm volatile("cp.async.commit_group;\n");
    };

    load_tile(0, 0);

    for (int t = 0; t < ntiles; t++) {
        asm volatile("cp.async.wait_group 0;\n");
        __syncthreads();
        if (t + 1 < ntiles) load_tile(t + 1, (t + 1) & 1);
        int buf = t & 1;

#pragma unroll
        for (int ks = 0; ks < 2; ks++) {
            int kb = ks * 8;
            uint32_t afrag[2][4], bfrag[4][2];
#pragma unroll
            for (int mi = 0; mi < 2; mi++) {
                int mrow = warp_m * 32 + mi * 16 + qr;
                afrag[mi][0] = As[buf][mrow    ][kb + qc];
                afrag[mi][1] = As[buf][mrow + 8][kb + qc];
                afrag[mi][2] = As[buf][mrow    ][kb + qc + 4];
                afrag[mi][3] = As[buf][mrow + 8][kb + qc + 4];
            }
#pragma unroll
            for (int nj = 0; nj < 4; nj++) {
                int ncol = warp_n * 32 + nj * 8 + qr;
                bfrag[nj][0] = Bs[buf][kb + qc    ][ncol];
                bfrag[nj][1] = Bs[buf][kb + qc + 4][ncol];
            }
#pragma unroll
            for (int mi = 0; mi < 2; mi++)
#pragma unroll
                for (int nj = 0; nj < 4; nj++) {
                    asm volatile(
                        "mma.sync.aligned.m16n8k8.row.col.f32.tf32.tf32.f32 "
                        "{%0,%1,%2,%3}, {%4,%5,%6,%7}, {%8,%9}, {%0,%1,%2,%3};"
                        : "+f"(c[mi][nj][0]), "+f"(c[mi][nj][1]),
                          "+f"(c[mi][nj][2]), "+f"(c[mi][nj][3])
                        : "r"(afrag[mi][0]), "r"(afrag[mi][1]),
                          "r"(afrag[mi][2]), "r"(afrag[mi][3]),
                          "r"(bfrag[nj][0]), "r"(bfrag[nj][1]));
                }
        }
        __syncthreads();
    }

#pragma unroll
    for (int mi = 0; mi < 2; mi++) {
#pragma unroll
        for (int rh = 0; rh < 2; rh++) {
            int gr = row0 + warp_m * 32 + mi * 16 + rh * 8 + qr;
            if (gr >= M) continue;
#pragma unroll
            for (int nj = 0; nj < 4; nj++) {
#pragma unroll
                for (int jc = 0; jc < 2; jc++) {
                    int gc = col0 + warp_n * 32 + nj * 8 + qc * 2 + jc;
                    if (gc >= N) continue;
                    float v = c[mi][nj][rh * 2 + jc];
                    if (sg.bias) v += sg.bias[gc];
                    if (sg.act) v = fmaxf(v, 0.f);
                    sg.C[(size_t)gr * N + gc] = v;
                }
            }
        }
    }
}

// ---------------- GATv2: paired-edge online softmax, float4 lanes, warp/node ----------------
template <int F>
__global__ __launch_bounds__(256) void gat_agg_kernel(
    const float* __restrict__ xl, const float* __restrict__ xr,
    const float* __restrict__ att, const float* __restrict__ bias,
    const int* __restrict__ ssrc, const int* __restrict__ off,
    float* __restrict__ out, uint32_t* __restrict__ out_tf, int relu)
{
    static_assert(F % 4 == 0, "F must be multiple of 4");
    constexpr int C4 = F / 4;
    constexpr int NJ = (C4 + 31) / 32;
    int warp = (blockIdx.x * blockDim.x + threadIdx.x) >> 5;
    int lane = threadIdx.x & 31;
    if (warp >= NN) return;
    int d = warp;

    float4 xrv[NJ], attv[NJ], acc[NJ];
    bool act[NJ];
#pragma unroll
    for (int j = 0; j < NJ; j++) {
        int cidx = lane + 32 * j;
        act[j] = (cidx < C4);
        float4 zf = make_float4(0.f, 0.f, 0.f, 0.f);
        xrv[j]  = act[j] ? *reinterpret_cast<const float4*>(&xr[(size_t)d * F + 4 * cidx]) : zf;
        attv[j] = act[j] ? *reinterpret_cast<const float4*>(&att[4 * cidx]) : zf;
        acc[j]  = zf;
    }
    int k0 = off[d], k1 = off[d + 1];

    float m = -1e30f, ssum = 0.f;

    int k = k0;
    for (; k + 1 < k1; k += 2) {
        int sa = ssrc[k], sb = ssrc[k + 1];
        const float4* xar = reinterpret_cast<const float4*>(xl + (size_t)sa * F);
        const float4* xbr = reinterpret_cast<const float4*>(xl + (size_t)sb * F);
        float4 xa[NJ], xb[NJ];
#pragma unroll
        for (int j = 0; j < NJ; j++) {
            int cidx = lane + 32 * j;
            float4 zf = make_float4(0.f, 0.f, 0.f, 0.f);
            xa[j] = act[j] ? xar[cidx] : zf;
            xb[j] = act[j] ? xbr[cidx] : zf;
        }
        float pa = 0.f, pb = 0.f;
#pragma unroll
        for (int j = 0; j < NJ; j++) {
            float v;
            v = xa[j].x + xrv[j].x; v = (v > 0.f) ? v : 0.2f * v; pa += v * attv[j].x;
            v = xa[j].y + xrv[j].y; v = (v > 0.f) ? v : 0.2f * v; pa += v * attv[j].y;
            v = xa[j].z + xrv[j].z; v = (v > 0.f) ? v : 0.2f * v; pa += v * attv[j].z;
            v = xa[j].w + xrv[j].w; v = (v > 0.f) ? v : 0.2f * v; pa += v * attv[j].w;
            v = xb[j].x + xrv[j].x; v = (v > 0.f) ? v : 0.2f * v; pb += v * attv[j].x;
            v = xb[j].y + xrv[j].y; v = (v > 0.f) ? v : 0.2f * v; pb += v * attv[j].y;
            v = xb[j].z + xrv[j].z; v = (v > 0.f) ? v : 0.2f * v; pb += v * attv[j].z;
            v = xb[j].w + xrv[j].w; v = (v > 0.f) ? v : 0.2f * v; pb += v * attv[j].w;
        }
#pragma unroll
        for (int o = 16; o > 0; o >>= 1) {
            pa += __shfl_xor_sync(0xffffffffu, pa, o);
            pb += __shfl_xor_sync(0xffffffffu, pb, o);
        }
        float mn = fmaxf(m, fmaxf(pa, pb));
        float sc = __expf(m - mn);          // first pair: exp(-inf) -> 0
        float wa = __expf(pa - mn);
        float wb = __expf(pb - mn);
        ssum = ssum * sc + wa + wb;
#pragma unroll
        for (int j = 0; j < NJ; j++) {
            acc[j].x = acc[j].x * sc + wa * xa[j].x + wb * xb[j].x;
            acc[j].y = acc[j].y * sc + wa * xa[j].y + wb * xb[j].y;
            acc[j].z = acc[j].z * sc + wa * xa[j].z + wb * xb[j].z;
            acc[j].w = acc[j].w * sc + wa * xa[j].w + wb * xb[j].w;
        }
        m = mn;
    }
    if (k < k1) {                            // odd tail
        int s = ssrc[k];
        const float4* xar = reinterpret_cast<const float4*>(xl + (size_t)s * F);
        float4 xa[NJ];
#pragma unroll
        for (int j = 0; j < NJ; j++) {
            int cidx = lane + 32 * j;
            xa[j] = act[j] ? xar[cidx] : make_float4(0.f, 0.f, 0.f, 0.f);
        }
        float p = 0.f;
#pragma unroll
        for (int j = 0; j < NJ; j++) {
            float v;
            v = xa[j].x + xrv[j].x; v = (v > 0.f) ? v : 0.2f * v; p += v * attv[j].x;
            v = xa[j].y + xrv[j].y; v = (v > 0.f) ? v : 0.2f * v; p += v * attv[j].y;
            v = xa[j].z + xrv[j].z; v = (v > 0.f) ? v : 0.2f * v; p += v * attv[j].z;
            v = xa[j].w + xrv[j].w; v = (v > 0.f) ? v : 0.2f * v; p += v * attv[j].w;
        }
#pragma unroll
        for (int o = 16; o > 0; o >>= 1) p += __shfl_xor_sync(0xffffffffu, p, o);
        float mn = fmaxf(m, p);
        float sc = __expf(m - mn);
        float w  = __expf(p - mn);
        ssum = ssum * sc + w;
#pragma unroll
        for (int j = 0; j < NJ; j++) {
            acc[j].x = acc[j].x * sc + w * xa[j].x;
            acc[j].y = acc[j].y * sc + w * xa[j].y;
            acc[j].z = acc[j].z * sc + w * xa[j].z;
            acc[j].w = acc[j].w * sc + w * xa[j].w;
        }
        m = mn;
    }

    float inv = 1.f / (ssum + 1e-16f);
#pragma unroll
    for (int j = 0; j < NJ; j++) {
        int cidx = lane + 32 * j;
        if (!act[j]) continue;
        float4 bv = *reinterpret_cast<const float4*>(&bias[4 * cidx]);
        float4 o;
        o.x = acc[j].x * inv + bv.x;
        o.y = acc[j].y * inv + bv.y;
        o.z = acc[j].z * inv + bv.z;
        o.w = acc[j].w * inv + bv.w;
        if (relu) {
            o.x = fmaxf(o.x, 0.f); o.y = fmaxf(o.y, 0.f);
            o.z = fmaxf(o.z, 0.f); o.w = fmaxf(o.w, 0.f);
        }
        if (out)
            *reinterpret_cast<float4*>(&out[(size_t)d * F + 4 * cidx]) = o;
        if (out_tf) {
            uint4 t;
            t.x = f2tf32(o.x); t.y = f2tf32(o.y);
            t.z = f2tf32(o.z); t.w = f2tf32(o.w);
            *reinterpret_cast<uint4*>(&out_tf[(size_t)d * F + 4 * cidx]) = t;
        }
    }
}

// ---------------- residual adds ----------------
__global__ void add_kernel(const float* __restrict__ h2,
                           const float* __restrict__ lin1, const float* __restrict__ lin2,
                           float* __restrict__ xo, float* __restrict__ z) {
    int i = blockIdx.x * blockDim.x + threadIdx.x;
    if (i >= NN * 100) return;
    float h = h2[i];
    xo[i] = h + lin1[i];
    z[i]  = h + lin2[i];
}

// ---------------- layer-3 projections ----------------
__global__ __launch_bounds__(256) void lin3_kernel(
    const float* __restrict__ xo, const float* __restrict__ Wl3, const float* __restrict__ Wr3,
    float* __restrict__ xl3, float* __restrict__ xr3)
{
    int warp = (blockIdx.x * blockDim.x + threadIdx.x) >> 5;
    int lane = threadIdx.x & 31;
    if (warp >= NN) return;
    float pl = 0.f, pr = 0.f;
    if (lane < 25) {
        float4 v = *reinterpret_cast<const float4*>(&xo[(size_t)warp * 100 + lane * 4]);
        float4 wl = *reinterpret_cast<const float4*>(&Wl3[lane * 4]);
        float4 wr = *reinterpret_cast<const float4*>(&Wr3[lane * 4]);
        pl = v.x * wl.x + v.y * wl.y + v.z * wl.z + v.w * wl.w;
        pr = v.x * wr.x + v.y * wr.y + v.z * wr.z + v.w * wr.w;
    }
#pragma unroll
    for (int o = 16; o > 0; o >>= 1) {
        pl += __shfl_xor_sync(0xffffffffu, pl, o);
        pr += __shfl_xor_sync(0xffffffffu, pr, o);
    }
    if (lane == 0) { xl3[warp] = pl; xr3[warp] = pr; }
}

// ---------------- layer-3 GAT (F=1) ----------------
__global__ __launch_bounds__(256) void gat3_kernel(
    const float* __restrict__ xl3, const float* __restrict__ xr3,
    const float* __restrict__ att3, const float* __restrict__ b3,
    const int* __restrict__ ssrc, const int* __restrict__ off,
    float* __restrict__ out)
{
    int warp = (blockIdx.x * blockDim.x + threadIdx.x) >> 5;
    int lane = threadIdx.x & 31;
    if (warp >= NN) return;
    int d = warp;
    float a0 = att3[0];
    float xrd = xr3[d];
    int k0 = off[d], k1 = off[d + 1];

    float m = -1e30f;
    for (int k = k0 + lane; k < k1; k += 32) {
        float v = xl3[ssrc[k]] + xrd;
        v = (v > 0.f) ? v : 0.2f * v;
        m = fmaxf(m, v * a0);
    }
#pragma unroll
    for (int o = 16; o > 0; o >>= 1) m = fmaxf(m, __shfl_xor_sync(0xffffffffu, m, o));

    float ssum = 0.f, acc = 0.f;
    for (int k = k0 + lane; k < k1; k += 32) {
        float xs = xl3[ssrc[k]];
        float v = xs + xrd;
        v = (v > 0.f) ? v : 0.2f * v;
        float w = __expf(v * a0 - m);
        ssum += w;
        acc  += w * xs;
    }
#pragma unroll
    for (int o = 16; o > 0; o >>= 1) {
        ssum += __shfl_xor_sync(0xffffffffu, ssum, o);
        acc  += __shfl_xor_sync(0xffffffffu, acc, o);
    }
    if (lane == 0) out[d] = acc / (ssum + 1e-16f) + b3[0];
}

// ---------------- link-prediction loss: pos+neg, paired edges, float4 lanes ----------------
__global__ void loss_kernel(const float* __restrict__ z, const int* __restrict__ ei,
                            const int* __restrict__ nei, float* __restrict__ accum) {
    int half = gridDim.x >> 1;
    int positive = (blockIdx.x < half) ? 1 : 0;
    int bid = positive ? blockIdx.x : (blockIdx.x - half);
    const int* ea = positive ? ei : nei;
    const int* eb = positive ? (ei + EE) : (nei + EE);

    int warp = (bid * blockDim.x + threadIdx.x) >> 5;
    int lane = threadIdx.x & 31;
    int nwarps = (half * blockDim.x) >> 5;
    float local = 0.f;
    for (int e = warp * 2; e + 1 < EE; e += 2 * nwarps) {
        int a0 = ea[e],     b0 = eb[e];
        int a1 = ea[e + 1], b1 = eb[e + 1];
        float p0 = 0.f, p1 = 0.f;
        if (lane < 25) {
            float4 va0 = *reinterpret_cast<const float4*>(&z[(size_t)a0 * 100 + lane * 4]);
            float4 vb0 = *reinterpret_cast<const float4*>(&z[(size_t)b0 * 100 + lane * 4]);
            float4 va1 = *reinterpret_cast<const float4*>(&z[(size_t)a1 * 100 + lane * 4]);
            float4 vb1 = *reinterpret_cast<const float4*>(&z[(size_t)b1 * 100 + lane * 4]);
            p0 = va0.x * vb0.x + va0.y * vb0.y + va0.z * vb0.z + va0.w * vb0.w;
            p1 = va1.x * vb1.x + va1.y * vb1.y + va1.z * vb1.z + va1.w * vb1.w;
        }
#pragma unroll
        for (int o = 16; o > 0; o >>= 1) {
            p0 += __shfl_xor_sync(0xffffffffu, p0, o);
            p1 += __shfl_xor_sync(0xffffffffu, p1, o);
        }
        if (lane == 0) {
            float s0 = 1.f / (1.f + __expf(-p0));
            float s1 = 1.f / (1.f + __expf(-p1));
            if (positive) local += __logf(s0 + 1e-15f) + __logf(s1 + 1e-15f);
            else          local += __logf(1.f - s0 + 1e-15f) + __logf(1.f - s1 + 1e-15f);
        }
    }
    if (lane == 0) atomicAdd(&accum[positive ? 0 : 1], local);
}

__global__ void finalize_kernel(float* __restrict__ d_out, const float* __restrict__ loss,
                                const float* __restrict__ c1, const float* __restrict__ c2) {
    if (threadIdx.x == 0) {
        d_out[NN]     = -(loss[0] + loss[1]) / (float)EE;
        d_out[NN + 1] = c1[0];
        d_out[NN + 2] = c2[0];
    }
}

// ---------------- launch ----------------
extern "C" void kernel_launch(void* const* d_in, const int* in_sizes, int n_in,
                              void* d_out, int out_size) {
    const float* x     = (const float*)d_in[0];
    const int*   ei    = (const int*)  d_in[1];
    const int*   nei   = (const int*)  d_in[2];
    const float* Wl1   = (const float*)d_in[3];
    const float* Wr1   = (const float*)d_in[4];
    const float* att1  = (const float*)d_in[5];
    const float* b1    = (const float*)d_in[6];
    const float* Wl2   = (const float*)d_in[7];
    const float* Wr2   = (const float*)d_in[8];
    const float* att2  = (const float*)d_in[9];
    const float* b2    = (const float*)d_in[10];
    const float* Wl3   = (const float*)d_in[11];
    const float* Wr3   = (const float*)d_in[12];
    const float* att3  = (const float*)d_in[13];
    const float* b3    = (const float*)d_in[14];
    const float* Wlin1 = (const float*)d_in[15];
    const float* blin1 = (const float*)d_in[16];
    const float* Wlin2 = (const float*)d_in[17];
    const float* blin2 = (const float*)d_in[18];
    const float* c1    = (const float*)d_in[19];
    const float* c2    = (const float*)d_in[20];
    float* out = (float*)d_out;

    uint32_t *xtf, *h1tf, *wtf;
    float *xl1, *xr1, *xl2, *xr2, *h2, *lin1, *lin2, *xo, *z, *xl3, *xr3, *loss;
    int *deg, *off, *cur, *ssrc;
    cudaGetSymbolAddress((void**)&xtf,  g_xtf);
    cudaGetSymbolAddress((void**)&h1tf, g_h1tf);
    cudaGetSymbolAddress((void**)&wtf,  g_wtf);
    cudaGetSymbolAddress((void**)&xl1,  g_xl1);
    cudaGetSymbolAddress((void**)&xr1,  g_xr1);
    cudaGetSymbolAddress((void**)&xl2,  g_xl2);
    cudaGetSymbolAddress((void**)&xr2,  g_xr2);
    cudaGetSymbolAddress((void**)&h2,   g_h2);
    cudaGetSymbolAddress((void**)&lin1, g_lin1);
    cudaGetSymbolAddress((void**)&lin2, g_lin2);
    cudaGetSymbolAddress((void**)&xo,   g_xo);
    cudaGetSymbolAddress((void**)&z,    g_z);
    cudaGetSymbolAddress((void**)&xl3,  g_xl3);
    cudaGetSymbolAddress((void**)&xr3,  g_xr3);
    cudaGetSymbolAddress((void**)&loss, g_loss);
    cudaGetSymbolAddress((void**)&deg,  g_deg);
    cudaGetSymbolAddress((void**)&off,  g_off);
    cudaGetSymbolAddress((void**)&cur,  g_cur);
    cudaGetSymbolAddress((void**)&ssrc, g_src);

    // ---- tf32 pre-conversion of x + all GEMM weights (one launch) ----
    {
        CSeg c0 = { x,     xtf,             NN * 500 / 4 };
        CSeg c1s= { Wl1,   wtf + OFF_WL1,   150000 / 4 };
        CSeg c2s= { Wr1,   wtf + OFF_WR1,   150000 / 4 };
        CSeg c3 = { Wlin1, wtf + OFF_WLIN1, 50000 / 4 };
        CSeg c4 = { Wlin2, wtf + OFF_WLIN2, 50000 / 4 };
        CSeg c5 = { Wl2,   wtf + OFF_WL2,   30000 / 4 };
        CSeg c6 = { Wr2,   wtf + OFF_WR2,   30000 / 4 };
        int n4 = NN * 500 / 4;
        conv_multi<<<(n4 + 255) / 256, 256>>>(c0, c1s, c2s, c3, c4, c5, c6);
    }

    // ---- build CSR-by-dst (edges + self loops) ----
    zero_kernel<<<(NN + 255) / 256, 256>>>(deg, cur, loss);
    hist_kernel<<<(E2T + 255) / 256, 256>>>(ei, deg);
    scan_kernel<<<1, 1024>>>(deg, off);
    scatter_kernel<<<(E2T + 255) / 256, 256>>>(ei, cur, off, ssrc);

    dim3 tb(256);
    int rows = (NN + BM - 1) / BM;   // 107

    // ---- layer 1: [Wl1 | Wr1 | Wlin1 | Wlin2] in one launch ----
    {
        GSeg s0 = { wtf + OFF_WL1,   nullptr, xl1,  300, 0, 0  };
        GSeg s1 = { wtf + OFF_WR1,   nullptr, xr1,  300, 0, 5  };
        GSeg s2 = { wtf + OFF_WLIN1, blin1,   lin1, 100, 1, 10 };
        GSeg s3 = { wtf + OFF_WLIN2, blin2,   lin2, 100, 1, 12 };
        gemm_tf32_multi<<<dim3(14, rows), tb>>>(xtf, NN, 500, s0, s1, s2, s3, 4);
    }

    int agg_blocks = (NN + 7) / 8;  // 8 warps per block
    // h1 is consumed only by the layer-2 GEMM -> emit tf32 bits directly
    gat_agg_kernel<300><<<agg_blocks, 256>>>(xl1, xr1, att1, b1, ssrc, off,
                                             nullptr, h1tf, 1);

    // ---- layer 2: [Wl2 | Wr2] in one launch ----
    {
        GSeg s0 = { wtf + OFF_WL2, nullptr, xl2, 100, 0, 0 };
        GSeg s1 = { wtf + OFF_WR2, nullptr, xr2, 100, 0, 2 };
        gemm_tf32_multi<<<dim3(4, rows), tb>>>(h1tf, NN, 300, s0, s1, s0, s1, 2);
    }
    gat_agg_kernel<100><<<agg_blocks, 256>>>(xl2, xr2, att2, b2, ssrc, off,
                                             h2, nullptr, 1);

    // ---- residuals ----
    add_kernel<<<(NN * 100 + 255) / 256, 256>>>(h2, lin1, lin2, xo, z);

    // ---- reconstruction loss ----
    loss_kernel<<<4096, 256>>>(z, ei, nei, loss);

    // ---- layer 3 ----
    lin3_kernel<<<agg_blocks, 256>>>(xo, Wl3, Wr3, xl3, xr3);
    gat3_kernel<<<agg_blocks, 256>>>(xl3, xr3, att3, b3, ssrc, off, out);

    finalize_kernel<<<1, 32>>>(out, loss, c1, c2);
}

// round 8
// speedup vs baseline: 3.1974x; 1.0851x over previous
#include <cuda_runtime.h>
#include <math.h>
#include <stdint.h>

#define NN 13627
#define EE 504378
#define E2T (EE + NN)

// ---------------- scratch (static device globals; no allocation) ----------------
__device__ uint32_t g_xtf [NN * 500];   // x as tf32 bits
__device__ uint32_t g_h1tf[NN * 300];   // h1 as tf32 bits
__device__ uint32_t g_wtf [460000];     // all weights as tf32 bits
__device__ float g_xl1[NN * 300];
__device__ float g_xr1[NN * 300];
__device__ float g_xl2[NN * 100];
__device__ float g_xr2[NN * 100];
__device__ float g_lin1[NN * 100];
__device__ float g_lin2[NN * 100];
__device__ float g_z [NN * 100];
__device__ float g_xl3[NN];
__device__ float g_xr3[NN];
__device__ int   g_deg[NN];
__device__ int   g_off[NN + 1];
__device__ int   g_cur[NN];
__device__ int   g_src[E2T];
__device__ float g_loss[2];

// weight offsets inside g_wtf
#define OFF_WL1   0
#define OFF_WR1   150000
#define OFF_WLIN1 300000
#define OFF_WLIN2 350000
#define OFF_WL2   400000
#define OFF_WR2   430000

__device__ __forceinline__ uint32_t f2tf32(float f) {
    uint32_t o;
    asm("cvt.rna.tf32.f32 %0, %1;" : "=r"(o) : "f"(f));
    return o;
}

// ---------------- tf32 conversion: 7 segments in one launch ----------------
struct CSeg { const float* src; uint32_t* dst; int n4; };  // n4 = n/4

__global__ void conv_multi(CSeg c0, CSeg c1, CSeg c2, CSeg c3, CSeg c4, CSeg c5, CSeg c6) {
    int i = blockIdx.x * blockDim.x + threadIdx.x;
    CSeg segs[7] = {c0, c1, c2, c3, c4, c5, c6};
#pragma unroll
    for (int j = 0; j < 7; j++) {
        if (i < segs[j].n4) {
            float4 v = reinterpret_cast<const float4*>(segs[j].src)[i];
            uint4 o;
            o.x = f2tf32(v.x); o.y = f2tf32(v.y);
            o.z = f2tf32(v.z); o.w = f2tf32(v.w);
            reinterpret_cast<uint4*>(segs[j].dst)[i] = o;
        }
    }
}

// ---------------- utility kernels ----------------
__global__ void zero_kernel(int* deg, int* cur, float* loss) {
    int i = blockIdx.x * blockDim.x + threadIdx.x;
    if (i < NN) { deg[i] = 0; cur[i] = 0; }
    if (i < 2) loss[i] = 0.f;
}

__global__ void hist_kernel(const int* __restrict__ ei, int* __restrict__ deg) {
    int k = blockIdx.x * blockDim.x + threadIdx.x;
    if (k >= E2T) return;
    int d = (k < EE) ? ei[EE + k] : (k - EE);
    atomicAdd(&deg[d], 1);
}

__global__ void scan_kernel(const int* __restrict__ deg, int* __restrict__ off) {
    __shared__ int sdata[1024];
    const int n = NN;
    int tid = threadIdx.x;
    const int per = (n + 1023) / 1024;  // 14
    int start = tid * per;
    int vals[16];
    int local = 0;
    for (int i = 0; i < per; i++) {
        int idx = start + i;
        int v = (idx < n) ? deg[idx] : 0;
        vals[i] = local;
        local += v;
    }
    sdata[tid] = local;
    __syncthreads();
    for (int ofs = 1; ofs < 1024; ofs <<= 1) {
        int v = (tid >= ofs) ? sdata[tid - ofs] : 0;
        __syncthreads();
        sdata[tid] += v;
        __syncthreads();
    }
    int base = (tid == 0) ? 0 : sdata[tid - 1];
    for (int i = 0; i < per; i++) {
        int idx = start + i;
        if (idx < n) off[idx] = base + vals[i];
    }
    if (tid == 0) off[n] = sdata[1023];
}

__global__ void scatter_kernel(const int* __restrict__ ei, int* __restrict__ cur,
                               const int* __restrict__ off, int* __restrict__ ssrc) {
    int k = blockIdx.x * blockDim.x + threadIdx.x;
    if (k >= E2T) return;
    int s, d;
    if (k < EE) { s = ei[k]; d = ei[EE + k]; }
    else        { s = d = k - EE; }
    int pos = off[d] + atomicAdd(&cur[d], 1);
    ssrc[pos] = s;
}

// ---------------- TF32 GEMM, cp.async double-buffered, multi-segment B ----------------
#define BM 128
#define BN 64
#define BK 16
#define AS_STRIDE 20
#define BS_STRIDE 72

struct GSeg {
    const uint32_t* B;   // tf32 bits [K,N]
    const float* bias;
    float* C;
    int N;
    int act;
    int blk0;
};

__device__ __forceinline__ void cpa16(uint32_t dst, const void* src, int sz) {
    asm volatile("cp.async.ca.shared.global [%0], [%1], 16, %2;\n"
                 :: "r"(dst), "l"(src), "r"(sz));
}

__global__ __launch_bounds__(256) void gemm_tf32_multi(
    const uint32_t* __restrict__ A, int M, int K,
    GSeg s0, GSeg s1, GSeg s2, GSeg s3, int nseg)
{
    __shared__ uint32_t As[2][BM][AS_STRIDE];
    __shared__ uint32_t Bs[2][BK][BS_STRIDE];

    GSeg sg = s0;
    if (nseg > 1 && (int)blockIdx.x >= s1.blk0) sg = s1;
    if (nseg > 2 && (int)blockIdx.x >= s2.blk0) sg = s2;
    if (nseg > 3 && (int)blockIdx.x >= s3.blk0) sg = s3;
    const uint32_t* B = sg.B;
    int N = sg.N;

    int tid  = threadIdx.x;
    int warp = tid >> 5, lane = tid & 31;
    int warp_m = warp & 3;
    int warp_n = warp >> 2;
    int row0 = blockIdx.y * BM;
    int col0 = ((int)blockIdx.x - sg.blk0) * BN;
    int qr = lane >> 2;
    int qc = lane & 3;

    int ar = tid >> 2;
    int ac = (tid & 3) * 4;
    int br = tid >> 4;
    int bc = (tid & 15) * 4;

    uint32_t as_base = (uint32_t)__cvta_generic_to_shared(&As[0][0][0]);
    uint32_t bs_base = (uint32_t)__cvta_generic_to_shared(&Bs[0][0][0]);
    const uint32_t asbuf = BM * AS_STRIDE * 4;
    const uint32_t bsbuf = BK * BS_STRIDE * 4;

    int ntiles = (K + BK - 1) / BK;

    float c[2][4][4];
#pragma unroll
    for (int mi = 0; mi < 2; mi++)
#pragma unroll
        for (int nj = 0; nj < 4; nj++)
#pragma unroll
            for (int q = 0; q < 4; q++) c[mi][nj][q] = 0.f;

    auto load_tile = [&](int t, int buf) {
        int k0 = t * BK;
#pragma unroll
        for (int h = 0; h < 2; h++) {
            int r  = ar + h * 64;
            int gr = row0 + r;
            int gk = k0 + ac;
            bool ok = (gr < M) && (gk + 3 < K);
            const uint32_t* src = ok ? (A + (size_t)gr * K + gk) : A;
            cpa16(as_base + buf * asbuf + (r * AS_STRIDE + ac) * 4, src, ok ? 16 : 0);
        }
        {
            int gk = k0 + br;
            int gc = col0 + bc;
            bool ok = (gk < K) && (gc + 3 < N);
            const uint32_t* src = ok ? (B + (size_t)gk * N + gc) : B;
            cpa16(bs_base + buf * bsbuf + (br * BS_STRIDE + bc) * 4, src, ok ? 16 : 0);
        }
        asm volatile("cp.async.commit_group;\n");
    };

    load_tile(0, 0);

    for (int t = 0; t < ntiles; t++) {
        asm volatile("cp.async.wait_group 0;\n");
        __syncthreads();
        if (t + 1 < ntiles) load_tile(t + 1, (t + 1) & 1);
        int buf = t & 1;

#pragma unroll
        for (int ks = 0; ks < 2; ks++) {
            int kb = ks * 8;
            uint32_t afrag[2][4], bfrag[4][2];
#pragma unroll
            for (int mi = 0; mi < 2; mi++) {
                int mrow = warp_m * 32 + mi * 16 + qr;
                afrag[mi][0] = As[buf][mrow    ][kb + qc];
                afrag[mi][1] = As[buf][mrow + 8][kb + qc];
                afrag[mi][2] = As[buf][mrow    ][kb + qc + 4];
                afrag[mi][3] = As[buf][mrow + 8][kb + qc + 4];
            }
#pragma unroll
            for (int nj = 0; nj < 4; nj++) {
                int ncol = warp_n * 32 + nj * 8 + qr;
                bfrag[nj][0] = Bs[buf][kb + qc    ][ncol];
                bfrag[nj][1] = Bs[buf][kb + qc + 4][ncol];
            }
#pragma unroll
            for (int mi = 0; mi < 2; mi++)
#pragma unroll
                for (int nj = 0; nj < 4; nj++) {
                    asm volatile(
                        "mma.sync.aligned.m16n8k8.row.col.f32.tf32.tf32.f32 "
                        "{%0,%1,%2,%3}, {%4,%5,%6,%7}, {%8,%9}, {%0,%1,%2,%3};"
                        : "+f"(c[mi][nj][0]), "+f"(c[mi][nj][1]),
                          "+f"(c[mi][nj][2]), "+f"(c[mi][nj][3])
                        : "r"(afrag[mi][0]), "r"(afrag[mi][1]),
                          "r"(afrag[mi][2]), "r"(afrag[mi][3]),
                          "r"(bfrag[nj][0]), "r"(bfrag[nj][1]));
                }
        }
        __syncthreads();
    }

#pragma unroll
    for (int mi = 0; mi < 2; mi++) {
#pragma unroll
        for (int rh = 0; rh < 2; rh++) {
            int gr = row0 + warp_m * 32 + mi * 16 + rh * 8 + qr;
            if (gr >= M) continue;
#pragma unroll
            for (int nj = 0; nj < 4; nj++) {
#pragma unroll
                for (int jc = 0; jc < 2; jc++) {
                    int gc = col0 + warp_n * 32 + nj * 8 + qc * 2 + jc;
                    if (gc >= N) continue;
                    float v = c[mi][nj][rh * 2 + jc];
                    if (sg.bias) v += sg.bias[gc];
                    if (sg.act) v = fmaxf(v, 0.f);
                    sg.C[(size_t)gr * N + gc] = v;
                }
            }
        }
    }
}

// ---------------- GATv2 layer 1: paired-edge online softmax, emits tf32 h1 ----------------
template <int F>
__global__ __launch_bounds__(256) void gat_agg_kernel(
    const float* __restrict__ xl, const float* __restrict__ xr,
    const float* __restrict__ att, const float* __restrict__ bias,
    const int* __restrict__ ssrc, const int* __restrict__ off,
    uint32_t* __restrict__ out_tf)
{
    static_assert(F % 4 == 0, "F must be multiple of 4");
    constexpr int C4 = F / 4;
    constexpr int NJ = (C4 + 31) / 32;
    int warp = (blockIdx.x * blockDim.x + threadIdx.x) >> 5;
    int lane = threadIdx.x & 31;
    if (warp >= NN) return;
    int d = warp;

    float4 xrv[NJ], attv[NJ], acc[NJ];
    bool act[NJ];
#pragma unroll
    for (int j = 0; j < NJ; j++) {
        int cidx = lane + 32 * j;
        act[j] = (cidx < C4);
        float4 zf = make_float4(0.f, 0.f, 0.f, 0.f);
        xrv[j]  = act[j] ? *reinterpret_cast<const float4*>(&xr[(size_t)d * F + 4 * cidx]) : zf;
        attv[j] = act[j] ? *reinterpret_cast<const float4*>(&att[4 * cidx]) : zf;
        acc[j]  = zf;
    }
    int k0 = off[d], k1 = off[d + 1];

    float m = -1e30f, ssum = 0.f;

    int k = k0;
    for (; k + 1 < k1; k += 2) {
        int sa = ssrc[k], sb = ssrc[k + 1];
        const float4* xar = reinterpret_cast<const float4*>(xl + (size_t)sa * F);
        const float4* xbr = reinterpret_cast<const float4*>(xl + (size_t)sb * F);
        float4 xa[NJ], xb[NJ];
#pragma unroll
        for (int j = 0; j < NJ; j++) {
            int cidx = lane + 32 * j;
            float4 zf = make_float4(0.f, 0.f, 0.f, 0.f);
            xa[j] = act[j] ? xar[cidx] : zf;
            xb[j] = act[j] ? xbr[cidx] : zf;
        }
        float pa = 0.f, pb = 0.f;
#pragma unroll
        for (int j = 0; j < NJ; j++) {
            float v;
            v = xa[j].x + xrv[j].x; v = (v > 0.f) ? v : 0.2f * v; pa += v * attv[j].x;
            v = xa[j].y + xrv[j].y; v = (v > 0.f) ? v : 0.2f * v; pa += v * attv[j].y;
            v = xa[j].z + xrv[j].z; v = (v > 0.f) ? v : 0.2f * v; pa += v * attv[j].z;
            v = xa[j].w + xrv[j].w; v = (v > 0.f) ? v : 0.2f * v; pa += v * attv[j].w;
            v = xb[j].x + xrv[j].x; v = (v > 0.f) ? v : 0.2f * v; pb += v * attv[j].x;
            v = xb[j].y + xrv[j].y; v = (v > 0.f) ? v : 0.2f * v; pb += v * attv[j].y;
            v = xb[j].z + xrv[j].z; v = (v > 0.f) ? v : 0.2f * v; pb += v * attv[j].z;
            v = xb[j].w + xrv[j].w; v = (v > 0.f) ? v : 0.2f * v; pb += v * attv[j].w;
        }
#pragma unroll
        for (int o = 16; o > 0; o >>= 1) {
            pa += __shfl_xor_sync(0xffffffffu, pa, o);
            pb += __shfl_xor_sync(0xffffffffu, pb, o);
        }
        float mn = fmaxf(m, fmaxf(pa, pb));
        float sc = __expf(m - mn);
        float wa = __expf(pa - mn);
        float wb = __expf(pb - mn);
        ssum = ssum * sc + wa + wb;
#pragma unroll
        for (int j = 0; j < NJ; j++) {
            acc[j].x = acc[j].x * sc + wa * xa[j].x + wb * xb[j].x;
            acc[j].y = acc[j].y * sc + wa * xa[j].y + wb * xb[j].y;
            acc[j].z = acc[j].z * sc + wa * xa[j].z + wb * xb[j].z;
            acc[j].w = acc[j].w * sc + wa * xa[j].w + wb * xb[j].w;
        }
        m = mn;
    }
    if (k < k1) {
        int s = ssrc[k];
        const float4* xar = reinterpret_cast<const float4*>(xl + (size_t)s * F);
        float4 xa[NJ];
#pragma unroll
        for (int j = 0; j < NJ; j++) {
            int cidx = lane + 32 * j;
            xa[j] = act[j] ? xar[cidx] : make_float4(0.f, 0.f, 0.f, 0.f);
        }
        float p = 0.f;
#pragma unroll
        for (int j = 0; j < NJ; j++) {
            float v;
            v = xa[j].x + xrv[j].x; v = (v > 0.f) ? v : 0.2f * v; p += v * attv[j].x;
            v = xa[j].y + xrv[j].y; v = (v > 0.f) ? v : 0.2f * v; p += v * attv[j].y;
            v = xa[j].z + xrv[j].z; v = (v > 0.f) ? v : 0.2f * v; p += v * attv[j].z;
            v = xa[j].w + xrv[j].w; v = (v > 0.f) ? v : 0.2f * v; p += v * attv[j].w;
        }
#pragma unroll
        for (int o = 16; o > 0; o >>= 1) p += __shfl_xor_sync(0xffffffffu, p, o);
        float mn = fmaxf(m, p);
        float sc = __expf(m - mn);
        float w  = __expf(p - mn);
        ssum = ssum * sc + w;
#pragma unroll
        for (int j = 0; j < NJ; j++) {
            acc[j].x = acc[j].x * sc + w * xa[j].x;
            acc[j].y = acc[j].y * sc + w * xa[j].y;
            acc[j].z = acc[j].z * sc + w * xa[j].z;
            acc[j].w = acc[j].w * sc + w * xa[j].w;
        }
        m = mn;
    }

    float inv = 1.f / (ssum + 1e-16f);
#pragma unroll
    for (int j = 0; j < NJ; j++) {
        int cidx = lane + 32 * j;
        if (!act[j]) continue;
        float4 bv = *reinterpret_cast<const float4*>(&bias[4 * cidx]);
        float4 o;
        o.x = fmaxf(acc[j].x * inv + bv.x, 0.f);
        o.y = fmaxf(acc[j].y * inv + bv.y, 0.f);
        o.z = fmaxf(acc[j].z * inv + bv.z, 0.f);
        o.w = fmaxf(acc[j].w * inv + bv.w, 0.f);
        uint4 t;
        t.x = f2tf32(o.x); t.y = f2tf32(o.y);
        t.z = f2tf32(o.z); t.w = f2tf32(o.w);
        *reinterpret_cast<uint4*>(&out_tf[(size_t)d * F + 4 * cidx]) = t;
    }
}

// ---------------- GATv2 layer 2 (F=100), fused epilogue: emits z, xl3, xr3 ----------------
__global__ __launch_bounds__(256) void gat_agg100_fused(
    const float* __restrict__ xl, const float* __restrict__ xr,
    const float* __restrict__ att, const float* __restrict__ bias,
    const int* __restrict__ ssrc, const int* __restrict__ off,
    const float* __restrict__ lin1, const float* __restrict__ lin2,
    const float* __restrict__ Wl3, const float* __restrict__ Wr3,
    float* __restrict__ z, float* __restrict__ xl3, float* __restrict__ xr3)
{
    int warp = (blockIdx.x * blockDim.x + threadIdx.x) >> 5;
    int lane = threadIdx.x & 31;
    if (warp >= NN) return;
    int d = warp;
    bool on = (lane < 25);    // 25 float4 chunks cover F=100

    float4 zf = make_float4(0.f, 0.f, 0.f, 0.f);
    float4 xrv = on ? *reinterpret_cast<const float4*>(&xr[(size_t)d * 100 + 4 * lane]) : zf;
    float4 attv = on ? *reinterpret_cast<const float4*>(&att[4 * lane]) : zf;
    float4 acc = zf;
    int k0 = off[d], k1 = off[d + 1];

    float m = -1e30f, ssum = 0.f;

    int k = k0;
    for (; k + 1 < k1; k += 2) {
        int sa = ssrc[k], sb = ssrc[k + 1];
        float4 xa = on ? *reinterpret_cast<const float4*>(&xl[(size_t)sa * 100 + 4 * lane]) : zf;
        float4 xb = on ? *reinterpret_cast<const float4*>(&xl[(size_t)sb * 100 + 4 * lane]) : zf;
        float pa = 0.f, pb = 0.f, v;
        v = xa.x + xrv.x; v = (v > 0.f) ? v : 0.2f * v; pa += v * attv.x;
        v = xa.y + xrv.y; v = (v > 0.f) ? v : 0.2f * v; pa += v * attv.y;
        v = xa.z + xrv.z; v = (v > 0.f) ? v : 0.2f * v; pa += v * attv.z;
        v = xa.w + xrv.w; v = (v > 0.f) ? v : 0.2f * v; pa += v * attv.w;
        v = xb.x + xrv.x; v = (v > 0.f) ? v : 0.2f * v; pb += v * attv.x;
        v = xb.y + xrv.y; v = (v > 0.f) ? v : 0.2f * v; pb += v * attv.y;
        v = xb.z + xrv.z; v = (v > 0.f) ? v : 0.2f * v; pb += v * attv.z;
        v = xb.w + xrv.w; v = (v > 0.f) ? v : 0.2f * v; pb += v * attv.w;
#pragma unroll
        for (int o = 16; o > 0; o >>= 1) {
            pa += __shfl_xor_sync(0xffffffffu, pa, o);
            pb += __shfl_xor_sync(0xffffffffu, pb, o);
        }
        float mn = fmaxf(m, fmaxf(pa, pb));
        float sc = __expf(m - mn);
        float wa = __expf(pa - mn);
        float wb = __expf(pb - mn);
        ssum = ssum * sc + wa + wb;
        acc.x = acc.x * sc + wa * xa.x + wb * xb.x;
        acc.y = acc.y * sc + wa * xa.y + wb * xb.y;
        acc.z = acc.z * sc + wa * xa.z + wb * xb.z;
        acc.w = acc.w * sc + wa * xa.w + wb * xb.w;
        m = mn;
    }
    if (k < k1) {
        int s = ssrc[k];
        float4 xa = on ? *reinterpret_cast<const float4*>(&xl[(size_t)s * 100 + 4 * lane]) : zf;
        float p = 0.f, v;
        v = xa.x + xrv.x; v = (v > 0.f) ? v : 0.2f * v; p += v * attv.x;
        v = xa.y + xrv.y; v = (v > 0.f) ? v : 0.2f * v; p += v * attv.y;
        v = xa.z + xrv.z; v = (v > 0.f) ? v : 0.2f * v; p += v * attv.z;
        v = xa.w + xrv.w; v = (v > 0.f) ? v : 0.2f * v; p += v * attv.w;
#pragma unroll
        for (int o = 16; o > 0; o >>= 1) p += __shfl_xor_sync(0xffffffffu, p, o);
        float mn = fmaxf(m, p);
        float sc = __expf(m - mn);
        float w  = __expf(p - mn);
        ssum = ssum * sc + w;
        acc.x = acc.x * sc + w * xa.x;
        acc.y = acc.y * sc + w * xa.y;
        acc.z = acc.z * sc + w * xa.z;
        acc.w = acc.w * sc + w * xa.w;
        m = mn;
    }

    float inv = 1.f / (ssum + 1e-16f);
    float pl = 0.f, pr = 0.f;
    if (on) {
        float4 bv = *reinterpret_cast<const float4*>(&bias[4 * lane]);
        float4 h;
        h.x = fmaxf(acc.x * inv + bv.x, 0.f);
        h.y = fmaxf(acc.y * inv + bv.y, 0.f);
        h.z = fmaxf(acc.z * inv + bv.z, 0.f);
        h.w = fmaxf(acc.w * inv + bv.w, 0.f);
        float4 l1 = *reinterpret_cast<const float4*>(&lin1[(size_t)d * 100 + 4 * lane]);
        float4 l2 = *reinterpret_cast<const float4*>(&lin2[(size_t)d * 100 + 4 * lane]);
        float4 xo4, z4;
        xo4.x = h.x + l1.x; xo4.y = h.y + l1.y; xo4.z = h.z + l1.z; xo4.w = h.w + l1.w;
        z4.x  = h.x + l2.x; z4.y  = h.y + l2.y; z4.z  = h.z + l2.z; z4.w  = h.w + l2.w;
        *reinterpret_cast<float4*>(&z[(size_t)d * 100 + 4 * lane]) = z4;
        float4 wl = *reinterpret_cast<const float4*>(&Wl3[4 * lane]);
        float4 wr = *reinterpret_cast<const float4*>(&Wr3[4 * lane]);
        pl = xo4.x * wl.x + xo4.y * wl.y + xo4.z * wl.z + xo4.w * wl.w;
        pr = xo4.x * wr.x + xo4.y * wr.y + xo4.z * wr.z + xo4.w * wr.w;
    }
#pragma unroll
    for (int o = 16; o > 0; o >>= 1) {
        pl += __shfl_xor_sync(0xffffffffu, pl, o);
        pr += __shfl_xor_sync(0xffffffffu, pr, o);
    }
    if (lane == 0) { xl3[d] = pl; xr3[d] = pr; }
}

// ---------------- layer-3 GAT (F=1) ----------------
__global__ __launch_bounds__(256) void gat3_kernel(
    const float* __restrict__ xl3, const float* __restrict__ xr3,
    const float* __restrict__ att3, const float* __restrict__ b3,
    const int* __restrict__ ssrc, const int* __restrict__ off,
    float* __restrict__ out)
{
    int warp = (blockIdx.x * blockDim.x + threadIdx.x) >> 5;
    int lane = threadIdx.x & 31;
    if (warp >= NN) return;
    int d = warp;
    float a0 = att3[0];
    float xrd = xr3[d];
    int k0 = off[d], k1 = off[d + 1];

    float m = -1e30f;
    for (int k = k0 + lane; k < k1; k += 32) {
        float v = xl3[ssrc[k]] + xrd;
        v = (v > 0.f) ? v : 0.2f * v;
        m = fmaxf(m, v * a0);
    }
#pragma unroll
    for (int o = 16; o > 0; o >>= 1) m = fmaxf(m, __shfl_xor_sync(0xffffffffu, m, o));

    float ssum = 0.f, acc = 0.f;
    for (int k = k0 + lane; k < k1; k += 32) {
        float xs = xl3[ssrc[k]];
        float v = xs + xrd;
        v = (v > 0.f) ? v : 0.2f * v;
        float w = __expf(v * a0 - m);
        ssum += w;
        acc  += w * xs;
    }
#pragma unroll
    for (int o = 16; o > 0; o >>= 1) {
        ssum += __shfl_xor_sync(0xffffffffu, ssum, o);
        acc  += __shfl_xor_sync(0xffffffffu, acc, o);
    }
    if (lane == 0) out[d] = acc / (ssum + 1e-16f) + b3[0];
}

// ---------------- link-prediction loss ----------------
__global__ void loss_kernel(const float* __restrict__ z, const int* __restrict__ ei,
                            const int* __restrict__ nei, float* __restrict__ accum) {
    int half = gridDim.x >> 1;
    int positive = (blockIdx.x < half) ? 1 : 0;
    int bid = positive ? blockIdx.x : (blockIdx.x - half);
    const int* ea = positive ? ei : nei;
    const int* eb = positive ? (ei + EE) : (nei + EE);

    int warp = (bid * blockDim.x + threadIdx.x) >> 5;
    int lane = threadIdx.x & 31;
    int nwarps = (half * blockDim.x) >> 5;
    float local = 0.f;
    for (int e = warp * 2; e + 1 < EE; e += 2 * nwarps) {
        int a0 = ea[e],     b0 = eb[e];
        int a1 = ea[e + 1], b1 = eb[e + 1];
        float p0 = 0.f, p1 = 0.f;
        if (lane < 25) {
            float4 va0 = *reinterpret_cast<const float4*>(&z[(size_t)a0 * 100 + lane * 4]);
            float4 vb0 = *reinterpret_cast<const float4*>(&z[(size_t)b0 * 100 + lane * 4]);
            float4 va1 = *reinterpret_cast<const float4*>(&z[(size_t)a1 * 100 + lane * 4]);
            float4 vb1 = *reinterpret_cast<const float4*>(&z[(size_t)b1 * 100 + lane * 4]);
            p0 = va0.x * vb0.x + va0.y * vb0.y + va0.z * vb0.z + va0.w * vb0.w;
            p1 = va1.x * vb1.x + va1.y * vb1.y + va1.z * vb1.z + va1.w * vb1.w;
        }
#pragma unroll
        for (int o = 16; o > 0; o >>= 1) {
            p0 += __shfl_xor_sync(0xffffffffu, p0, o);
            p1 += __shfl_xor_sync(0xffffffffu, p1, o);
        }
        if (lane == 0) {
            float s0 = 1.f / (1.f + __expf(-p0));
            float s1 = 1.f / (1.f + __expf(-p1));
            if (positive) local += __logf(s0 + 1e-15f) + __logf(s1 + 1e-15f);
            else          local += __logf(1.f - s0 + 1e-15f) + __logf(1.f - s1 + 1e-15f);
        }
    }
    if (lane == 0) atomicAdd(&accum[positive ? 0 : 1], local);
}

__global__ void finalize_kernel(float* __restrict__ d_out, const float* __restrict__ loss,
                                const float* __restrict__ c1, const float* __restrict__ c2) {
    if (threadIdx.x == 0) {
        d_out[NN]     = -(loss[0] + loss[1]) / (float)EE;
        d_out[NN + 1] = c1[0];
        d_out[NN + 2] = c2[0];
    }
}

// ---------------- launch ----------------
extern "C" void kernel_launch(void* const* d_in, const int* in_sizes, int n_in,
                              void* d_out, int out_size) {
    const float* x     = (const float*)d_in[0];
    const int*   ei    = (const int*)  d_in[1];
    const int*   nei   = (const int*)  d_in[2];
    const float* Wl1   = (const float*)d_in[3];
    const float* Wr1   = (const float*)d_in[4];
    const float* att1  = (const float*)d_in[5];
    const float* b1    = (const float*)d_in[6];
    const float* Wl2   = (const float*)d_in[7];
    const float* Wr2   = (const float*)d_in[8];
    const float* att2  = (const float*)d_in[9];
    const float* b2    = (const float*)d_in[10];
    const float* Wl3   = (const float*)d_in[11];
    const float* Wr3   = (const float*)d_in[12];
    const float* att3  = (const float*)d_in[13];
    const float* b3    = (const float*)d_in[14];
    const float* Wlin1 = (const float*)d_in[15];
    const float* blin1 = (const float*)d_in[16];
    const float* Wlin2 = (const float*)d_in[17];
    const float* blin2 = (const float*)d_in[18];
    const float* c1    = (const float*)d_in[19];
    const float* c2    = (const float*)d_in[20];
    float* out = (float*)d_out;

    uint32_t *xtf, *h1tf, *wtf;
    float *xl1, *xr1, *xl2, *xr2, *lin1, *lin2, *z, *xl3, *xr3, *loss;
    int *deg, *off, *cur, *ssrc;
    cudaGetSymbolAddress((void**)&xtf,  g_xtf);
    cudaGetSymbolAddress((void**)&h1tf, g_h1tf);
    cudaGetSymbolAddress((void**)&wtf,  g_wtf);
    cudaGetSymbolAddress((void**)&xl1,  g_xl1);
    cudaGetSymbolAddress((void**)&xr1,  g_xr1);
    cudaGetSymbolAddress((void**)&xl2,  g_xl2);
    cudaGetSymbolAddress((void**)&xr2,  g_xr2);
    cudaGetSymbolAddress((void**)&lin1, g_lin1);
    cudaGetSymbolAddress((void**)&lin2, g_lin2);
    cudaGetSymbolAddress((void**)&z,    g_z);
    cudaGetSymbolAddress((void**)&xl3,  g_xl3);
    cudaGetSymbolAddress((void**)&xr3,  g_xr3);
    cudaGetSymbolAddress((void**)&loss, g_loss);
    cudaGetSymbolAddress((void**)&deg,  g_deg);
    cudaGetSymbolAddress((void**)&off,  g_off);
    cudaGetSymbolAddress((void**)&cur,  g_cur);
    cudaGetSymbolAddress((void**)&ssrc, g_src);

    // side streams + fork/join events (capturable pattern)
    cudaStream_t sCsr, sLoss;
    cudaStreamCreateWithFlags(&sCsr,  cudaStreamNonBlocking);
    cudaStreamCreateWithFlags(&sLoss, cudaStreamNonBlocking);
    cudaEvent_t evRoot, evCsr, evMid, evLoss;
    cudaEventCreateWithFlags(&evRoot, cudaEventDisableTiming);
    cudaEventCreateWithFlags(&evCsr,  cudaEventDisableTiming);
    cudaEventCreateWithFlags(&evMid,  cudaEventDisableTiming);
    cudaEventCreateWithFlags(&evLoss, cudaEventDisableTiming);

    // ---- fork: CSR build on side stream (depends only on ei) ----
    cudaEventRecord(evRoot, 0);
    cudaStreamWaitEvent(sCsr, evRoot, 0);
    zero_kernel<<<(NN + 255) / 256, 256, 0, sCsr>>>(deg, cur, loss);
    hist_kernel<<<(E2T + 255) / 256, 256, 0, sCsr>>>(ei, deg);
    scan_kernel<<<1, 1024, 0, sCsr>>>(deg, off);
    scatter_kernel<<<(E2T + 255) / 256, 256, 0, sCsr>>>(ei, cur, off, ssrc);
    cudaEventRecord(evCsr, sCsr);

    // ---- main stream: tf32 conversion + layer-1 GEMM ----
    {
        CSeg c0 = { x,     xtf,             NN * 500 / 4 };
        CSeg c1s= { Wl1,   wtf + OFF_WL1,   150000 / 4 };
        CSeg c2s= { Wr1,   wtf + OFF_WR1,   150000 / 4 };
        CSeg c3 = { Wlin1, wtf + OFF_WLIN1, 50000 / 4 };
        CSeg c4 = { Wlin2, wtf + OFF_WLIN2, 50000 / 4 };
        CSeg c5 = { Wl2,   wtf + OFF_WL2,   30000 / 4 };
        CSeg c6 = { Wr2,   wtf + OFF_WR2,   30000 / 4 };
        int n4 = NN * 500 / 4;
        conv_multi<<<(n4 + 255) / 256, 256>>>(c0, c1s, c2s, c3, c4, c5, c6);
    }

    dim3 tb(256);
    int rows = (NN + BM - 1) / BM;   // 107
    {
        GSeg s0 = { wtf + OFF_WL1,   nullptr, xl1,  300, 0, 0  };
        GSeg s1 = { wtf + OFF_WR1,   nullptr, xr1,  300, 0, 5  };
        GSeg s2 = { wtf + OFF_WLIN1, blin1,   lin1, 100, 1, 10 };
        GSeg s3 = { wtf + OFF_WLIN2, blin2,   lin2, 100, 1, 12 };
        gemm_tf32_multi<<<dim3(14, rows), tb>>>(xtf, NN, 500, s0, s1, s2, s3, 4);
    }

    // ---- join CSR, then edge phase ----
    cudaStreamWaitEvent(0, evCsr, 0);
    int agg_blocks = (NN + 7) / 8;
    gat_agg_kernel<300><<<agg_blocks, 256>>>(xl1, xr1, att1, b1, ssrc, off, h1tf);

    {
        GSeg s0 = { wtf + OFF_WL2, nullptr, xl2, 100, 0, 0 };
        GSeg s1 = { wtf + OFF_WR2, nullptr, xr2, 100, 0, 2 };
        gemm_tf32_multi<<<dim3(4, rows), tb>>>(h1tf, NN, 300, s0, s1, s0, s1, 2);
    }
    gat_agg100_fused<<<agg_blocks, 256>>>(xl2, xr2, att2, b2, ssrc, off,
                                          lin1, lin2, Wl3, Wr3, z, xl3, xr3);

    // ---- fork: loss on side stream, gat3 on main ----
    cudaEventRecord(evMid, 0);
    cudaStreamWaitEvent(sLoss, evMid, 0);
    loss_kernel<<<4096, 256, 0, sLoss>>>(z, ei, nei, loss);
    cudaEventRecord(evLoss, sLoss);

    gat3_kernel<<<agg_blocks, 256>>>(xl3, xr3, att3, b3, ssrc, off, out);

    cudaStreamWaitEvent(0, evLoss, 0);
    finalize_kernel<<<1, 32>>>(out, loss, c1, c2);

    cudaEventDestroy(evRoot);
    cudaEventDestroy(evCsr);
    cudaEventDestroy(evMid);
    cudaEventDestroy(evLoss);
    cudaStreamDestroy(sCsr);
    cudaStreamDestroy(sLoss);
}

// round 12
// speedup vs baseline: 3.2370x; 1.0124x over previous
#include <cuda_runtime.h>
#include <math.h>
#include <stdint.h>

#define NN 13627
#define EE 504378
#define E2T (EE + NN)

// ---------------- scratch (static device globals; no allocation) ----------------
__device__ uint32_t g_xtf [NN * 500];   // x as tf32 bits
__device__ uint32_t g_h1tf[NN * 300];   // h1 as tf32 bits
__device__ uint32_t g_wtf [460000];     // all weights as tf32 bits
__device__ float g_xl1[NN * 300];
__device__ float g_xr1[NN * 300];
__device__ float g_xl2[NN * 100];
__device__ float g_xr2[NN * 100];
__device__ float g_lin1[NN * 100];
__device__ float g_lin2[NN * 100];
__device__ uint32_t g_zb[NN * 50];      // z as bf16x2 (loss-only consumer)
__device__ float g_xl3[NN];
__device__ float g_xr3[NN];
__device__ int   g_deg[NN];
__device__ int   g_off[NN + 1];
__device__ int   g_cur[NN];
__device__ int   g_src[E2T];
__device__ float g_loss[2];

// weight offsets inside g_wtf
#define OFF_WL1   0
#define OFF_WR1   150000
#define OFF_WLIN1 300000
#define OFF_WLIN2 350000
#define OFF_WL2   400000
#define OFF_WR2   430000

__device__ __forceinline__ uint32_t f2tf32(float f) {
    uint32_t o;
    asm("cvt.rna.tf32.f32 %0, %1;" : "=r"(o) : "f"(f));
    return o;
}

// pack two floats into bf16x2 bits (lo = first arg, hi = second)
__device__ __forceinline__ uint32_t pack_bf16x2(float lo, float hi) {
    uint32_t o;
    asm("cvt.rn.bf16x2.f32 %0, %1, %2;" : "=r"(o) : "f"(hi), "f"(lo));
    return o;
}
// exact bf16->fp32 widening via bit ops
__device__ __forceinline__ float bf16lo(uint32_t v) { return __uint_as_float(v << 16); }
__device__ __forceinline__ float bf16hi(uint32_t v) { return __uint_as_float(v & 0xffff0000u); }

// ---------------- tf32 conversion: 7 segments in one launch ----------------
struct CSeg { const float* src; uint32_t* dst; int n4; };  // n4 = n/4

__global__ void conv_multi(CSeg c0, CSeg c1, CSeg c2, CSeg c3, CSeg c4, CSeg c5, CSeg c6) {
    int i = blockIdx.x * blockDim.x + threadIdx.x;
    CSeg segs[7] = {c0, c1, c2, c3, c4, c5, c6};
#pragma unroll
    for (int j = 0; j < 7; j++) {
        if (i < segs[j].n4) {
            float4 v = reinterpret_cast<const float4*>(segs[j].src)[i];
            uint4 o;
            o.x = f2tf32(v.x); o.y = f2tf32(v.y);
            o.z = f2tf32(v.z); o.w = f2tf32(v.w);
            reinterpret_cast<uint4*>(segs[j].dst)[i] = o;
        }
    }
}

// ---------------- utility kernels ----------------
__global__ void zero_kernel(int* deg, int* cur, float* loss) {
    int i = blockIdx.x * blockDim.x + threadIdx.x;
    if (i < NN) { deg[i] = 0; cur[i] = 0; }
    if (i < 2) loss[i] = 0.f;
}

__global__ void hist_kernel(const int* __restrict__ ei, int* __restrict__ deg) {
    int k = blockIdx.x * blockDim.x + threadIdx.x;
    if (k >= E2T) return;
    int d = (k < EE) ? ei[EE + k] : (k - EE);
    atomicAdd(&deg[d], 1);
}

__global__ void scan_kernel(const int* __restrict__ deg, int* __restrict__ off) {
    __shared__ int sdata[1024];
    const int n = NN;
    int tid = threadIdx.x;
    const int per = (n + 1023) / 1024;  // 14
    int start = tid * per;
    int vals[16];
    int local = 0;
    for (int i = 0; i < per; i++) {
        int idx = start + i;
        int v = (idx < n) ? deg[idx] : 0;
        vals[i] = local;
        local += v;
    }
    sdata[tid] = local;
    __syncthreads();
    for (int ofs = 1; ofs < 1024; ofs <<= 1) {
        int v = (tid >= ofs) ? sdata[tid - ofs] : 0;
        __syncthreads();
        sdata[tid] += v;
        __syncthreads();
    }
    int base = (tid == 0) ? 0 : sdata[tid - 1];
    for (int i = 0; i < per; i++) {
        int idx = start + i;
        if (idx < n) off[idx] = base + vals[i];
    }
    if (tid == 0) off[n] = sdata[1023];
}

__global__ void scatter_kernel(const int* __restrict__ ei, int* __restrict__ cur,
                               const int* __restrict__ off, int* __restrict__ ssrc) {
    int k = blockIdx.x * blockDim.x + threadIdx.x;
    if (k >= E2T) return;
    int s, d;
    if (k < EE) { s = ei[k]; d = ei[EE + k]; }
    else        { s = d = k - EE; }
    int pos = off[d] + atomicAdd(&cur[d], 1);
    ssrc[pos] = s;
}

// ---------------- TF32 GEMM, cp.async double-buffered, multi-segment B ----------------
#define BM 128
#define BN 64
#define BK 16
#define AS_STRIDE 20
#define BS_STRIDE 72

struct GSeg {
    const uint32_t* B;   // tf32 bits [K,N]
    const float* bias;
    float* C;
    int N;
    int act;
    int blk0;
};

__device__ __forceinline__ void cpa16(uint32_t dst, const void* src, int sz) {
    asm volatile("cp.async.ca.shared.global [%0], [%1], 16, %2;\n"
                 :: "r"(dst), "l"(src), "r"(sz));
}

__global__ __launch_bounds__(256) void gemm_tf32_multi(
    const uint32_t* __restrict__ A, int M, int K,
    GSeg s0, GSeg s1, GSeg s2, GSeg s3, int nseg)
{
    __shared__ uint32_t As[2][BM][AS_STRIDE];
    __shared__ uint32_t Bs[2][BK][BS_STRIDE];

    GSeg sg = s0;
    if (nseg > 1 && (int)blockIdx.x >= s1.blk0) sg = s1;
    if (nseg > 2 && (int)blockIdx.x >= s2.blk0) sg = s2;
    if (nseg > 3 && (int)blockIdx.x >= s3.blk0) sg = s3;
    const uint32_t* B = sg.B;
    int N = sg.N;

    int tid  = threadIdx.x;
    int warp = tid >> 5, lane = tid & 31;
    int warp_m = warp & 3;
    int warp_n = warp >> 2;
    int row0 = blockIdx.y * BM;
    int col0 = ((int)blockIdx.x - sg.blk0) * BN;
    int qr = lane >> 2;
    int qc = lane & 3;

    int ar = tid >> 2;
    int ac = (tid & 3) * 4;
    int br = tid >> 4;
    int bc = (tid & 15) * 4;

    uint32_t as_base = (uint32_t)__cvta_generic_to_shared(&As[0][0][0]);
    uint32_t bs_base = (uint32_t)__cvta_generic_to_shared(&Bs[0][0][0]);
    const uint32_t asbuf = BM * AS_STRIDE * 4;
    const uint32_t bsbuf = BK * BS_STRIDE * 4;

    int ntiles = (K + BK - 1) / BK;

    float c[2][4][4];
#pragma unroll
    for (int mi = 0; mi < 2; mi++)
#pragma unroll
        for (int nj = 0; nj < 4; nj++)
#pragma unroll
            for (int q = 0; q < 4; q++) c[mi][nj][q] = 0.f;

    auto load_tile = [&](int t, int buf) {
        int k0 = t * BK;
#pragma unroll
        for (int h = 0; h < 2; h++) {
            int r  = ar + h * 64;
            int gr = row0 + r;
            int gk = k0 + ac;
            bool ok = (gr < M) && (gk + 3 < K);
            const uint32_t* src = ok ? (A + (size_t)gr * K + gk) : A;
            cpa16(as_base + buf * asbuf + (r * AS_STRIDE + ac) * 4, src, ok ? 16 : 0);
        }
        {
            int gk = k0 + br;
            int gc = col0 + bc;
            bool ok = (gk < K) && (gc + 3 < N);
            const uint32_t* src = ok ? (B + (size_t)gk * N + gc) : B;
            cpa16(bs_base + buf * bsbuf + (br * BS_STRIDE + bc) * 4, src, ok ? 16 : 0);
        }
        asm volatile("cp.async.commit_group;\n");
    };

    load_tile(0, 0);

    for (int t = 0; t < ntiles; t++) {
        asm volatile("cp.async.wait_group 0;\n");
        __syncthreads();
        if (t + 1 < ntiles) load_tile(t + 1, (t + 1) & 1);
        int buf = t & 1;

#pragma unroll
        for (int ks = 0; ks < 2; ks++) {
            int kb = ks * 8;
            uint32_t afrag[2][4], bfrag[4][2];
#pragma unroll
            for (int mi = 0; mi < 2; mi++) {
                int mrow = warp_m * 32 + mi * 16 + qr;
                afrag[mi][0] = As[buf][mrow    ][kb + qc];
                afrag[mi][1] = As[buf][mrow + 8][kb + qc];
                afrag[mi][2] = As[buf][mrow    ][kb + qc + 4];
                afrag[mi][3] = As[buf][mrow + 8][kb + qc + 4];
            }
#pragma unroll
            for (int nj = 0; nj < 4; nj++) {
                int ncol = warp_n * 32 + nj * 8 + qr;
                bfrag[nj][0] = Bs[buf][kb + qc    ][ncol];
                bfrag[nj][1] = Bs[buf][kb + qc + 4][ncol];
            }
#pragma unroll
            for (int mi = 0; mi < 2; mi++)
#pragma unroll
                for (int nj = 0; nj < 4; nj++) {
                    asm volatile(
                        "mma.sync.aligned.m16n8k8.row.col.f32.tf32.tf32.f32 "
                        "{%0,%1,%2,%3}, {%4,%5,%6,%7}, {%8,%9}, {%0,%1,%2,%3};"
                        : "+f"(c[mi][nj][0]), "+f"(c[mi][nj][1]),
                          "+f"(c[mi][nj][2]), "+f"(c[mi][nj][3])
                        : "r"(afrag[mi][0]), "r"(afrag[mi][1]),
                          "r"(afrag[mi][2]), "r"(afrag[mi][3]),
                          "r"(bfrag[nj][0]), "r"(bfrag[nj][1]));
                }
        }
        __syncthreads();
    }

#pragma unroll
    for (int mi = 0; mi < 2; mi++) {
#pragma unroll
        for (int rh = 0; rh < 2; rh++) {
            int gr = row0 + warp_m * 32 + mi * 16 + rh * 8 + qr;
            if (gr >= M) continue;
#pragma unroll
            for (int nj = 0; nj < 4; nj++) {
#pragma unroll
                for (int jc = 0; jc < 2; jc++) {
                    int gc = col0 + warp_n * 32 + nj * 8 + qc * 2 + jc;
                    if (gc >= N) continue;
                    float v = c[mi][nj][rh * 2 + jc];
                    if (sg.bias) v += sg.bias[gc];
                    if (sg.act) v = fmaxf(v, 0.f);
                    sg.C[(size_t)gr * N + gc] = v;
                }
            }
        }
    }
}

// ---------------- GATv2 layer 1: paired-edge online softmax, emits tf32 h1 ----------------
template <int F>
__global__ __launch_bounds__(256) void gat_agg_kernel(
    const float* __restrict__ xl, const float* __restrict__ xr,
    const float* __restrict__ att, const float* __restrict__ bias,
    const int* __restrict__ ssrc, const int* __restrict__ off,
    uint32_t* __restrict__ out_tf)
{
    static_assert(F % 4 == 0, "F must be multiple of 4");
    constexpr int C4 = F / 4;
    constexpr int NJ = (C4 + 31) / 32;
    int warp = (blockIdx.x * blockDim.x + threadIdx.x) >> 5;
    int lane = threadIdx.x & 31;
    if (warp >= NN) return;
    int d = warp;

    float4 xrv[NJ], attv[NJ], acc[NJ];
    bool act[NJ];
#pragma unroll
    for (int j = 0; j < NJ; j++) {
        int cidx = lane + 32 * j;
        act[j] = (cidx < C4);
        float4 zf = make_float4(0.f, 0.f, 0.f, 0.f);
        xrv[j]  = act[j] ? *reinterpret_cast<const float4*>(&xr[(size_t)d * F + 4 * cidx]) : zf;
        attv[j] = act[j] ? *reinterpret_cast<const float4*>(&att[4 * cidx]) : zf;
        acc[j]  = zf;
    }
    int k0 = off[d], k1 = off[d + 1];

    float m = -1e30f, ssum = 0.f;

    int k = k0;
    for (; k + 1 < k1; k += 2) {
        int sa = ssrc[k], sb = ssrc[k + 1];
        const float4* xar = reinterpret_cast<const float4*>(xl + (size_t)sa * F);
        const float4* xbr = reinterpret_cast<const float4*>(xl + (size_t)sb * F);
        float4 xa[NJ], xb[NJ];
#pragma unroll
        for (int j = 0; j < NJ; j++) {
            int cidx = lane + 32 * j;
            float4 zf = make_float4(0.f, 0.f, 0.f, 0.f);
            xa[j] = act[j] ? xar[cidx] : zf;
            xb[j] = act[j] ? xbr[cidx] : zf;
        }
        float pa = 0.f, pb = 0.f;
#pragma unroll
        for (int j = 0; j < NJ; j++) {
            float v;
            v = xa[j].x + xrv[j].x; v = (v > 0.f) ? v : 0.2f * v; pa += v * attv[j].x;
            v = xa[j].y + xrv[j].y; v = (v > 0.f) ? v : 0.2f * v; pa += v * attv[j].y;
            v = xa[j].z + xrv[j].z; v = (v > 0.f) ? v : 0.2f * v; pa += v * attv[j].z;
            v = xa[j].w + xrv[j].w; v = (v > 0.f) ? v : 0.2f * v; pa += v * attv[j].w;
            v = xb[j].x + xrv[j].x; v = (v > 0.f) ? v : 0.2f * v; pb += v * attv[j].x;
            v = xb[j].y + xrv[j].y; v = (v > 0.f) ? v : 0.2f * v; pb += v * attv[j].y;
            v = xb[j].z + xrv[j].z; v = (v > 0.f) ? v : 0.2f * v; pb += v * attv[j].z;
            v = xb[j].w + xrv[j].w; v = (v > 0.f) ? v : 0.2f * v; pb += v * attv[j].w;
        }
#pragma unroll
        for (int o = 16; o > 0; o >>= 1) {
            pa += __shfl_xor_sync(0xffffffffu, pa, o);
            pb += __shfl_xor_sync(0xffffffffu, pb, o);
        }
        float mn = fmaxf(m, fmaxf(pa, pb));
        float sc = __expf(m - mn);
        float wa = __expf(pa - mn);
        float wb = __expf(pb - mn);
        ssum = ssum * sc + wa + wb;
#pragma unroll
        for (int j = 0; j < NJ; j++) {
            acc[j].x = acc[j].x * sc + wa * xa[j].x + wb * xb[j].x;
            acc[j].y = acc[j].y * sc + wa * xa[j].y + wb * xb[j].y;
            acc[j].z = acc[j].z * sc + wa * xa[j].z + wb * xb[j].z;
            acc[j].w = acc[j].w * sc + wa * xa[j].w + wb * xb[j].w;
        }
        m = mn;
    }
    if (k < k1) {
        int s = ssrc[k];
        const float4* xar = reinterpret_cast<const float4*>(xl + (size_t)s * F);
        float4 xa[NJ];
#pragma unroll
        for (int j = 0; j < NJ; j++) {
            int cidx = lane + 32 * j;
            xa[j] = act[j] ? xar[cidx] : make_float4(0.f, 0.f, 0.f, 0.f);
        }
        float p = 0.f;
#pragma unroll
        for (int j = 0; j < NJ; j++) {
            float v;
            v = xa[j].x + xrv[j].x; v = (v > 0.f) ? v : 0.2f * v; p += v * attv[j].x;
            v = xa[j].y + xrv[j].y; v = (v > 0.f) ? v : 0.2f * v; p += v * attv[j].y;
            v = xa[j].z + xrv[j].z; v = (v > 0.f) ? v : 0.2f * v; p += v * attv[j].z;
            v = xa[j].w + xrv[j].w; v = (v > 0.f) ? v : 0.2f * v; p += v * attv[j].w;
        }
#pragma unroll
        for (int o = 16; o > 0; o >>= 1) p += __shfl_xor_sync(0xffffffffu, p, o);
        float mn = fmaxf(m, p);
        float sc = __expf(m - mn);
        float w  = __expf(p - mn);
        ssum = ssum * sc + w;
#pragma unroll
        for (int j = 0; j < NJ; j++) {
            acc[j].x = acc[j].x * sc + w * xa[j].x;
            acc[j].y = acc[j].y * sc + w * xa[j].y;
            acc[j].z = acc[j].z * sc + w * xa[j].z;
            acc[j].w = acc[j].w * sc + w * xa[j].w;
        }
        m = mn;
    }

    float inv = 1.f / (ssum + 1e-16f);
#pragma unroll
    for (int j = 0; j < NJ; j++) {
        int cidx = lane + 32 * j;
        if (!act[j]) continue;
        float4 bv = *reinterpret_cast<const float4*>(&bias[4 * cidx]);
        float4 o;
        o.x = fmaxf(acc[j].x * inv + bv.x, 0.f);
        o.y = fmaxf(acc[j].y * inv + bv.y, 0.f);
        o.z = fmaxf(acc[j].z * inv + bv.z, 0.f);
        o.w = fmaxf(acc[j].w * inv + bv.w, 0.f);
        uint4 t;
        t.x = f2tf32(o.x); t.y = f2tf32(o.y);
        t.z = f2tf32(o.z); t.w = f2tf32(o.w);
        *reinterpret_cast<uint4*>(&out_tf[(size_t)d * F + 4 * cidx]) = t;
    }
}

// ---------------- GATv2 layer 2 (F=100), fused epilogue: emits z(bf16), xl3, xr3 ----------------
__global__ __launch_bounds__(256) void gat_agg100_fused(
    const float* __restrict__ xl, const float* __restrict__ xr,
    const float* __restrict__ att, const float* __restrict__ bias,
    const int* __restrict__ ssrc, const int* __restrict__ off,
    const float* __restrict__ lin1, const float* __restrict__ lin2,
    const float* __restrict__ Wl3, const float* __restrict__ Wr3,
    uint32_t* __restrict__ zb, float* __restrict__ xl3, float* __restrict__ xr3)
{
    int warp = (blockIdx.x * blockDim.x + threadIdx.x) >> 5;
    int lane = threadIdx.x & 31;
    if (warp >= NN) return;
    int d = warp;
    bool on = (lane < 25);    // 25 float4 chunks cover F=100

    float4 zf = make_float4(0.f, 0.f, 0.f, 0.f);
    float4 xrv = on ? *reinterpret_cast<const float4*>(&xr[(size_t)d * 100 + 4 * lane]) : zf;
    float4 attv = on ? *reinterpret_cast<const float4*>(&att[4 * lane]) : zf;
    float4 acc = zf;
    int k0 = off[d], k1 = off[d + 1];

    float m = -1e30f, ssum = 0.f;

    int k = k0;
    for (; k + 1 < k1; k += 2) {
        int sa = ssrc[k], sb = ssrc[k + 1];
        float4 xa = on ? *reinterpret_cast<const float4*>(&xl[(size_t)sa * 100 + 4 * lane]) : zf;
        float4 xb = on ? *reinterpret_cast<const float4*>(&xl[(size_t)sb * 100 + 4 * lane]) : zf;
        float pa = 0.f, pb = 0.f, v;
        v = xa.x + xrv.x; v = (v > 0.f) ? v : 0.2f * v; pa += v * attv.x;
        v = xa.y + xrv.y; v = (v > 0.f) ? v : 0.2f * v; pa += v * attv.y;
        v = xa.z + xrv.z; v = (v > 0.f) ? v : 0.2f * v; pa += v * attv.z;
        v = xa.w + xrv.w; v = (v > 0.f) ? v : 0.2f * v; pa += v * attv.w;
        v = xb.x + xrv.x; v = (v > 0.f) ? v : 0.2f * v; pb += v * attv.x;
        v = xb.y + xrv.y; v = (v > 0.f) ? v : 0.2f * v; pb += v * attv.y;
        v = xb.z + xrv.z; v = (v > 0.f) ? v : 0.2f * v; pb += v * attv.z;
        v = xb.w + xrv.w; v = (v > 0.f) ? v : 0.2f * v; pb += v * attv.w;
#pragma unroll
        for (int o = 16; o > 0; o >>= 1) {
            pa += __shfl_xor_sync(0xffffffffu, pa, o);
            pb += __shfl_xor_sync(0xffffffffu, pb, o);
        }
        float mn = fmaxf(m, fmaxf(pa, pb));
        float sc = __expf(m - mn);
        float wa = __expf(pa - mn);
        float wb = __expf(pb - mn);
        ssum = ssum * sc + wa + wb;
        acc.x = acc.x * sc + wa * xa.x + wb * xb.x;
        acc.y = acc.y * sc + wa * xa.y + wb * xb.y;
        acc.z = acc.z * sc + wa * xa.z + wb * xb.z;
        acc.w = acc.w * sc + wa * xa.w + wb * xb.w;
        m = mn;
    }
    if (k < k1) {
        int s = ssrc[k];
        float4 xa = on ? *reinterpret_cast<const float4*>(&xl[(size_t)s * 100 + 4 * lane]) : zf;
        float p = 0.f, v;
        v = xa.x + xrv.x; v = (v > 0.f) ? v : 0.2f * v; p += v * attv.x;
        v = xa.y + xrv.y; v = (v > 0.f) ? v : 0.2f * v; p += v * attv.y;
        v = xa.z + xrv.z; v = (v > 0.f) ? v : 0.2f * v; p += v * attv.z;
        v = xa.w + xrv.w; v = (v > 0.f) ? v : 0.2f * v; p += v * attv.w;
#pragma unroll
        for (int o = 16; o > 0; o >>= 1) p += __shfl_xor_sync(0xffffffffu, p, o);
        float mn = fmaxf(m, p);
        float sc = __expf(m - mn);
        float w  = __expf(p - mn);
        ssum = ssum * sc + w;
        acc.x = acc.x * sc + w * xa.x;
        acc.y = acc.y * sc + w * xa.y;
        acc.z = acc.z * sc + w * xa.z;
        acc.w = acc.w * sc + w * xa.w;
        m = mn;
    }

    float inv = 1.f / (ssum + 1e-16f);
    float pl = 0.f, pr = 0.f;
    if (on) {
        float4 bv = *reinterpret_cast<const float4*>(&bias[4 * lane]);
        float4 h;
        h.x = fmaxf(acc.x * inv + bv.x, 0.f);
        h.y = fmaxf(acc.y * inv + bv.y, 0.f);
        h.z = fmaxf(acc.z * inv + bv.z, 0.f);
        h.w = fmaxf(acc.w * inv + bv.w, 0.f);
        float4 l1 = *reinterpret_cast<const float4*>(&lin1[(size_t)d * 100 + 4 * lane]);
        float4 l2 = *reinterpret_cast<const float4*>(&lin2[(size_t)d * 100 + 4 * lane]);
        float4 xo4, z4;
        xo4.x = h.x + l1.x; xo4.y = h.y + l1.y; xo4.z = h.z + l1.z; xo4.w = h.w + l1.w;
        z4.x  = h.x + l2.x; z4.y  = h.y + l2.y; z4.z  = h.z + l2.z; z4.w  = h.w + l2.w;
        // z as bf16x2 pairs (consumed only by the loss kernel)
        uint2 zp;
        zp.x = pack_bf16x2(z4.x, z4.y);
        zp.y = pack_bf16x2(z4.z, z4.w);
        *reinterpret_cast<uint2*>(&zb[(size_t)d * 50 + 2 * lane]) = zp;
        float4 wl = *reinterpret_cast<const float4*>(&Wl3[4 * lane]);
        float4 wr = *reinterpret_cast<const float4*>(&Wr3[4 * lane]);
        pl = xo4.x * wl.x + xo4.y * wl.y + xo4.z * wl.z + xo4.w * wl.w;
        pr = xo4.x * wr.x + xo4.y * wr.y + xo4.z * wr.z + xo4.w * wr.w;
    }
#pragma unroll
    for (int o = 16; o > 0; o >>= 1) {
        pl += __shfl_xor_sync(0xffffffffu, pl, o);
        pr += __shfl_xor_sync(0xffffffffu, pr, o);
    }
    if (lane == 0) { xl3[d] = pl; xr3[d] = pr; }
}

// ---------------- layer-3 GAT (F=1) ----------------
__global__ __launch_bounds__(256) void gat3_kernel(
    const float* __restrict__ xl3, const float* __restrict__ xr3,
    const float* __restrict__ att3, const float* __restrict__ b3,
    const int* __restrict__ ssrc, const int* __restrict__ off,
    float* __restrict__ out)
{
    int warp = (blockIdx.x * blockDim.x + threadIdx.x) >> 5;
    int lane = threadIdx.x & 31;
    if (warp >= NN) return;
    int d = warp;
    float a0 = att3[0];
    float xrd = xr3[d];
    int k0 = off[d], k1 = off[d + 1];

    float m = -1e30f;
    for (int k = k0 + lane; k < k1; k += 32) {
        float v = xl3[ssrc[k]] + xrd;
        v = (v > 0.f) ? v : 0.2f * v;
        m = fmaxf(m, v * a0);
    }
#pragma unroll
    for (int o = 16; o > 0; o >>= 1) m = fmaxf(m, __shfl_xor_sync(0xffffffffu, m, o));

    float ssum = 0.f, acc = 0.f;
    for (int k = k0 + lane; k < k1; k += 32) {
        float xs = xl3[ssrc[k]];
        float v = xs + xrd;
        v = (v > 0.f) ? v : 0.2f * v;
        float w = __expf(v * a0 - m);
        ssum += w;
        acc  += w * xs;
    }
#pragma unroll
    for (int o = 16; o > 0; o >>= 1) {
        ssum += __shfl_xor_sync(0xffffffffu, ssum, o);
        acc  += __shfl_xor_sync(0xffffffffu, acc, o);
    }
    if (lane == 0) out[d] = acc / (ssum + 1e-16f) + b3[0];
}

// ---------------- link-prediction loss: bf16 z, paired edges ----------------
__global__ void loss_kernel(const uint32_t* __restrict__ zb, const int* __restrict__ ei,
                            const int* __restrict__ nei, float* __restrict__ accum) {
    int half = gridDim.x >> 1;
    int positive = (blockIdx.x < half) ? 1 : 0;
    int bid = positive ? blockIdx.x : (blockIdx.x - half);
    const int* ea = positive ? ei : nei;
    const int* eb = positive ? (ei + EE) : (nei + EE);

    int warp = (bid * blockDim.x + threadIdx.x) >> 5;
    int lane = threadIdx.x & 31;
    int nwarps = (half * blockDim.x) >> 5;
    float local = 0.f;
    for (int e = warp * 2; e + 1 < EE; e += 2 * nwarps) {
        int a0 = ea[e],     b0 = eb[e];
        int a1 = ea[e + 1], b1 = eb[e + 1];
        float p0 = 0.f, p1 = 0.f;
        if (lane < 25) {
            uint2 va0 = *reinterpret_cast<const uint2*>(&zb[(size_t)a0 * 50 + lane * 2]);
            uint2 vb0 = *reinterpret_cast<const uint2*>(&zb[(size_t)b0 * 50 + lane * 2]);
            uint2 va1 = *reinterpret_cast<const uint2*>(&zb[(size_t)a1 * 50 + lane * 2]);
            uint2 vb1 = *reinterpret_cast<const uint2*>(&zb[(size_t)b1 * 50 + lane * 2]);
            p0 += bf16lo(va0.x) * bf16lo(vb0.x) + bf16hi(va0.x) * bf16hi(vb0.x);
            p0 += bf16lo(va0.y) * bf16lo(vb0.y) + bf16hi(va0.y) * bf16hi(vb0.y);
            p1 += bf16lo(va1.x) * bf16lo(vb1.x) + bf16hi(va1.x) * bf16hi(vb1.x);
            p1 += bf16lo(va1.y) * bf16lo(vb1.y) + bf16hi(va1.y) * bf16hi(vb1.y);
        }
#pragma unroll
        for (int o = 16; o > 0; o >>= 1) {
            p0 += __shfl_xor_sync(0xffffffffu, p0, o);
            p1 += __shfl_xor_sync(0xffffffffu, p1, o);
        }
        if (lane == 0) {
            float s0 = 1.f / (1.f + __expf(-p0));
            float s1 = 1.f / (1.f + __expf(-p1));
            if (positive) local += __logf(s0 + 1e-15f) + __logf(s1 + 1e-15f);
            else          local += __logf(1.f - s0 + 1e-15f) + __logf(1.f - s1 + 1e-15f);
        }
    }
    if (lane == 0) atomicAdd(&accum[positive ? 0 : 1], local);
}

__global__ void finalize_kernel(float* __restrict__ d_out, const float* __restrict__ loss,
                                const float* __restrict__ c1, const float* __restrict__ c2) {
    if (threadIdx.x == 0) {
        d_out[NN]     = -(loss[0] + loss[1]) / (float)EE;
        d_out[NN + 1] = c1[0];
        d_out[NN + 2] = c2[0];
    }
}

// ---------------- launch ----------------
extern "C" void kernel_launch(void* const* d_in, const int* in_sizes, int n_in,
                              void* d_out, int out_size) {
    const float* x     = (const float*)d_in[0];
    const int*   ei    = (const int*)  d_in[1];
    const int*   nei   = (const int*)  d_in[2];
    const float* Wl1   = (const float*)d_in[3];
    const float* Wr1   = (const float*)d_in[4];
    const float* att1  = (const float*)d_in[5];
    const float* b1    = (const float*)d_in[6];
    const float* Wl2   = (const float*)d_in[7];
    const float* Wr2   = (const float*)d_in[8];
    const float* att2  = (const float*)d_in[9];
    const float* b2    = (const float*)d_in[10];
    const float* Wl3   = (const float*)d_in[11];
    const float* Wr3   = (const float*)d_in[12];
    const float* att3  = (const float*)d_in[13];
    const float* b3    = (const float*)d_in[14];
    const float* Wlin1 = (const float*)d_in[15];
    const float* blin1 = (const float*)d_in[16];
    const float* Wlin2 = (const float*)d_in[17];
    const float* blin2 = (const float*)d_in[18];
    const float* c1    = (const float*)d_in[19];
    const float* c2    = (const float*)d_in[20];
    float* out = (float*)d_out;

    uint32_t *xtf, *h1tf, *wtf, *zb;
    float *xl1, *xr1, *xl2, *xr2, *lin1, *lin2, *xl3, *xr3, *loss;
    int *deg, *off, *cur, *ssrc;
    cudaGetSymbolAddress((void**)&xtf,  g_xtf);
    cudaGetSymbolAddress((void**)&h1tf, g_h1tf);
    cudaGetSymbolAddress((void**)&wtf,  g_wtf);
    cudaGetSymbolAddress((void**)&xl1,  g_xl1);
    cudaGetSymbolAddress((void**)&xr1,  g_xr1);
    cudaGetSymbolAddress((void**)&xl2,  g_xl2);
    cudaGetSymbolAddress((void**)&xr2,  g_xr2);
    cudaGetSymbolAddress((void**)&lin1, g_lin1);
    cudaGetSymbolAddress((void**)&lin2, g_lin2);
    cudaGetSymbolAddress((void**)&zb,   g_zb);
    cudaGetSymbolAddress((void**)&xl3,  g_xl3);
    cudaGetSymbolAddress((void**)&xr3,  g_xr3);
    cudaGetSymbolAddress((void**)&loss, g_loss);
    cudaGetSymbolAddress((void**)&deg,  g_deg);
    cudaGetSymbolAddress((void**)&off,  g_off);
    cudaGetSymbolAddress((void**)&cur,  g_cur);
    cudaGetSymbolAddress((void**)&ssrc, g_src);

    // side streams + fork/join events (capturable pattern)
    cudaStream_t sCsr, sLin, sLoss;
    cudaStreamCreateWithFlags(&sCsr,  cudaStreamNonBlocking);
    cudaStreamCreateWithFlags(&sLin,  cudaStreamNonBlocking);
    cudaStreamCreateWithFlags(&sLoss, cudaStreamNonBlocking);
    cudaEvent_t evRoot, evCsr, evConv, evLin, evMid, evLoss;
    cudaEventCreateWithFlags(&evRoot, cudaEventDisableTiming);
    cudaEventCreateWithFlags(&evCsr,  cudaEventDisableTiming);
    cudaEventCreateWithFlags(&evConv, cudaEventDisableTiming);
    cudaEventCreateWithFlags(&evLin,  cudaEventDisableTiming);
    cudaEventCreateWithFlags(&evMid,  cudaEventDisableTiming);
    cudaEventCreateWithFlags(&evLoss, cudaEventDisableTiming);

    // ---- fork: CSR build on side stream (depends only on ei) ----
    cudaEventRecord(evRoot, 0);
    cudaStreamWaitEvent(sCsr, evRoot, 0);
    zero_kernel<<<(NN + 255) / 256, 256, 0, sCsr>>>(deg, cur, loss);
    hist_kernel<<<(E2T + 255) / 256, 256, 0, sCsr>>>(ei, deg);
    scan_kernel<<<1, 1024, 0, sCsr>>>(deg, off);
    scatter_kernel<<<(E2T + 255) / 256, 256, 0, sCsr>>>(ei, cur, off, ssrc);
    cudaEventRecord(evCsr, sCsr);

    // ---- main: tf32 conversion ----
    {
        CSeg c0 = { x,     xtf,             NN * 500 / 4 };
        CSeg c1s= { Wl1,   wtf + OFF_WL1,   150000 / 4 };
        CSeg c2s= { Wr1,   wtf + OFF_WR1,   150000 / 4 };
        CSeg c3 = { Wlin1, wtf + OFF_WLIN1, 50000 / 4 };
        CSeg c4 = { Wlin2, wtf + OFF_WLIN2, 50000 / 4 };
        CSeg c5 = { Wl2,   wtf + OFF_WL2,   30000 / 4 };
        CSeg c6 = { Wr2,   wtf + OFF_WR2,   30000 / 4 };
        int n4 = NN * 500 / 4;
        conv_multi<<<(n4 + 255) / 256, 256>>>(c0, c1s, c2s, c3, c4, c5, c6);
    }
    cudaEventRecord(evConv, 0);

    dim3 tb(256);
    int rows = (NN + BM - 1) / BM;   // 107

    // ---- fork: skip-linear GEMM on side stream (needed only at agg100_fused) ----
    cudaStreamWaitEvent(sLin, evConv, 0);
    {
        GSeg s0 = { wtf + OFF_WLIN1, blin1, lin1, 100, 1, 0 };
        GSeg s1 = { wtf + OFF_WLIN2, blin2, lin2, 100, 1, 2 };
        gemm_tf32_multi<<<dim3(4, rows), tb, 0, sLin>>>(xtf, NN, 500, s0, s1, s0, s1, 2);
    }
    cudaEventRecord(evLin, sLin);

    // ---- main: layer-1 attention projections ----
    {
        GSeg s0 = { wtf + OFF_WL1, nullptr, xl1, 300, 0, 0 };
        GSeg s1 = { wtf + OFF_WR1, nullptr, xr1, 300, 0, 5 };
        gemm_tf32_multi<<<dim3(10, rows), tb>>>(xtf, NN, 500, s0, s1, s0, s1, 2);
    }

    // ---- join CSR, then edge phase ----
    cudaStreamWaitEvent(0, evCsr, 0);
    int agg_blocks = (NN + 7) / 8;
    gat_agg_kernel<300><<<agg_blocks, 256>>>(xl1, xr1, att1, b1, ssrc, off, h1tf);

    {
        GSeg s0 = { wtf + OFF_WL2, nullptr, xl2, 100, 0, 0 };
        GSeg s1 = { wtf + OFF_WR2, nullptr, xr2, 100, 0, 2 };
        gemm_tf32_multi<<<dim3(4, rows), tb>>>(h1tf, NN, 300, s0, s1, s0, s1, 2);
    }

    // join the skip-linear GEMM before the fused layer-2 aggregation
    cudaStreamWaitEvent(0, evLin, 0);
    gat_agg100_fused<<<agg_blocks, 256>>>(xl2, xr2, att2, b2, ssrc, off,
                                          lin1, lin2, Wl3, Wr3, zb, xl3, xr3);

    // ---- fork: loss on side stream, gat3 on main ----
    cudaEventRecord(evMid, 0);
    cudaStreamWaitEvent(sLoss, evMid, 0);
    loss_kernel<<<4096, 256, 0, sLoss>>>(zb, ei, nei, loss);
    cudaEventRecord(evLoss, sLoss);

    gat3_kernel<<<agg_blocks, 256>>>(xl3, xr3, att3, b3, ssrc, off, out);

    cudaStreamWaitEvent(0, evLoss, 0);
    finalize_kernel<<<1, 32>>>(out, loss, c1, c2);

    cudaEventDestroy(evRoot);
    cudaEventDestroy(evCsr);
    cudaEventDestroy(evConv);
    cudaEventDestroy(evLin);
    cudaEventDestroy(evMid);
    cudaEventDestroy(evLoss);
    cudaStreamDestroy(sCsr);
    cudaStreamDestroy(sLin);
    cudaStreamDestroy(sLoss);
}

// round 13
// speedup vs baseline: 3.3031x; 1.0204x over previous
#include <cuda_runtime.h>
#include <math.h>
#include <stdint.h>

#define NN 13627
#define EE 504378
#define E2T (EE + NN)

// ---------------- scratch (static device globals; no allocation) ----------------
__device__ uint32_t g_xtf [NN * 500];   // x as tf32 bits
__device__ uint32_t g_h1tf[NN * 300];   // h1 as tf32 bits
__device__ uint32_t g_wtf [460000];     // all weights as tf32 bits
__device__ float g_xl1[NN * 300];
__device__ float g_xr1[NN * 300];
__device__ float g_xl2[NN * 100];
__device__ float g_xr2[NN * 100];
__device__ float g_lin1[NN * 100];
__device__ float g_lin2[NN * 100];
__device__ uint32_t g_zb[NN * 50];      // z as bf16x2 (loss-only consumer)
__device__ float g_xl3[NN];
__device__ float g_xr3[NN];
__device__ int   g_deg[NN];
__device__ int   g_off[NN + 1];
__device__ int   g_cur[NN];
__device__ int   g_src[E2T];
__device__ float g_loss[2];

// weight offsets inside g_wtf
#define OFF_WL1   0
#define OFF_WR1   150000
#define OFF_WLIN1 300000
#define OFF_WLIN2 350000
#define OFF_WL2   400000
#define OFF_WR2   430000

__device__ __forceinline__ uint32_t f2tf32(float f) {
    uint32_t o;
    asm("cvt.rna.tf32.f32 %0, %1;" : "=r"(o) : "f"(f));
    return o;
}

// pack two floats into bf16x2 bits (lo = first arg, hi = second)
__device__ __forceinline__ uint32_t pack_bf16x2(float lo, float hi) {
    uint32_t o;
    asm("cvt.rn.bf16x2.f32 %0, %1, %2;" : "=r"(o) : "f"(hi), "f"(lo));
    return o;
}
// exact bf16->fp32 widening via bit ops
__device__ __forceinline__ float bf16lo(uint32_t v) { return __uint_as_float(v << 16); }
__device__ __forceinline__ float bf16hi(uint32_t v) { return __uint_as_float(v & 0xffff0000u); }

// ---------------- tf32 conversion: 7 segments in one launch ----------------
struct CSeg { const float* src; uint32_t* dst; int n4; };  // n4 = n/4

__global__ void conv_multi(CSeg c0, CSeg c1, CSeg c2, CSeg c3, CSeg c4, CSeg c5, CSeg c6) {
    int i = blockIdx.x * blockDim.x + threadIdx.x;
    CSeg segs[7] = {c0, c1, c2, c3, c4, c5, c6};
#pragma unroll
    for (int j = 0; j < 7; j++) {
        if (i < segs[j].n4) {
            float4 v = reinterpret_cast<const float4*>(segs[j].src)[i];
            uint4 o;
            o.x = f2tf32(v.x); o.y = f2tf32(v.y);
            o.z = f2tf32(v.z); o.w = f2tf32(v.w);
            reinterpret_cast<uint4*>(segs[j].dst)[i] = o;
        }
    }
}

// ---------------- utility kernels ----------------
__global__ void zero_kernel(int* deg, int* cur, float* loss) {
    int i = blockIdx.x * blockDim.x + threadIdx.x;
    if (i < NN) { deg[i] = 0; cur[i] = 0; }
    if (i < 2) loss[i] = 0.f;
}

__global__ void hist_kernel(const int* __restrict__ ei, int* __restrict__ deg) {
    int k = blockIdx.x * blockDim.x + threadIdx.x;
    if (k >= E2T) return;
    int d = (k < EE) ? ei[EE + k] : (k - EE);
    atomicAdd(&deg[d], 1);
}

__global__ void scan_kernel(const int* __restrict__ deg, int* __restrict__ off) {
    __shared__ int sdata[1024];
    const int n = NN;
    int tid = threadIdx.x;
    const int per = (n + 1023) / 1024;  // 14
    int start = tid * per;
    int vals[16];
    int local = 0;
    for (int i = 0; i < per; i++) {
        int idx = start + i;
        int v = (idx < n) ? deg[idx] : 0;
        vals[i] = local;
        local += v;
    }
    sdata[tid] = local;
    __syncthreads();
    for (int ofs = 1; ofs < 1024; ofs <<= 1) {
        int v = (tid >= ofs) ? sdata[tid - ofs] : 0;
        __syncthreads();
        sdata[tid] += v;
        __syncthreads();
    }
    int base = (tid == 0) ? 0 : sdata[tid - 1];
    for (int i = 0; i < per; i++) {
        int idx = start + i;
        if (idx < n) off[idx] = base + vals[i];
    }
    if (tid == 0) off[n] = sdata[1023];
}

__global__ void scatter_kernel(const int* __restrict__ ei, int* __restrict__ cur,
                               const int* __restrict__ off, int* __restrict__ ssrc) {
    int k = blockIdx.x * blockDim.x + threadIdx.x;
    if (k >= E2T) return;
    int s, d;
    if (k < EE) { s = ei[k]; d = ei[EE + k]; }
    else        { s = d = k - EE; }
    int pos = off[d] + atomicAdd(&cur[d], 1);
    ssrc[pos] = s;
}

// ---------------- TF32 GEMM: BM=192, warp tile 48x32, cp.async double-buffered ----------------
#define BM 192
#define BN 64
#define BK 16
#define AS_STRIDE 20
#define BS_STRIDE 72

struct GSeg {
    const uint32_t* B;   // tf32 bits [K,N]
    const float* bias;
    float* C;
    int N;
    int act;
    int blk0;
};

__device__ __forceinline__ void cpa16(uint32_t dst, const void* src, int sz) {
    asm volatile("cp.async.ca.shared.global [%0], [%1], 16, %2;\n"
                 :: "r"(dst), "l"(src), "r"(sz));
}

__global__ __launch_bounds__(256) void gemm_tf32_multi(
    const uint32_t* __restrict__ A, int M, int K,
    GSeg s0, GSeg s1, GSeg s2, GSeg s3, int nseg)
{
    __shared__ uint32_t As[2][BM][AS_STRIDE];   // 30720 B
    __shared__ uint32_t Bs[2][BK][BS_STRIDE];   //  9216 B

    GSeg sg = s0;
    if (nseg > 1 && (int)blockIdx.x >= s1.blk0) sg = s1;
    if (nseg > 2 && (int)blockIdx.x >= s2.blk0) sg = s2;
    if (nseg > 3 && (int)blockIdx.x >= s3.blk0) sg = s3;
    const uint32_t* B = sg.B;
    int N = sg.N;

    int tid  = threadIdx.x;
    int warp = tid >> 5, lane = tid & 31;
    int warp_m = warp & 3;            // 4 warps along M, 48 rows each
    int warp_n = warp >> 2;           // 2 warps along N, 32 cols each
    int row0 = blockIdx.y * BM;
    int col0 = ((int)blockIdx.x - sg.blk0) * BN;
    int qr = lane >> 2;
    int qc = lane & 3;

    int ar = tid >> 2;                // 0..63
    int ac = (tid & 3) * 4;           // 0,4,8,12
    int br = tid >> 4;                // 0..15
    int bc = (tid & 15) * 4;          // 0..60

    uint32_t as_base = (uint32_t)__cvta_generic_to_shared(&As[0][0][0]);
    uint32_t bs_base = (uint32_t)__cvta_generic_to_shared(&Bs[0][0][0]);
    const uint32_t asbuf = BM * AS_STRIDE * 4;
    const uint32_t bsbuf = BK * BS_STRIDE * 4;

    int ntiles = (K + BK - 1) / BK;

    float c[3][4][4];
#pragma unroll
    for (int mi = 0; mi < 3; mi++)
#pragma unroll
        for (int nj = 0; nj < 4; nj++)
#pragma unroll
            for (int q = 0; q < 4; q++) c[mi][nj][q] = 0.f;

    auto load_tile = [&](int t, int buf) {
        int k0 = t * BK;
#pragma unroll
        for (int h = 0; h < 3; h++) {           // 192 rows = 3 x 64
            int r  = ar + h * 64;
            int gr = row0 + r;
            int gk = k0 + ac;
            bool ok = (gr < M) && (gk + 3 < K);
            const uint32_t* src = ok ? (A + (size_t)gr * K + gk) : A;
            cpa16(as_base + buf * asbuf + (r * AS_STRIDE + ac) * 4, src, ok ? 16 : 0);
        }
        {
            int gk = k0 + br;
            int gc = col0 + bc;
            bool ok = (gk < K) && (gc + 3 < N);
            const uint32_t* src = ok ? (B + (size_t)gk * N + gc) : B;
            cpa16(bs_base + buf * bsbuf + (br * BS_STRIDE + bc) * 4, src, ok ? 16 : 0);
        }
        asm volatile("cp.async.commit_group;\n");
    };

    load_tile(0, 0);

    for (int t = 0; t < ntiles; t++) {
        asm volatile("cp.async.wait_group 0;\n");
        __syncthreads();
        if (t + 1 < ntiles) load_tile(t + 1, (t + 1) & 1);
        int buf = t & 1;

#pragma unroll
        for (int ks = 0; ks < 2; ks++) {
            int kb = ks * 8;
            uint32_t afrag[3][4], bfrag[4][2];
#pragma unroll
            for (int mi = 0; mi < 3; mi++) {
                int mrow = warp_m * 48 + mi * 16 + qr;
                afrag[mi][0] = As[buf][mrow    ][kb + qc];
                afrag[mi][1] = As[buf][mrow + 8][kb + qc];
                afrag[mi][2] = As[buf][mrow    ][kb + qc + 4];
                afrag[mi][3] = As[buf][mrow + 8][kb + qc + 4];
            }
#pragma unroll
            for (int nj = 0; nj < 4; nj++) {
                int ncol = warp_n * 32 + nj * 8 + qr;
                bfrag[nj][0] = Bs[buf][kb + qc    ][ncol];
                bfrag[nj][1] = Bs[buf][kb + qc + 4][ncol];
            }
#pragma unroll
            for (int mi = 0; mi < 3; mi++)
#pragma unroll
                for (int nj = 0; nj < 4; nj++) {
                    asm volatile(
                        "mma.sync.aligned.m16n8k8.row.col.f32.tf32.tf32.f32 "
                        "{%0,%1,%2,%3}, {%4,%5,%6,%7}, {%8,%9}, {%0,%1,%2,%3};"
                        : "+f"(c[mi][nj][0]), "+f"(c[mi][nj][1]),
                          "+f"(c[mi][nj][2]), "+f"(c[mi][nj][3])
                        : "r"(afrag[mi][0]), "r"(afrag[mi][1]),
                          "r"(afrag[mi][2]), "r"(afrag[mi][3]),
                          "r"(bfrag[nj][0]), "r"(bfrag[nj][1]));
                }
        }
        __syncthreads();
    }

#pragma unroll
    for (int mi = 0; mi < 3; mi++) {
#pragma unroll
        for (int rh = 0; rh < 2; rh++) {
            int gr = row0 + warp_m * 48 + mi * 16 + rh * 8 + qr;
            if (gr >= M) continue;
#pragma unroll
            for (int nj = 0; nj < 4; nj++) {
#pragma unroll
                for (int jc = 0; jc < 2; jc++) {
                    int gc = col0 + warp_n * 32 + nj * 8 + qc * 2 + jc;
                    if (gc >= N) continue;
                    float v = c[mi][nj][rh * 2 + jc];
                    if (sg.bias) v += sg.bias[gc];
                    if (sg.act) v = fmaxf(v, 0.f);
                    sg.C[(size_t)gr * N + gc] = v;
                }
            }
        }
    }
}

// ---------------- GATv2 layer 1: quad-edge online softmax, emits tf32 h1 ----------------
template <int F>
__global__ __launch_bounds__(256) void gat_agg_kernel(
    const float* __restrict__ xl, const float* __restrict__ xr,
    const float* __restrict__ att, const float* __restrict__ bias,
    const int* __restrict__ ssrc, const int* __restrict__ off,
    uint32_t* __restrict__ out_tf)
{
    static_assert(F % 4 == 0, "F must be multiple of 4");
    constexpr int C4 = F / 4;
    constexpr int NJ = (C4 + 31) / 32;
    int warp = (blockIdx.x * blockDim.x + threadIdx.x) >> 5;
    int lane = threadIdx.x & 31;
    if (warp >= NN) return;
    int d = warp;

    float4 xrv[NJ], attv[NJ], acc[NJ];
    bool act[NJ];
#pragma unroll
    for (int j = 0; j < NJ; j++) {
        int cidx = lane + 32 * j;
        act[j] = (cidx < C4);
        float4 zf = make_float4(0.f, 0.f, 0.f, 0.f);
        xrv[j]  = act[j] ? *reinterpret_cast<const float4*>(&xr[(size_t)d * F + 4 * cidx]) : zf;
        attv[j] = act[j] ? *reinterpret_cast<const float4*>(&att[4 * cidx]) : zf;
        acc[j]  = zf;
    }
    int k0 = off[d], k1 = off[d + 1];

    float m = -1e30f, ssum = 0.f;
    const float4 zf4 = make_float4(0.f, 0.f, 0.f, 0.f);

    int k = k0;
    // ---- quad loop ----
    for (; k + 3 < k1; k += 4) {
        int s[4] = { ssrc[k], ssrc[k + 1], ssrc[k + 2], ssrc[k + 3] };
        float4 xs[4][NJ];
#pragma unroll
        for (int e = 0; e < 4; e++) {
            const float4* xp = reinterpret_cast<const float4*>(xl + (size_t)s[e] * F);
#pragma unroll
            for (int j = 0; j < NJ; j++) {
                int cidx = lane + 32 * j;
                xs[e][j] = act[j] ? xp[cidx] : zf4;
            }
        }
        float p[4] = {0.f, 0.f, 0.f, 0.f};
#pragma unroll
        for (int e = 0; e < 4; e++) {
#pragma unroll
            for (int j = 0; j < NJ; j++) {
                float v;
                v = xs[e][j].x + xrv[j].x; v = (v > 0.f) ? v : 0.2f * v; p[e] += v * attv[j].x;
                v = xs[e][j].y + xrv[j].y; v = (v > 0.f) ? v : 0.2f * v; p[e] += v * attv[j].y;
                v = xs[e][j].z + xrv[j].z; v = (v > 0.f) ? v : 0.2f * v; p[e] += v * attv[j].z;
                v = xs[e][j].w + xrv[j].w; v = (v > 0.f) ? v : 0.2f * v; p[e] += v * attv[j].w;
            }
        }
#pragma unroll
        for (int o = 16; o > 0; o >>= 1) {
            p[0] += __shfl_xor_sync(0xffffffffu, p[0], o);
            p[1] += __shfl_xor_sync(0xffffffffu, p[1], o);
            p[2] += __shfl_xor_sync(0xffffffffu, p[2], o);
            p[3] += __shfl_xor_sync(0xffffffffu, p[3], o);
        }
        float mn = fmaxf(fmaxf(m, fmaxf(p[0], p[1])), fmaxf(p[2], p[3]));
        float sc = __expf(m - mn);
        float w0 = __expf(p[0] - mn);
        float w1 = __expf(p[1] - mn);
        float w2 = __expf(p[2] - mn);
        float w3 = __expf(p[3] - mn);
        ssum = ssum * sc + w0 + w1 + w2 + w3;
#pragma unroll
        for (int j = 0; j < NJ; j++) {
            acc[j].x = acc[j].x * sc + w0 * xs[0][j].x + w1 * xs[1][j].x + w2 * xs[2][j].x + w3 * xs[3][j].x;
            acc[j].y = acc[j].y * sc + w0 * xs[0][j].y + w1 * xs[1][j].y + w2 * xs[2][j].y + w3 * xs[3][j].y;
            acc[j].z = acc[j].z * sc + w0 * xs[0][j].z + w1 * xs[1][j].z + w2 * xs[2][j].z + w3 * xs[3][j].z;
            acc[j].w = acc[j].w * sc + w0 * xs[0][j].w + w1 * xs[1][j].w + w2 * xs[2][j].w + w3 * xs[3][j].w;
        }
        m = mn;
    }
    // ---- tail: singles ----
    for (; k < k1; k++) {
        int s = ssrc[k];
        const float4* xar = reinterpret_cast<const float4*>(xl + (size_t)s * F);
        float4 xa[NJ];
#pragma unroll
        for (int j = 0; j < NJ; j++) {
            int cidx = lane + 32 * j;
            xa[j] = act[j] ? xar[cidx] : zf4;
        }
        float p = 0.f;
#pragma unroll
        for (int j = 0; j < NJ; j++) {
            float v;
            v = xa[j].x + xrv[j].x; v = (v > 0.f) ? v : 0.2f * v; p += v * attv[j].x;
            v = xa[j].y + xrv[j].y; v = (v > 0.f) ? v : 0.2f * v; p += v * attv[j].y;
            v = xa[j].z + xrv[j].z; v = (v > 0.f) ? v : 0.2f * v; p += v * attv[j].z;
            v = xa[j].w + xrv[j].w; v = (v > 0.f) ? v : 0.2f * v; p += v * attv[j].w;
        }
#pragma unroll
        for (int o = 16; o > 0; o >>= 1) p += __shfl_xor_sync(0xffffffffu, p, o);
        float mn = fmaxf(m, p);
        float sc = __expf(m - mn);
        float w  = __expf(p - mn);
        ssum = ssum * sc + w;
#pragma unroll
        for (int j = 0; j < NJ; j++) {
            acc[j].x = acc[j].x * sc + w * xa[j].x;
            acc[j].y = acc[j].y * sc + w * xa[j].y;
            acc[j].z = acc[j].z * sc + w * xa[j].z;
            acc[j].w = acc[j].w * sc + w * xa[j].w;
        }
        m = mn;
    }

    float inv = 1.f / (ssum + 1e-16f);
#pragma unroll
    for (int j = 0; j < NJ; j++) {
        int cidx = lane + 32 * j;
        if (!act[j]) continue;
        float4 bv = *reinterpret_cast<const float4*>(&bias[4 * cidx]);
        float4 o;
        o.x = fmaxf(acc[j].x * inv + bv.x, 0.f);
        o.y = fmaxf(acc[j].y * inv + bv.y, 0.f);
        o.z = fmaxf(acc[j].z * inv + bv.z, 0.f);
        o.w = fmaxf(acc[j].w * inv + bv.w, 0.f);
        uint4 t;
        t.x = f2tf32(o.x); t.y = f2tf32(o.y);
        t.z = f2tf32(o.z); t.w = f2tf32(o.w);
        *reinterpret_cast<uint4*>(&out_tf[(size_t)d * F + 4 * cidx]) = t;
    }
}

// ---------------- GATv2 layer 2 (F=100), quad-edge, fused epilogue ----------------
__global__ __launch_bounds__(256) void gat_agg100_fused(
    const float* __restrict__ xl, const float* __restrict__ xr,
    const float* __restrict__ att, const float* __restrict__ bias,
    const int* __restrict__ ssrc, const int* __restrict__ off,
    const float* __restrict__ lin1, const float* __restrict__ lin2,
    const float* __restrict__ Wl3, const float* __restrict__ Wr3,
    uint32_t* __restrict__ zb, float* __restrict__ xl3, float* __restrict__ xr3)
{
    int warp = (blockIdx.x * blockDim.x + threadIdx.x) >> 5;
    int lane = threadIdx.x & 31;
    if (warp >= NN) return;
    int d = warp;
    bool on = (lane < 25);    // 25 float4 chunks cover F=100

    float4 zf = make_float4(0.f, 0.f, 0.f, 0.f);
    float4 xrv = on ? *reinterpret_cast<const float4*>(&xr[(size_t)d * 100 + 4 * lane]) : zf;
    float4 attv = on ? *reinterpret_cast<const float4*>(&att[4 * lane]) : zf;
    float4 acc = zf;
    int k0 = off[d], k1 = off[d + 1];

    float m = -1e30f, ssum = 0.f;

    int k = k0;
    // ---- quad loop ----
    for (; k + 3 < k1; k += 4) {
        int s[4] = { ssrc[k], ssrc[k + 1], ssrc[k + 2], ssrc[k + 3] };
        float4 xs[4];
#pragma unroll
        for (int e = 0; e < 4; e++)
            xs[e] = on ? *reinterpret_cast<const float4*>(&xl[(size_t)s[e] * 100 + 4 * lane]) : zf;
        float p[4] = {0.f, 0.f, 0.f, 0.f};
#pragma unroll
        for (int e = 0; e < 4; e++) {
            float v;
            v = xs[e].x + xrv.x; v = (v > 0.f) ? v : 0.2f * v; p[e] += v * attv.x;
            v = xs[e].y + xrv.y; v = (v > 0.f) ? v : 0.2f * v; p[e] += v * attv.y;
            v = xs[e].z + xrv.z; v = (v > 0.f) ? v : 0.2f * v; p[e] += v * attv.z;
            v = xs[e].w + xrv.w; v = (v > 0.f) ? v : 0.2f * v; p[e] += v * attv.w;
        }
#pragma unroll
        for (int o = 16; o > 0; o >>= 1) {
            p[0] += __shfl_xor_sync(0xffffffffu, p[0], o);
            p[1] += __shfl_xor_sync(0xffffffffu, p[1], o);
            p[2] += __shfl_xor_sync(0xffffffffu, p[2], o);
            p[3] += __shfl_xor_sync(0xffffffffu, p[3], o);
        }
        float mn = fmaxf(fmaxf(m, fmaxf(p[0], p[1])), fmaxf(p[2], p[3]));
        float sc = __expf(m - mn);
        float w0 = __expf(p[0] - mn);
        float w1 = __expf(p[1] - mn);
        float w2 = __expf(p[2] - mn);
        float w3 = __expf(p[3] - mn);
        ssum = ssum * sc + w0 + w1 + w2 + w3;
        acc.x = acc.x * sc + w0 * xs[0].x + w1 * xs[1].x + w2 * xs[2].x + w3 * xs[3].x;
        acc.y = acc.y * sc + w0 * xs[0].y + w1 * xs[1].y + w2 * xs[2].y + w3 * xs[3].y;
        acc.z = acc.z * sc + w0 * xs[0].z + w1 * xs[1].z + w2 * xs[2].z + w3 * xs[3].z;
        acc.w = acc.w * sc + w0 * xs[0].w + w1 * xs[1].w + w2 * xs[2].w + w3 * xs[3].w;
        m = mn;
    }
    // ---- tail: singles ----
    for (; k < k1; k++) {
        int s = ssrc[k];
        float4 xa = on ? *reinterpret_cast<const float4*>(&xl[(size_t)s * 100 + 4 * lane]) : zf;
        float p = 0.f, v;
        v = xa.x + xrv.x; v = (v > 0.f) ? v : 0.2f * v; p += v * attv.x;
        v = xa.y + xrv.y; v = (v > 0.f) ? v : 0.2f * v; p += v * attv.y;
        v = xa.z + xrv.z; v = (v > 0.f) ? v : 0.2f * v; p += v * attv.z;
        v = xa.w + xrv.w; v = (v > 0.f) ? v : 0.2f * v; p += v * attv.w;
#pragma unroll
        for (int o = 16; o > 0; o >>= 1) p += __shfl_xor_sync(0xffffffffu, p, o);
        float mn = fmaxf(m, p);
        float sc = __expf(m - mn);
        float w  = __expf(p - mn);
        ssum = ssum * sc + w;
        acc.x = acc.x * sc + w * xa.x;
        acc.y = acc.y * sc + w * xa.y;
        acc.z = acc.z * sc + w * xa.z;
        acc.w = acc.w * sc + w * xa.w;
        m = mn;
    }

    float inv = 1.f / (ssum + 1e-16f);
    float pl = 0.f, pr = 0.f;
    if (on) {
        float4 bv = *reinterpret_cast<const float4*>(&bias[4 * lane]);
        float4 h;
        h.x = fmaxf(acc.x * inv + bv.x, 0.f);
        h.y = fmaxf(acc.y * inv + bv.y, 0.f);
        h.z = fmaxf(acc.z * inv + bv.z, 0.f);
        h.w = fmaxf(acc.w * inv + bv.w, 0.f);
        float4 l1 = *reinterpret_cast<const float4*>(&lin1[(size_t)d * 100 + 4 * lane]);
        float4 l2 = *reinterpret_cast<const float4*>(&lin2[(size_t)d * 100 + 4 * lane]);
        float4 xo4, z4;
        xo4.x = h.x + l1.x; xo4.y = h.y + l1.y; xo4.z = h.z + l1.z; xo4.w = h.w + l1.w;
        z4.x  = h.x + l2.x; z4.y  = h.y + l2.y; z4.z  = h.z + l2.z; z4.w  = h.w + l2.w;
        // z as bf16x2 pairs (consumed only by the loss kernel)
        uint2 zp;
        zp.x = pack_bf16x2(z4.x, z4.y);
        zp.y = pack_bf16x2(z4.z, z4.w);
        *reinterpret_cast<uint2*>(&zb[(size_t)d * 50 + 2 * lane]) = zp;
        float4 wl = *reinterpret_cast<const float4*>(&Wl3[4 * lane]);
        float4 wr = *reinterpret_cast<const float4*>(&Wr3[4 * lane]);
        pl = xo4.x * wl.x + xo4.y * wl.y + xo4.z * wl.z + xo4.w * wl.w;
        pr = xo4.x * wr.x + xo4.y * wr.y + xo4.z * wr.z + xo4.w * wr.w;
    }
#pragma unroll
    for (int o = 16; o > 0; o >>= 1) {
        pl += __shfl_xor_sync(0xffffffffu, pl, o);
        pr += __shfl_xor_sync(0xffffffffu, pr, o);
    }
    if (lane == 0) { xl3[d] = pl; xr3[d] = pr; }
}

// ---------------- layer-3 GAT (F=1) ----------------
__global__ __launch_bounds__(256) void gat3_kernel(
    const float* __restrict__ xl3, const float* __restrict__ xr3,
    const float* __restrict__ att3, const float* __restrict__ b3,
    const int* __restrict__ ssrc, const int* __restrict__ off,
    float* __restrict__ out)
{
    int warp = (blockIdx.x * blockDim.x + threadIdx.x) >> 5;
    int lane = threadIdx.x & 31;
    if (warp >= NN) return;
    int d = warp;
    float a0 = att3[0];
    float xrd = xr3[d];
    int k0 = off[d], k1 = off[d + 1];

    float m = -1e30f;
    for (int k = k0 + lane; k < k1; k += 32) {
        float v = xl3[ssrc[k]] + xrd;
        v = (v > 0.f) ? v : 0.2f * v;
        m = fmaxf(m, v * a0);
    }
#pragma unroll
    for (int o = 16; o > 0; o >>= 1) m = fmaxf(m, __shfl_xor_sync(0xffffffffu, m, o));

    float ssum = 0.f, acc = 0.f;
    for (int k = k0 + lane; k < k1; k += 32) {
        float xs = xl3[ssrc[k]];
        float v = xs + xrd;
        v = (v > 0.f) ? v : 0.2f * v;
        float w = __expf(v * a0 - m);
        ssum += w;
        acc  += w * xs;
    }
#pragma unroll
    for (int o = 16; o > 0; o >>= 1) {
        ssum += __shfl_xor_sync(0xffffffffu, ssum, o);
        acc  += __shfl_xor_sync(0xffffffffu, acc, o);
    }
    if (lane == 0) out[d] = acc / (ssum + 1e-16f) + b3[0];
}

// ---------------- link-prediction loss: bf16 z, paired edges ----------------
__global__ void loss_kernel(const uint32_t* __restrict__ zb, const int* __restrict__ ei,
                            const int* __restrict__ nei, float* __restrict__ accum) {
    int half = gridDim.x >> 1;
    int positive = (blockIdx.x < half) ? 1 : 0;
    int bid = positive ? blockIdx.x : (blockIdx.x - half);
    const int* ea = positive ? ei : nei;
    const int* eb = positive ? (ei + EE) : (nei + EE);

    int warp = (bid * blockDim.x + threadIdx.x) >> 5;
    int lane = threadIdx.x & 31;
    int nwarps = (half * blockDim.x) >> 5;
    float local = 0.f;
    for (int e = warp * 2; e + 1 < EE; e += 2 * nwarps) {
        int a0 = ea[e],     b0 = eb[e];
        int a1 = ea[e + 1], b1 = eb[e + 1];
        float p0 = 0.f, p1 = 0.f;
        if (lane < 25) {
            uint2 va0 = *reinterpret_cast<const uint2*>(&zb[(size_t)a0 * 50 + lane * 2]);
            uint2 vb0 = *reinterpret_cast<const uint2*>(&zb[(size_t)b0 * 50 + lane * 2]);
            uint2 va1 = *reinterpret_cast<const uint2*>(&zb[(size_t)a1 * 50 + lane * 2]);
            uint2 vb1 = *reinterpret_cast<const uint2*>(&zb[(size_t)b1 * 50 + lane * 2]);
            p0 += bf16lo(va0.x) * bf16lo(vb0.x) + bf16hi(va0.x) * bf16hi(vb0.x);
            p0 += bf16lo(va0.y) * bf16lo(vb0.y) + bf16hi(va0.y) * bf16hi(vb0.y);
            p1 += bf16lo(va1.x) * bf16lo(vb1.x) + bf16hi(va1.x) * bf16hi(vb1.x);
            p1 += bf16lo(va1.y) * bf16lo(vb1.y) + bf16hi(va1.y) * bf16hi(vb1.y);
        }
#pragma unroll
        for (int o = 16; o > 0; o >>= 1) {
            p0 += __shfl_xor_sync(0xffffffffu, p0, o);
            p1 += __shfl_xor_sync(0xffffffffu, p1, o);
        }
        if (lane == 0) {
            float s0 = 1.f / (1.f + __expf(-p0));
            float s1 = 1.f / (1.f + __expf(-p1));
            if (positive) local += __logf(s0 + 1e-15f) + __logf(s1 + 1e-15f);
            else          local += __logf(1.f - s0 + 1e-15f) + __logf(1.f - s1 + 1e-15f);
        }
    }
    if (lane == 0) atomicAdd(&accum[positive ? 0 : 1], local);
}

__global__ void finalize_kernel(float* __restrict__ d_out, const float* __restrict__ loss,
                                const float* __restrict__ c1, const float* __restrict__ c2) {
    if (threadIdx.x == 0) {
        d_out[NN]     = -(loss[0] + loss[1]) / (float)EE;
        d_out[NN + 1] = c1[0];
        d_out[NN + 2] = c2[0];
    }
}

// ---------------- launch ----------------
extern "C" void kernel_launch(void* const* d_in, const int* in_sizes, int n_in,
                              void* d_out, int out_size) {
    const float* x     = (const float*)d_in[0];
    const int*   ei    = (const int*)  d_in[1];
    const int*   nei   = (const int*)  d_in[2];
    const float* Wl1   = (const float*)d_in[3];
    const float* Wr1   = (const float*)d_in[4];
    const float* att1  = (const float*)d_in[5];
    const float* b1    = (const float*)d_in[6];
    const float* Wl2   = (const float*)d_in[7];
    const float* Wr2   = (const float*)d_in[8];
    const float* att2  = (const float*)d_in[9];
    const float* b2    = (const float*)d_in[10];
    const float* Wl3   = (const float*)d_in[11];
    const float* Wr3   = (const float*)d_in[12];
    const float* att3  = (const float*)d_in[13];
    const float* b3    = (const float*)d_in[14];
    const float* Wlin1 = (const float*)d_in[15];
    const float* blin1 = (const float*)d_in[16];
    const float* Wlin2 = (const float*)d_in[17];
    const float* blin2 = (const float*)d_in[18];
    const float* c1    = (const float*)d_in[19];
    const float* c2    = (const float*)d_in[20];
    float* out = (float*)d_out;

    uint32_t *xtf, *h1tf, *wtf, *zb;
    float *xl1, *xr1, *xl2, *xr2, *lin1, *lin2, *xl3, *xr3, *loss;
    int *deg, *off, *cur, *ssrc;
    cudaGetSymbolAddress((void**)&xtf,  g_xtf);
    cudaGetSymbolAddress((void**)&h1tf, g_h1tf);
    cudaGetSymbolAddress((void**)&wtf,  g_wtf);
    cudaGetSymbolAddress((void**)&xl1,  g_xl1);
    cudaGetSymbolAddress((void**)&xr1,  g_xr1);
    cudaGetSymbolAddress((void**)&xl2,  g_xl2);
    cudaGetSymbolAddress((void**)&xr2,  g_xr2);
    cudaGetSymbolAddress((void**)&lin1, g_lin1);
    cudaGetSymbolAddress((void**)&lin2, g_lin2);
    cudaGetSymbolAddress((void**)&zb,   g_zb);
    cudaGetSymbolAddress((void**)&xl3,  g_xl3);
    cudaGetSymbolAddress((void**)&xr3,  g_xr3);
    cudaGetSymbolAddress((void**)&loss, g_loss);
    cudaGetSymbolAddress((void**)&deg,  g_deg);
    cudaGetSymbolAddress((void**)&off,  g_off);
    cudaGetSymbolAddress((void**)&cur,  g_cur);
    cudaGetSymbolAddress((void**)&ssrc, g_src);

    // side streams + fork/join events (capturable pattern)
    cudaStream_t sCsr, sLin, sLoss;
    cudaStreamCreateWithFlags(&sCsr,  cudaStreamNonBlocking);
    cudaStreamCreateWithFlags(&sLin,  cudaStreamNonBlocking);
    cudaStreamCreateWithFlags(&sLoss, cudaStreamNonBlocking);
    cudaEvent_t evRoot, evCsr, evConv, evLin, evMid, evLoss;
    cudaEventCreateWithFlags(&evRoot, cudaEventDisableTiming);
    cudaEventCreateWithFlags(&evCsr,  cudaEventDisableTiming);
    cudaEventCreateWithFlags(&evConv, cudaEventDisableTiming);
    cudaEventCreateWithFlags(&evLin,  cudaEventDisableTiming);
    cudaEventCreateWithFlags(&evMid,  cudaEventDisableTiming);
    cudaEventCreateWithFlags(&evLoss, cudaEventDisableTiming);

    // ---- fork: CSR build on side stream (depends only on ei) ----
    cudaEventRecord(evRoot, 0);
    cudaStreamWaitEvent(sCsr, evRoot, 0);
    zero_kernel<<<(NN + 255) / 256, 256, 0, sCsr>>>(deg, cur, loss);
    hist_kernel<<<(E2T + 255) / 256, 256, 0, sCsr>>>(ei, deg);
    scan_kernel<<<1, 1024, 0, sCsr>>>(deg, off);
    scatter_kernel<<<(E2T + 255) / 256, 256, 0, sCsr>>>(ei, cur, off, ssrc);
    cudaEventRecord(evCsr, sCsr);

    // ---- main: tf32 conversion ----
    {
        CSeg c0 = { x,     xtf,             NN * 500 / 4 };
        CSeg c1s= { Wl1,   wtf + OFF_WL1,   150000 / 4 };
        CSeg c2s= { Wr1,   wtf + OFF_WR1,   150000 / 4 };
        CSeg c3 = { Wlin1, wtf + OFF_WLIN1, 50000 / 4 };
        CSeg c4 = { Wlin2, wtf + OFF_WLIN2, 50000 / 4 };
        CSeg c5 = { Wl2,   wtf + OFF_WL2,   30000 / 4 };
        CSeg c6 = { Wr2,   wtf + OFF_WR2,   30000 / 4 };
        int n4 = NN * 500 / 4;
        conv_multi<<<(n4 + 255) / 256, 256>>>(c0, c1s, c2s, c3, c4, c5, c6);
    }
    cudaEventRecord(evConv, 0);

    dim3 tb(256);
    int rows = (NN + BM - 1) / BM;   // 71

    // ---- fork: skip-linear GEMM on side stream (needed only at agg100_fused) ----
    cudaStreamWaitEvent(sLin, evConv, 0);
    {
        GSeg s0 = { wtf + OFF_WLIN1, blin1, lin1, 100, 1, 0 };
        GSeg s1 = { wtf + OFF_WLIN2, blin2, lin2, 100, 1, 2 };
        gemm_tf32_multi<<<dim3(4, rows), tb, 0, sLin>>>(xtf, NN, 500, s0, s1, s0, s1, 2);
    }
    cudaEventRecord(evLin, sLin);

    // ---- main: layer-1 attention projections ----
    {
        GSeg s0 = { wtf + OFF_WL1, nullptr, xl1, 300, 0, 0 };
        GSeg s1 = { wtf + OFF_WR1, nullptr, xr1, 300, 0, 5 };
        gemm_tf32_multi<<<dim3(10, rows), tb>>>(xtf, NN, 500, s0, s1, s0, s1, 2);
    }

    // ---- join CSR, then edge phase ----
    cudaStreamWaitEvent(0, evCsr, 0);
    int agg_blocks = (NN + 7) / 8;
    gat_agg_kernel<300><<<agg_blocks, 256>>>(xl1, xr1, att1, b1, ssrc, off, h1tf);

    {
        GSeg s0 = { wtf + OFF_WL2, nullptr, xl2, 100, 0, 0 };
        GSeg s1 = { wtf + OFF_WR2, nullptr, xr2, 100, 0, 2 };
        gemm_tf32_multi<<<dim3(4, rows), tb>>>(h1tf, NN, 300, s0, s1, s0, s1, 2);
    }

    // join the skip-linear GEMM before the fused layer-2 aggregation
    cudaStreamWaitEvent(0, evLin, 0);
    gat_agg100_fused<<<agg_blocks, 256>>>(xl2, xr2, att2, b2, ssrc, off,
                                          lin1, lin2, Wl3, Wr3, zb, xl3, xr3);

    // ---- fork: loss on side stream, gat3 on main ----
    cudaEventRecord(evMid, 0);
    cudaStreamWaitEvent(sLoss, evMid, 0);
    loss_kernel<<<4096, 256, 0, sLoss>>>(zb, ei, nei, loss);
    cudaEventRecord(evLoss, sLoss);

    gat3_kernel<<<agg_blocks, 256>>>(xl3, xr3, att3, b3, ssrc, off, out);

    cudaStreamWaitEvent(0, evLoss, 0);
    finalize_kernel<<<1, 32>>>(out, loss, c1, c2);

    cudaEventDestroy(evRoot);
    cudaEventDestroy(evCsr);
    cudaEventDestroy(evConv);
    cudaEventDestroy(evLin);
    cudaEventDestroy(evMid);
    cudaEventDestroy(evLoss);
    cudaStreamDestroy(sCsr);
    cudaStreamDestroy(sLin);
    cudaStreamDestroy(sLoss);
}